// round 5
// baseline (speedup 1.0000x reference)
#include <cuda_runtime.h>
#include <math.h>

typedef unsigned long long u64;

namespace {
constexpr int D = 128;
constexpr int R = 32;          // rows per block
constexpr int NT = 512;
constexpr int SA = 132;        // stride (floats) for [32][128] activation arrays (132%32==4 -> conflict-free f4)
constexpr int SF = 388;        // fusion stride
constexpr int SH = 68;         // H stride
constexpr int SR = 28;         // reduction scratch lane stride
constexpr int OFF_A   = 0;
constexpr int OFF_V   = OFF_A + R * SA;
constexpr int OFF_L   = OFF_V + R * SA;
constexpr int OFF_G0  = OFF_L + R * SA;
constexpr int OFF_G1  = OFF_G0 + R * SA;
constexpr int OFF_G2  = OFF_G1 + R * SA;
constexpr int OFF_FUS = OFF_G2 + R * SA;
constexpr int OFF_H   = OFF_FUS + R * SF;   // [96][SH]
constexpr int OFF_H2  = OFF_H + 96 * SH;    // [32][SH]
constexpr int OFF_RED = OFF_H2 + 32 * SH;   // [8][32][SR]
constexpr int OFF_AW  = OFF_RED + 8 * 32 * SR;
constexpr int OFF_SC  = OFF_AW + 128;
constexpr int SMEM_FLOATS = OFF_SC + R * 16;
}

__device__ __forceinline__ float warp_sum(float x) {
#pragma unroll
    for (int o = 16; o > 0; o >>= 1) x += __shfl_xor_sync(0xffffffffu, x, o);
    return x;
}
__device__ __forceinline__ float warp_max(float x) {
#pragma unroll
    for (int o = 16; o > 0; o >>= 1) x = fmaxf(x, __shfl_xor_sync(0xffffffffu, x, o));
    return x;
}
__device__ __forceinline__ float tanh_fast(float x) {
    float y;
    asm("tanh.approx.f32 %0, %1;" : "=f"(y) : "f"(x));
    return y;
}
// ---- packed f32x2 helpers ----
__device__ __forceinline__ u64 pk2(float lo, float hi) {
    u64 r; asm("mov.b64 %0, {%1, %2};" : "=l"(r) : "f"(lo), "f"(hi)); return r;
}
__device__ __forceinline__ u64 pkdup(float x) {
    u64 r; asm("mov.b64 %0, {%1, %1};" : "=l"(r) : "f"(x)); return r;
}
__device__ __forceinline__ void fma2(u64& d, u64 a, u64 b) {
    asm("fma.rn.f32x2 %0, %1, %2, %0;" : "+l"(d) : "l"(a), "l"(b));
}
__device__ __forceinline__ void add2(u64& d, u64 a) {
    asm("add.rn.f32x2 %0, %0, %1;" : "+l"(d) : "l"(a));
}
__device__ __forceinline__ float2 up2(u64 v) {
    float2 f; asm("mov.b64 {%0, %1}, %2;" : "=f"(f.x), "=f"(f.y) : "l"(v)); return f;
}
__device__ __forceinline__ float xcomp(const float4& v, int kk) {
    return (kk == 0) ? v.x : (kk == 1) ? v.y : (kk == 2) ? v.z : v.w;
}

// gf-style MLP over 3 row-pairs (96 rows):
//   H = leaky_relu(concat(x,y) @ W1 + b1); G = tanh(H @ W2 + b2)
// Warp layout GEMM1: h=wid>>3 selects k-half (x vs y), wq=wid&7 owns cols 8wq..8wq+7,
// lane l owns rows {l, l+32, l+64} (one per pair). k-halves reduced via smRed.
// GEMM2: all 16 warps own 8 cols each (128 cols), same lane->rows map.
// MODE 0: G -> smG[p]. MODE 1: smFus[l][256+c] += sum_p tanh(n2[p]*G_p) (exclusive, no atomics)
template <int MODE, int N2BASE>
__device__ __forceinline__ void mlp_stage(
    const float* __restrict__ W1, const float* __restrict__ b1,
    const float* __restrict__ W2, const float* __restrict__ b2,
    const float* x0, const float* x1, const float* x2,
    const float* y0, const float* y1, const float* y2,
    float* sm)
{
    const int tid = threadIdx.x;
    const int l   = tid & 31;
    const int wid = tid >> 5;
    const int h   = wid >> 3;
    const int wq  = wid & 7;
    float* smH   = sm + OFF_H;
    float* smRed = sm + OFF_RED;

    // ---------------- GEMM1 partial over this k-half ----------------
    u64 acc[3][4];
#pragma unroll
    for (int i = 0; i < 3; ++i)
#pragma unroll
        for (int j = 0; j < 4; ++j) acc[i][j] = 0ull;

    const float* s0 = h ? y0 : x0;
    const float* s1 = h ? y1 : x1;
    const float* s2 = h ? y2 : x2;
    const float4* xf[3] = { (const float4*)(s0 + l * SA),
                            (const float4*)(s1 + l * SA),
                            (const float4*)(s2 + l * SA) };
    const float* W1b = W1 + h * 128 * 64 + wq * 8;
#pragma unroll 2
    for (int k4 = 0; k4 < 32; ++k4) {
        float4 xv[3];
#pragma unroll
        for (int i = 0; i < 3; ++i) xv[i] = xf[i][k4];
#pragma unroll
        for (int kk = 0; kk < 4; ++kk) {
            const float* wr = W1b + (k4 * 4 + kk) * 64;
            ulonglong2 wa = __ldg((const ulonglong2*)wr);
            ulonglong2 wb = __ldg((const ulonglong2*)(wr + 4));
#pragma unroll
            for (int i = 0; i < 3; ++i) {
                u64 xx = pkdup(xcomp(xv[i], kk));
                fma2(acc[i][0], wa.x, xx);
                fma2(acc[i][1], wa.y, xx);
                fma2(acc[i][2], wb.x, xx);
                fma2(acc[i][3], wb.y, xx);
            }
        }
    }
    // ---------------- cross-half reduction + H epilogue ----------------
    float* rb = smRed + (wq * 32 + l) * SR;
    if (h) {
#pragma unroll
        for (int i = 0; i < 3; ++i) {
            ((ulonglong2*)(rb + i * 8))[0]     = make_ulonglong2(acc[i][0], acc[i][1]);
            ((ulonglong2*)(rb + i * 8 + 4))[0] = make_ulonglong2(acc[i][2], acc[i][3]);
        }
    }
    __syncthreads();
    if (!h) {
        const int col0 = wq * 8;
        float4 bb0 = __ldg((const float4*)(b1 + col0));
        float4 bb1 = __ldg((const float4*)(b1 + col0 + 4));
        float bias[8] = {bb0.x, bb0.y, bb0.z, bb0.w, bb1.x, bb1.y, bb1.z, bb1.w};
#pragma unroll
        for (int i = 0; i < 3; ++i) {
            ulonglong2 ra = ((const ulonglong2*)(rb + i * 8))[0];
            ulonglong2 rc = ((const ulonglong2*)(rb + i * 8 + 4))[0];
            add2(acc[i][0], ra.x); add2(acc[i][1], ra.y);
            add2(acc[i][2], rc.x); add2(acc[i][3], rc.y);
            float hv[8];
#pragma unroll
            for (int j = 0; j < 4; ++j) {
                float2 f = up2(acc[i][j]);
                hv[2 * j] = f.x; hv[2 * j + 1] = f.y;
            }
#pragma unroll
            for (int j = 0; j < 8; ++j) {
                float t = hv[j] + bias[j];
                hv[j] = (t >= 0.0f) ? t : 0.2f * t;
            }
            float* hp = smH + (l + 32 * i) * SH + col0;
            ((float4*)hp)[0]       = make_float4(hv[0], hv[1], hv[2], hv[3]);
            ((float4*)(hp + 4))[0] = make_float4(hv[4], hv[5], hv[6], hv[7]);
        }
    }
    __syncthreads();
    // ---------------- GEMM2: [96x64] @ [64x128] ----------------
    {
        const int col0 = wid * 8;
        float4 b20 = __ldg((const float4*)(b2 + col0));
        float4 b21 = __ldg((const float4*)(b2 + col0 + 4));
        u64 g[3][4];
#pragma unroll
        for (int i = 0; i < 3; ++i) {
            g[i][0] = pk2(b20.x, b20.y); g[i][1] = pk2(b20.z, b20.w);
            g[i][2] = pk2(b21.x, b21.y); g[i][3] = pk2(b21.z, b21.w);
        }
        const float4* hf[3] = { (const float4*)(smH + l * SH),
                                (const float4*)(smH + (l + 32) * SH),
                                (const float4*)(smH + (l + 64) * SH) };
        const float* W2b = W2 + col0;
#pragma unroll 2
        for (int k4 = 0; k4 < 16; ++k4) {
            float4 xv[3];
#pragma unroll
            for (int i = 0; i < 3; ++i) xv[i] = hf[i][k4];
#pragma unroll
            for (int kk = 0; kk < 4; ++kk) {
                const float* wr = W2b + (k4 * 4 + kk) * 128;
                ulonglong2 wa = __ldg((const ulonglong2*)wr);
                ulonglong2 wb = __ldg((const ulonglong2*)(wr + 4));
#pragma unroll
                for (int i = 0; i < 3; ++i) {
                    u64 xx = pkdup(xcomp(xv[i], kk));
                    fma2(g[i][0], wa.x, xx);
                    fma2(g[i][1], wa.y, xx);
                    fma2(g[i][2], wb.x, xx);
                    fma2(g[i][3], wb.y, xx);
                }
            }
        }
        float gv[3][8];
#pragma unroll
        for (int i = 0; i < 3; ++i)
#pragma unroll
            for (int j = 0; j < 4; ++j) {
                float2 f = up2(g[i][j]);
                gv[i][2 * j] = f.x; gv[i][2 * j + 1] = f.y;
            }
        if (MODE == 0) {
#pragma unroll
            for (int i = 0; i < 3; ++i) {
                float* gp = sm + ((i == 0) ? OFF_G0 : (i == 1) ? OFF_G1 : OFF_G2) + l * SA + col0;
                ((float4*)gp)[0]       = make_float4(tanh_fast(gv[i][0]), tanh_fast(gv[i][1]),
                                                     tanh_fast(gv[i][2]), tanh_fast(gv[i][3]));
                ((float4*)(gp + 4))[0] = make_float4(tanh_fast(gv[i][4]), tanh_fast(gv[i][5]),
                                                     tanh_fast(gv[i][6]), tanh_fast(gv[i][7]));
            }
        } else {
            const float* sc = sm + OFF_SC + l * 16;
            float nv0 = sc[9 + N2BASE + 0];
            float nv1 = sc[9 + N2BASE + 1];
            float nv2 = sc[9 + N2BASE + 2];
            float s[8];
#pragma unroll
            for (int j = 0; j < 8; ++j)
                s[j] = tanh_fast(nv0 * tanh_fast(gv[0][j]))
                     + tanh_fast(nv1 * tanh_fast(gv[1][j]))
                     + tanh_fast(nv2 * tanh_fast(gv[2][j]));
            float* fp = sm + OFF_FUS + l * SF + 256 + col0;
            float4 f0 = ((float4*)fp)[0];
            float4 f1 = ((float4*)(fp + 4))[0];
            f0.x += s[0]; f0.y += s[1]; f0.z += s[2]; f0.w += s[3];
            f1.x += s[4]; f1.y += s[5]; f1.z += s[6]; f1.w += s[7];
            ((float4*)fp)[0] = f0;
            ((float4*)(fp + 4))[0] = f1;
        }
    }
}

__global__ void __launch_bounds__(NT, 1)
graphfusion_kernel(
    const float* __restrict__ Lm, const float* __restrict__ Am, const float* __restrict__ Vm,
    const float* __restrict__ att_w, const float* __restrict__ att_b,
    const float* __restrict__ gf_w1, const float* __restrict__ gf_b1,
    const float* __restrict__ gf_w2, const float* __restrict__ gf_b2,
    const float* __restrict__ gf2_w1, const float* __restrict__ gf2_b1,
    const float* __restrict__ gf2_w2, const float* __restrict__ gf2_b2,
    const float* __restrict__ ll_w1, const float* __restrict__ ll_b1,
    const float* __restrict__ ll_w2, const float* __restrict__ ll_b2,
    const float* __restrict__ ll_w3, const float* __restrict__ ll_b3,
    float* __restrict__ out)
{
    extern __shared__ float sm[];
    float* smA   = sm + OFF_A;
    float* smV   = sm + OFF_V;
    float* smL   = sm + OFF_L;
    float* smFus = sm + OFF_FUS;
    float* smAttw = sm + OFF_AW;
    float* smScal = sm + OFF_SC;

    const int tid = threadIdx.x;
    const int lane = tid & 31;
    const int wid = tid >> 5;

    if (tid < D) smAttw[tid] = att_w[tid];
    __syncthreads();
    const float attb = __ldg(att_b);

    // ================= Phase A: scalars + softmaxes + unimodal =================
    {
        float4 aw = ((const float4*)smAttw)[lane];
#pragma unroll
        for (int rr = 0; rr < 2; ++rr) {
            int r = wid * 2 + rr;
            size_t grow = (size_t)blockIdx.x * R + r;
            float4 a4 = ((const float4*)(Am + grow * D))[lane];
            float4 v4 = ((const float4*)(Vm + grow * D))[lane];
            float4 l4 = ((const float4*)(Lm + grow * D))[lane];

            float sa = tanh_fast(warp_sum(a4.x * aw.x + a4.y * aw.y + a4.z * aw.z + a4.w * aw.w) + attb);
            float sv = tanh_fast(warp_sum(v4.x * aw.x + v4.y * aw.y + v4.z * aw.z + v4.w * aw.w) + attb);
            float sl = tanh_fast(warp_sum(l4.x * aw.x + l4.y * aw.y + l4.z * aw.z + l4.w * aw.w) + attb);

            float4 u;
            u.x = (sa * a4.x + sv * v4.x + sl * l4.x) * (1.0f / 3.0f);
            u.y = (sa * a4.y + sv * v4.y + sl * l4.y) * (1.0f / 3.0f);
            u.z = (sa * a4.z + sv * v4.z + sl * l4.z) * (1.0f / 3.0f);
            u.w = (sa * a4.w + sv * v4.w + sl * l4.w) * (1.0f / 3.0f);
            ((float4*)(smFus + r * SF))[lane] = u;

            float ma = warp_max(fmaxf(fmaxf(a4.x, a4.y), fmaxf(a4.z, a4.w)));
            float4 ea = make_float4(__expf(a4.x - ma), __expf(a4.y - ma), __expf(a4.z - ma), __expf(a4.w - ma));
            float ia = 1.0f / warp_sum(ea.x + ea.y + ea.z + ea.w);
            float4 pa = make_float4(ea.x * ia, ea.y * ia, ea.z * ia, ea.w * ia);

            float mv = warp_max(fmaxf(fmaxf(v4.x, v4.y), fmaxf(v4.z, v4.w)));
            float4 ev = make_float4(__expf(v4.x - mv), __expf(v4.y - mv), __expf(v4.z - mv), __expf(v4.w - mv));
            float iv = 1.0f / warp_sum(ev.x + ev.y + ev.z + ev.w);
            float4 pv = make_float4(ev.x * iv, ev.y * iv, ev.z * iv, ev.w * iv);

            float ml = warp_max(fmaxf(fmaxf(l4.x, l4.y), fmaxf(l4.z, l4.w)));
            float4 el = make_float4(__expf(l4.x - ml), __expf(l4.y - ml), __expf(l4.z - ml), __expf(l4.w - ml));
            float il = 1.0f / warp_sum(el.x + el.y + el.z + el.w);
            float4 pl = make_float4(el.x * il, el.y * il, el.z * il, el.w * il);

            ((float4*)(smA + r * SA))[lane] = pa;
            ((float4*)(smV + r * SA))[lane] = pv;
            ((float4*)(smL + r * SA))[lane] = pl;

            float dav = warp_sum(pa.x * pv.x + pa.y * pv.y + pa.z * pv.z + pa.w * pv.w);
            float dal = warp_sum(pa.x * pl.x + pa.y * pl.y + pa.z * pl.z + pa.w * pl.w);
            float dvl = warp_sum(pv.x * pl.x + pv.y * pl.y + pv.z * pl.z + pv.w * pl.w);

            float sav = (sa + sv) / (dav + 0.5f);
            float sal = (sa + sl) / (dal + 0.5f);
            float svl = (sl + sv) / (dvl + 0.5f);
            float mx = fmaxf(sav, fmaxf(sal, svl));
            float e0 = __expf(sav - mx), e1 = __expf(sal - mx), e2 = __expf(svl - mx);
            float is = 1.0f / (e0 + e1 + e2);
            if (lane == 0) {
                float* sc = smScal + r * 16;
                sc[0] = e0 * is; sc[1] = e1 * is; sc[2] = e2 * is;
                sc[3] = sav; sc[4] = sal; sc[5] = svl;
                sc[6] = sa;  sc[7] = sv;  sc[8] = sl;
            }
        }
    }
    __syncthreads();

    // ================= gf stage =================
    mlp_stage<0, 0>(gf_w1, gf_b1, gf_w2, gf_b2,
                    smA, smA, smV,       // x of pairs (a,v) (a,l) (v,l)
                    smV, smL, smL,       // y of pairs
                    sm);
    __syncthreads();

    // ============ Phase C ============
    {
#pragma unroll
        for (int rr = 0; rr < 2; ++rr) {
            int r = wid * 2 + rr;
            float4 g0 = ((const float4*)(sm + OFF_G0 + r * SA))[lane];
            float4 g1 = ((const float4*)(sm + OFF_G1 + r * SA))[lane];
            float4 g2 = ((const float4*)(sm + OFF_G2 + r * SA))[lane];
            float4 pa = ((const float4*)(smA + r * SA))[lane];
            float4 pv = ((const float4*)(smV + r * SA))[lane];
            float4 pl = ((const float4*)(smL + r * SA))[lane];

            float m0 = warp_max(fmaxf(fmaxf(g0.x, g0.y), fmaxf(g0.z, g0.w)));
            float m1 = warp_max(fmaxf(fmaxf(g1.x, g1.y), fmaxf(g1.z, g1.w)));
            float m2 = warp_max(fmaxf(fmaxf(g2.x, g2.y), fmaxf(g2.z, g2.w)));
            float4 e0 = make_float4(__expf(g0.x - m0), __expf(g0.y - m0), __expf(g0.z - m0), __expf(g0.w - m0));
            float4 e1 = make_float4(__expf(g1.x - m1), __expf(g1.y - m1), __expf(g1.z - m1), __expf(g1.w - m1));
            float4 e2 = make_float4(__expf(g2.x - m2), __expf(g2.y - m2), __expf(g2.z - m2), __expf(g2.w - m2));
            float i0 = 1.0f / warp_sum(e0.x + e0.y + e0.z + e0.w);
            float i1 = 1.0f / warp_sum(e1.x + e1.y + e1.z + e1.w);
            float i2 = 1.0f / warp_sum(e2.x + e2.y + e2.z + e2.w);

            float d01 = warp_sum(e0.x * e1.x + e0.y * e1.y + e0.z * e1.z + e0.w * e1.w);
            float d02 = warp_sum(e0.x * e2.x + e0.y * e2.y + e0.z * e2.z + e0.w * e2.w);
            float d12 = warp_sum(e1.x * e2.x + e1.y * e2.y + e1.z * e2.z + e1.w * e2.w);
            float d0l = warp_sum(e0.x * pl.x + e0.y * pl.y + e0.z * pl.z + e0.w * pl.w);
            float d1v = warp_sum(e1.x * pv.x + e1.y * pv.y + e1.z * pv.z + e1.w * pv.w);
            float d2a = warp_sum(e2.x * pa.x + e2.y * pa.y + e2.z * pa.z + e2.w * pa.w);

            const float* sc = smScal + r * 16;
            float sav = sc[3], sal = sc[4], svl = sc[5];
            float sa = sc[6], sv = sc[7], sl = sc[8];
            float t0 = (sav + svl) / (d02 * i0 * i2 + 0.5f);
            float t1 = (sav + sal) / (d01 * i0 * i1 + 0.5f);
            float t2 = (sal + svl) / (d12 * i1 * i2 + 0.5f);
            float t3 = (sav + sl)  / (d0l * i0 + 0.5f);
            float t4 = (sal + sv)  / (d1v * i1 + 0.5f);
            float t5 = (sa  + svl) / (d2a * i2 + 0.5f);
            float mm = fmaxf(fmaxf(fmaxf(t0, t1), fmaxf(t2, t3)), fmaxf(t4, t5));
            float q0 = __expf(t0 - mm), q1 = __expf(t1 - mm), q2 = __expf(t2 - mm);
            float q3 = __expf(t3 - mm), q4 = __expf(t4 - mm), q5 = __expf(t5 - mm);
            float qi = 1.0f / (q0 + q1 + q2 + q3 + q4 + q5);
            if (lane == 0) {
                float* scw = smScal + r * 16;
                scw[9] = q0 * qi; scw[10] = q1 * qi; scw[11] = q2 * qi;
                scw[12] = q3 * qi; scw[13] = q4 * qi; scw[14] = q5 * qi;
            }

            float n0 = sc[0], n1 = sc[1], n2v = sc[2];
            float4 av = make_float4(tanh_fast(n0 * g0.x), tanh_fast(n0 * g0.y), tanh_fast(n0 * g0.z), tanh_fast(n0 * g0.w));
            float4 al = make_float4(tanh_fast(n1 * g1.x), tanh_fast(n1 * g1.y), tanh_fast(n1 * g1.z), tanh_fast(n1 * g1.w));
            float4 vl = make_float4(tanh_fast(n2v * g2.x), tanh_fast(n2v * g2.y), tanh_fast(n2v * g2.z), tanh_fast(n2v * g2.w));
            ((float4*)(sm + OFF_G0 + r * SA))[lane] = av;
            ((float4*)(sm + OFF_G1 + r * SA))[lane] = al;
            ((float4*)(sm + OFF_G2 + r * SA))[lane] = vl;
            float4 bm = make_float4(av.x + al.x + vl.x, av.y + al.y + vl.y,
                                    av.z + al.z + vl.z, av.w + al.w + vl.w);
            ((float4*)(smFus + r * SF + 128))[lane] = bm;
            ((float4*)(smFus + r * SF + 256))[lane] = make_float4(0.f, 0.f, 0.f, 0.f);
        }
    }
    __syncthreads();

    // ================= gf2 stages (trimodal) =================
    float* G0 = sm + OFF_G0;   // a_v
    float* G1 = sm + OFF_G1;   // a_l
    float* G2 = sm + OFF_G2;   // v_l
    mlp_stage<1, 0>(gf2_w1, gf2_b1, gf2_w2, gf2_b2,
                    G0, G0, G2,          // x of (a_v,v_l) (a_v,a_l) (v_l,a_l)
                    G2, G1, G1,
                    sm);
    __syncthreads();
    mlp_stage<1, 3>(gf2_w1, gf2_b1, gf2_w2, gf2_b2,
                    G0, G1, G2,          // x of (a_v,l) (a_l,v) (v_l,a)
                    smL, smV, smA,
                    sm);
    __syncthreads();

    // ================= ll chain =================
    const int l = lane;
    // ll1: [32 x 384] @ [384 x 64], 8 col-groups x 2 k-halves
    {
        const int h2 = wid >> 3, wq = wid & 7, col0 = wq * 8;
        u64 acc[4] = {0ull, 0ull, 0ull, 0ull};
        const float4* xf = (const float4*)(sm + OFF_FUS + l * SF);
        const float* Wb = ll_w1 + h2 * 192 * 64 + col0;
#pragma unroll 2
        for (int k4 = 0; k4 < 48; ++k4) {
            float4 x = xf[h2 * 48 + k4];
#pragma unroll
            for (int kk = 0; kk < 4; ++kk) {
                const float* wr = Wb + (k4 * 4 + kk) * 64;
                ulonglong2 wa = __ldg((const ulonglong2*)wr);
                ulonglong2 wb = __ldg((const ulonglong2*)(wr + 4));
                u64 xx = pkdup(xcomp(x, kk));
                fma2(acc[0], wa.x, xx); fma2(acc[1], wa.y, xx);
                fma2(acc[2], wb.x, xx); fma2(acc[3], wb.y, xx);
            }
        }
        float* rb = sm + OFF_RED + (wq * 32 + l) * SR;
        if (h2) {
            ((ulonglong2*)rb)[0]       = make_ulonglong2(acc[0], acc[1]);
            ((ulonglong2*)(rb + 4))[0] = make_ulonglong2(acc[2], acc[3]);
        }
        __syncthreads();
        if (!h2) {
            ulonglong2 ra = ((const ulonglong2*)rb)[0];
            ulonglong2 rc = ((const ulonglong2*)(rb + 4))[0];
            add2(acc[0], ra.x); add2(acc[1], ra.y);
            add2(acc[2], rc.x); add2(acc[3], rc.y);
            float4 bb0 = __ldg((const float4*)(ll_b1 + col0));
            float4 bb1 = __ldg((const float4*)(ll_b1 + col0 + 4));
            float2 f0 = up2(acc[0]), f1 = up2(acc[1]), f2 = up2(acc[2]), f3 = up2(acc[3]);
            float* hp = sm + OFF_H2 + l * SH + col0;
            ((float4*)hp)[0] = make_float4(tanh_fast(f0.x + bb0.x), tanh_fast(f0.y + bb0.y),
                                           tanh_fast(f1.x + bb0.z), tanh_fast(f1.y + bb0.w));
            ((float4*)(hp + 4))[0] = make_float4(tanh_fast(f2.x + bb1.x), tanh_fast(f2.y + bb1.y),
                                                 tanh_fast(f3.x + bb1.z), tanh_fast(f3.y + bb1.w));
        }
        __syncthreads();
    }
    // ll2: [32 x 64] @ [64 x 64], 8 col-groups x 2 k-halves
    {
        const int h2 = wid >> 3, wq = wid & 7, col0 = wq * 8;
        u64 acc[4] = {0ull, 0ull, 0ull, 0ull};
        const float4* xf = (const float4*)(sm + OFF_H2 + l * SH);
        const float* Wb = ll_w2 + h2 * 32 * 64 + col0;
#pragma unroll
        for (int k4 = 0; k4 < 8; ++k4) {
            float4 x = xf[h2 * 8 + k4];
#pragma unroll
            for (int kk = 0; kk < 4; ++kk) {
                const float* wr = Wb + (k4 * 4 + kk) * 64;
                ulonglong2 wa = __ldg((const ulonglong2*)wr);
                ulonglong2 wb = __ldg((const ulonglong2*)(wr + 4));
                u64 xx = pkdup(xcomp(x, kk));
                fma2(acc[0], wa.x, xx); fma2(acc[1], wa.y, xx);
                fma2(acc[2], wb.x, xx); fma2(acc[3], wb.y, xx);
            }
        }
        float* rb = sm + OFF_RED + (wq * 32 + l) * SR;
        if (h2) {
            ((ulonglong2*)rb)[0]       = make_ulonglong2(acc[0], acc[1]);
            ((ulonglong2*)(rb + 4))[0] = make_ulonglong2(acc[2], acc[3]);
        }
        __syncthreads();
        if (!h2) {
            ulonglong2 ra = ((const ulonglong2*)rb)[0];
            ulonglong2 rc = ((const ulonglong2*)(rb + 4))[0];
            add2(acc[0], ra.x); add2(acc[1], ra.y);
            add2(acc[2], rc.x); add2(acc[3], rc.y);
            float4 bb0 = __ldg((const float4*)(ll_b2 + col0));
            float4 bb1 = __ldg((const float4*)(ll_b2 + col0 + 4));
            float2 f0 = up2(acc[0]), f1 = up2(acc[1]), f2 = up2(acc[2]), f3 = up2(acc[3]);
            float* hp = sm + OFF_H + l * SH + col0;   // reuse H rows 0-31
            ((float4*)hp)[0] = make_float4(tanh_fast(f0.x + bb0.x), tanh_fast(f0.y + bb0.y),
                                           tanh_fast(f1.x + bb0.z), tanh_fast(f1.y + bb0.w));
            ((float4*)(hp + 4))[0] = make_float4(tanh_fast(f2.x + bb1.x), tanh_fast(f2.y + bb1.y),
                                                 tanh_fast(f3.x + bb1.z), tanh_fast(f3.y + bb1.w));
        }
        __syncthreads();
    }
    // ll3: [32 x 64] @ [64 x 128], 16 col-groups, full k, accurate tanh
    {
        const int col0 = wid * 8;
        u64 acc[4] = {0ull, 0ull, 0ull, 0ull};
        const float4* xf = (const float4*)(sm + OFF_H + l * SH);
        const float* Wb = ll_w3 + col0;
#pragma unroll 2
        for (int k4 = 0; k4 < 16; ++k4) {
            float4 x = xf[k4];
#pragma unroll
            for (int kk = 0; kk < 4; ++kk) {
                const float* wr = Wb + (k4 * 4 + kk) * 128;
                ulonglong2 wa = __ldg((const ulonglong2*)wr);
                ulonglong2 wb = __ldg((const ulonglong2*)(wr + 4));
                u64 xx = pkdup(xcomp(x, kk));
                fma2(acc[0], wa.x, xx); fma2(acc[1], wa.y, xx);
                fma2(acc[2], wb.x, xx); fma2(acc[3], wb.y, xx);
            }
        }
        float4 bb0 = __ldg((const float4*)(ll_b3 + col0));
        float4 bb1 = __ldg((const float4*)(ll_b3 + col0 + 4));
        float2 f0 = up2(acc[0]), f1 = up2(acc[1]), f2 = up2(acc[2]), f3 = up2(acc[3]);
        float* op = out + ((size_t)blockIdx.x * R + l) * D + col0;
        ((float4*)op)[0] = make_float4(tanhf(f0.x + bb0.x), tanhf(f0.y + bb0.y),
                                       tanhf(f1.x + bb0.z), tanhf(f1.y + bb0.w));
        ((float4*)(op + 4))[0] = make_float4(tanhf(f2.x + bb1.x), tanhf(f2.y + bb1.y),
                                             tanhf(f3.x + bb1.z), tanhf(f3.y + bb1.w));
    }
}

extern "C" void kernel_launch(void* const* d_in, const int* in_sizes, int n_in,
                              void* d_out, int out_size) {
    const float* Lm     = (const float*)d_in[0];
    const float* Am     = (const float*)d_in[1];
    const float* Vm     = (const float*)d_in[2];
    const float* att_w  = (const float*)d_in[3];
    const float* att_b  = (const float*)d_in[4];
    const float* gf_w1  = (const float*)d_in[5];
    const float* gf_b1  = (const float*)d_in[6];
    const float* gf_w2  = (const float*)d_in[7];
    const float* gf_b2  = (const float*)d_in[8];
    const float* gf2_w1 = (const float*)d_in[9];
    const float* gf2_b1 = (const float*)d_in[10];
    const float* gf2_w2 = (const float*)d_in[11];
    const float* gf2_b2 = (const float*)d_in[12];
    const float* ll_w1  = (const float*)d_in[13];
    const float* ll_b1  = (const float*)d_in[14];
    const float* ll_w2  = (const float*)d_in[15];
    const float* ll_b2  = (const float*)d_in[16];
    const float* ll_w3  = (const float*)d_in[17];
    const float* ll_b3  = (const float*)d_in[18];

    int nrows = in_sizes[0] / D;
    int grid = nrows / R;
    size_t smem = (size_t)SMEM_FLOATS * sizeof(float);
    cudaFuncSetAttribute(graphfusion_kernel,
                         cudaFuncAttributeMaxDynamicSharedMemorySize, (int)smem);
    graphfusion_kernel<<<grid, NT, smem>>>(
        Lm, Am, Vm, att_w, att_b,
        gf_w1, gf_b1, gf_w2, gf_b2,
        gf2_w1, gf2_b1, gf2_w2, gf2_b2,
        ll_w1, ll_b1, ll_w2, ll_b2, ll_w3, ll_b3,
        (float*)d_out);
}

// round 6
// speedup vs baseline: 2.2132x; 2.2132x over previous
#include <cuda_runtime.h>
#include <mma.h>
#include <math.h>

using namespace nvcuda;

namespace {
constexpr int D = 128;
constexpr int R = 32;          // rows per block
constexpr int NT = 512;
constexpr int SA = 132;        // stride for [32][128] activation arrays (even, %32==4)
constexpr int SF = 388;        // fusion stride
constexpr int SH = 68;         // H stride
constexpr int OFF_A   = 0;
constexpr int OFF_V   = OFF_A + R * SA;
constexpr int OFF_L   = OFF_V + R * SA;
constexpr int OFF_G0  = OFF_L + R * SA;
constexpr int OFF_G1  = OFF_G0 + R * SA;
constexpr int OFF_G2  = OFF_G1 + R * SA;
constexpr int OFF_FUS = OFF_G2 + R * SA;    // [32][SF]
constexpr int OFF_H   = OFF_FUS + R * SF;   // [192][SH]
constexpr int OFF_H2  = OFF_H + 192 * SH;   // [32][SH]
constexpr int OFF_AW  = OFF_H2 + 32 * SH;   // [128]
constexpr int OFF_SC  = OFF_AW + 128;       // [32][16]
constexpr int SMEM_FLOATS = OFF_SC + R * 16;

// tf32-converted weight buffer (device global scratch; no allocations)
constexpr int WO_GF1 = 0;                       // gf_w1  [256x64]
constexpr int WO_GF2 = WO_GF1 + 256 * 64;       // gf_w2  [64x128]
constexpr int WO_G21 = WO_GF2 + 64 * 128;       // gf2_w1 [256x64]
constexpr int WO_G22 = WO_G21 + 256 * 64;       // gf2_w2 [64x128]
constexpr int WO_LL1 = WO_G22 + 64 * 128;       // ll_w1  [384x64]
constexpr int WO_LL2 = WO_LL1 + 384 * 64;       // ll_w2  [64x64]
constexpr int WO_LL3 = WO_LL2 + 64 * 64;        // ll_w3  [64x128]
constexpr int WTOT   = WO_LL3 + 64 * 128;       // 86016
}

__device__ float g_w[WTOT];

__device__ __forceinline__ float warp_sum(float x) {
#pragma unroll
    for (int o = 16; o > 0; o >>= 1) x += __shfl_xor_sync(0xffffffffu, x, o);
    return x;
}
__device__ __forceinline__ float warp_max(float x) {
#pragma unroll
    for (int o = 16; o > 0; o >>= 1) x = fmaxf(x, __shfl_xor_sync(0xffffffffu, x, o));
    return x;
}
__device__ __forceinline__ float tanh_fast(float x) {
    float y;
    asm("tanh.approx.f32 %0, %1;" : "=f"(y) : "f"(x));
    return y;
}
// round-to-nearest tf32 (result is an fp32 value exactly representable in tf32)
__device__ __forceinline__ float rna(float x) {
    unsigned u;
    asm("cvt.rna.tf32.f32 %0, %1;" : "=r"(u) : "f"(x));
    return __uint_as_float(u);
}
__device__ __forceinline__ float4 r4(float4 v) {
    return make_float4(rna(v.x), rna(v.y), rna(v.z), rna(v.w));
}

__global__ void convert_weights(
    const float* __restrict__ gf_w1, const float* __restrict__ gf_w2,
    const float* __restrict__ gf2_w1, const float* __restrict__ gf2_w2,
    const float* __restrict__ ll_w1, const float* __restrict__ ll_w2,
    const float* __restrict__ ll_w3)
{
    int i = blockIdx.x * 256 + threadIdx.x;
    if (i >= WTOT) return;
    float v;
    if      (i < WO_GF2) v = gf_w1[i - WO_GF1];
    else if (i < WO_G21) v = gf_w2[i - WO_GF2];
    else if (i < WO_G22) v = gf2_w1[i - WO_G21];
    else if (i < WO_LL1) v = gf2_w2[i - WO_G22];
    else if (i < WO_LL2) v = ll_w1[i - WO_LL1];
    else if (i < WO_LL3) v = ll_w2[i - WO_LL2];
    else                 v = ll_w3[i - WO_LL3];
    g_w[i] = rna(v);
}

// ---- A-operand source selectors (x for k<128, y for k>=128) ----
__device__ __forceinline__ const float* gf_src(const float* sm, int p, bool lo) {
    // pairs: (a,v) (a,l) (v,l)
    switch (p) {
        case 0:  return sm + (lo ? OFF_A : OFF_V);
        case 1:  return sm + (lo ? OFF_A : OFF_L);
        default: return sm + (lo ? OFF_V : OFF_L);
    }
}
__device__ __forceinline__ const float* gf2_src(const float* sm, int p, bool lo) {
    // pairs: (av,vl) (av,al) (vl,al) (av,l) (al,v) (vl,a)
    switch (p) {
        case 0:  return sm + (lo ? OFF_G0 : OFF_G2);
        case 1:  return sm + (lo ? OFF_G0 : OFF_G1);
        case 2:  return sm + (lo ? OFF_G2 : OFF_G1);
        case 3:  return sm + (lo ? OFF_G0 : OFF_L);
        case 4:  return sm + (lo ? OFF_G1 : OFF_V);
        default: return sm + (lo ? OFF_G2 : OFF_A);
    }
}

typedef wmma::fragment<wmma::matrix_a, 16, 16, 8, wmma::precision::tf32, wmma::row_major> FragA;
typedef wmma::fragment<wmma::matrix_b, 16, 16, 8, wmma::precision::tf32, wmma::row_major> FragB;
typedef wmma::fragment<wmma::accumulator, 16, 16, 8, float> FragC;

__global__ void __launch_bounds__(NT, 1)
graphfusion_kernel(
    const float* __restrict__ Lm, const float* __restrict__ Am, const float* __restrict__ Vm,
    const float* __restrict__ att_w, const float* __restrict__ att_b,
    const float* __restrict__ gf_b1, const float* __restrict__ gf_b2,
    const float* __restrict__ gf2_b1, const float* __restrict__ gf2_b2,
    const float* __restrict__ ll_b1, const float* __restrict__ ll_b2,
    const float* __restrict__ ll_b3,
    float* __restrict__ out)
{
    extern __shared__ float sm[];
    float* smA    = sm + OFF_A;
    float* smV    = sm + OFF_V;
    float* smL    = sm + OFF_L;
    float* smFus  = sm + OFF_FUS;
    float* smAttw = sm + OFF_AW;
    float* smScal = sm + OFF_SC;

    const int tid  = threadIdx.x;
    const int lane = tid & 31;
    const int wid  = tid >> 5;

    if (tid < D) smAttw[tid] = att_w[tid];
    __syncthreads();
    const float attb = __ldg(att_b);

    // ================= Phase A: scalars + softmaxes + unimodal =================
    {
        float4 aw = ((const float4*)smAttw)[lane];
#pragma unroll
        for (int rr = 0; rr < 2; ++rr) {
            int r = wid * 2 + rr;
            size_t grow = (size_t)blockIdx.x * R + r;
            float4 a4 = ((const float4*)(Am + grow * D))[lane];
            float4 v4 = ((const float4*)(Vm + grow * D))[lane];
            float4 l4 = ((const float4*)(Lm + grow * D))[lane];

            float sa = tanh_fast(warp_sum(a4.x * aw.x + a4.y * aw.y + a4.z * aw.z + a4.w * aw.w) + attb);
            float sv = tanh_fast(warp_sum(v4.x * aw.x + v4.y * aw.y + v4.z * aw.z + v4.w * aw.w) + attb);
            float sl = tanh_fast(warp_sum(l4.x * aw.x + l4.y * aw.y + l4.z * aw.z + l4.w * aw.w) + attb);

            float4 u;
            u.x = (sa * a4.x + sv * v4.x + sl * l4.x) * (1.0f / 3.0f);
            u.y = (sa * a4.y + sv * v4.y + sl * l4.y) * (1.0f / 3.0f);
            u.z = (sa * a4.z + sv * v4.z + sl * l4.z) * (1.0f / 3.0f);
            u.w = (sa * a4.w + sv * v4.w + sl * l4.w) * (1.0f / 3.0f);
            ((float4*)(smFus + r * SF))[lane] = r4(u);   // unimodal (tf32-rounded, feeds ll1)

            float ma = warp_max(fmaxf(fmaxf(a4.x, a4.y), fmaxf(a4.z, a4.w)));
            float4 ea = make_float4(__expf(a4.x - ma), __expf(a4.y - ma), __expf(a4.z - ma), __expf(a4.w - ma));
            float ia = 1.0f / warp_sum(ea.x + ea.y + ea.z + ea.w);
            float4 pa = make_float4(ea.x * ia, ea.y * ia, ea.z * ia, ea.w * ia);

            float mv = warp_max(fmaxf(fmaxf(v4.x, v4.y), fmaxf(v4.z, v4.w)));
            float4 ev = make_float4(__expf(v4.x - mv), __expf(v4.y - mv), __expf(v4.z - mv), __expf(v4.w - mv));
            float iv = 1.0f / warp_sum(ev.x + ev.y + ev.z + ev.w);
            float4 pv = make_float4(ev.x * iv, ev.y * iv, ev.z * iv, ev.w * iv);

            float ml = warp_max(fmaxf(fmaxf(l4.x, l4.y), fmaxf(l4.z, l4.w)));
            float4 el = make_float4(__expf(l4.x - ml), __expf(l4.y - ml), __expf(l4.z - ml), __expf(l4.w - ml));
            float il = 1.0f / warp_sum(el.x + el.y + el.z + el.w);
            float4 pl = make_float4(el.x * il, el.y * il, el.z * il, el.w * il);

            ((float4*)(smA + r * SA))[lane] = r4(pa);
            ((float4*)(smV + r * SA))[lane] = r4(pv);
            ((float4*)(smL + r * SA))[lane] = r4(pl);

            float dav = warp_sum(pa.x * pv.x + pa.y * pv.y + pa.z * pv.z + pa.w * pv.w);
            float dal = warp_sum(pa.x * pl.x + pa.y * pl.y + pa.z * pl.z + pa.w * pl.w);
            float dvl = warp_sum(pv.x * pl.x + pv.y * pl.y + pv.z * pl.z + pv.w * pl.w);

            float sav = (sa + sv) / (dav + 0.5f);
            float sal = (sa + sl) / (dal + 0.5f);
            float svl = (sl + sv) / (dvl + 0.5f);
            float mx = fmaxf(sav, fmaxf(sal, svl));
            float e0 = __expf(sav - mx), e1 = __expf(sal - mx), e2 = __expf(svl - mx);
            float is = 1.0f / (e0 + e1 + e2);
            if (lane == 0) {
                float* sc = smScal + r * 16;
                sc[0] = e0 * is; sc[1] = e1 * is; sc[2] = e2 * is;
                sc[3] = sav; sc[4] = sal; sc[5] = svl;
                sc[6] = sa;  sc[7] = sv;  sc[8] = sl;
            }
        }
    }
    __syncthreads();

    // ================= gf GEMM1: [96x256]@[256x64] -> raw H ====================
    if (wid < 12) {
        const int mh = wid >> 2, nt = wid & 3;
        FragC acc[2];
        wmma::fill_fragment(acc[0], 0.0f);
        wmma::fill_fragment(acc[1], 0.0f);
        FragA af; FragB bf;
        for (int kt = 0; kt < 32; ++kt) {
            wmma::load_matrix_sync(bf, g_w + WO_GF1 + kt * 8 * 64 + nt * 16, 64);
#pragma unroll
            for (int i = 0; i < 2; ++i) {
                int mt = mh * 2 + i;
                int p = mt >> 1, rr = (mt & 1) * 16;
                const float* xs = gf_src(sm, p, kt < 16);
                wmma::load_matrix_sync(af, xs + rr * SA + (kt & 15) * 8, SA);
                wmma::mma_sync(acc[i], af, bf, acc[i]);
            }
        }
#pragma unroll
        for (int i = 0; i < 2; ++i)
            wmma::store_matrix_sync(sm + OFF_H + (mh * 2 + i) * 16 * SH + nt * 16, acc[i], SH, wmma::mem_row_major);
    }
    __syncthreads();
    // epilogue: H = rna(leaky_relu(H + b1)) over [96][64]
    for (int idx = tid; idx < 96 * 64; idx += NT) {
        int r = idx >> 6, c = idx & 63;
        float v = sm[OFF_H + r * SH + c] + __ldg(gf_b1 + c);
        v = (v >= 0.0f) ? v : 0.2f * v;
        sm[OFF_H + r * SH + c] = rna(v);
    }
    __syncthreads();

    // ================= gf GEMM2: [96x64]@[64x128] -> raw G =====================
    {
        const int mh = wid >> 3, nt = wid & 7;
        FragC acc[3];
#pragma unroll
        for (int i = 0; i < 3; ++i) wmma::fill_fragment(acc[i], 0.0f);
        FragA af; FragB bf;
        for (int kt = 0; kt < 8; ++kt) {
            wmma::load_matrix_sync(bf, g_w + WO_GF2 + kt * 8 * 128 + nt * 16, 128);
#pragma unroll
            for (int i = 0; i < 3; ++i) {
                int mt = mh * 3 + i;
                wmma::load_matrix_sync(af, sm + OFF_H + mt * 16 * SH + kt * 8, SH);
                wmma::mma_sync(acc[i], af, bf, acc[i]);
            }
        }
#pragma unroll
        for (int i = 0; i < 3; ++i) {
            int mt = mh * 3 + i;
            int p = mt >> 1, rr = (mt & 1) * 16;
            wmma::store_matrix_sync(sm + OFF_G0 + p * R * SA + rr * SA + nt * 16, acc[i], SA, wmma::mem_row_major);
        }
    }
    __syncthreads();
    // epilogue: G = rna(tanh(G + b2)) over 3x[32][128]
    for (int idx = tid; idx < 96 * 128; idx += NT) {
        int r = idx >> 7, c = idx & 127;
        int p = r >> 5, rr = r & 31;
        float* gp = sm + OFF_G0 + p * R * SA + rr * SA + c;
        *gp = rna(tanh_fast(*gp + __ldg(gf_b2 + c)));
    }
    __syncthreads();

    // ============ Phase C: softmax(g) dots, n2, a_v/a_l/v_l, bimodal ============
    {
#pragma unroll
        for (int rr = 0; rr < 2; ++rr) {
            int r = wid * 2 + rr;
            float4 g0 = ((const float4*)(sm + OFF_G0 + r * SA))[lane];
            float4 g1 = ((const float4*)(sm + OFF_G1 + r * SA))[lane];
            float4 g2 = ((const float4*)(sm + OFF_G2 + r * SA))[lane];
            float4 pa = ((const float4*)(smA + r * SA))[lane];
            float4 pv = ((const float4*)(smV + r * SA))[lane];
            float4 pl = ((const float4*)(smL + r * SA))[lane];

            float m0 = warp_max(fmaxf(fmaxf(g0.x, g0.y), fmaxf(g0.z, g0.w)));
            float m1 = warp_max(fmaxf(fmaxf(g1.x, g1.y), fmaxf(g1.z, g1.w)));
            float m2 = warp_max(fmaxf(fmaxf(g2.x, g2.y), fmaxf(g2.z, g2.w)));
            float4 e0 = make_float4(__expf(g0.x - m0), __expf(g0.y - m0), __expf(g0.z - m0), __expf(g0.w - m0));
            float4 e1 = make_float4(__expf(g1.x - m1), __expf(g1.y - m1), __expf(g1.z - m1), __expf(g1.w - m1));
            float4 e2 = make_float4(__expf(g2.x - m2), __expf(g2.y - m2), __expf(g2.z - m2), __expf(g2.w - m2));
            float i0 = 1.0f / warp_sum(e0.x + e0.y + e0.z + e0.w);
            float i1 = 1.0f / warp_sum(e1.x + e1.y + e1.z + e1.w);
            float i2 = 1.0f / warp_sum(e2.x + e2.y + e2.z + e2.w);

            float d01 = warp_sum(e0.x * e1.x + e0.y * e1.y + e0.z * e1.z + e0.w * e1.w);
            float d02 = warp_sum(e0.x * e2.x + e0.y * e2.y + e0.z * e2.z + e0.w * e2.w);
            float d12 = warp_sum(e1.x * e2.x + e1.y * e2.y + e1.z * e2.z + e1.w * e2.w);
            float d0l = warp_sum(e0.x * pl.x + e0.y * pl.y + e0.z * pl.z + e0.w * pl.w);
            float d1v = warp_sum(e1.x * pv.x + e1.y * pv.y + e1.z * pv.z + e1.w * pv.w);
            float d2a = warp_sum(e2.x * pa.x + e2.y * pa.y + e2.z * pa.z + e2.w * pa.w);

            const float* sc = smScal + r * 16;
            float sav = sc[3], sal = sc[4], svl = sc[5];
            float sa = sc[6], sv = sc[7], sl = sc[8];
            float t0 = (sav + svl) / (d02 * i0 * i2 + 0.5f);
            float t1 = (sav + sal) / (d01 * i0 * i1 + 0.5f);
            float t2 = (sal + svl) / (d12 * i1 * i2 + 0.5f);
            float t3 = (sav + sl)  / (d0l * i0 + 0.5f);
            float t4 = (sal + sv)  / (d1v * i1 + 0.5f);
            float t5 = (sa  + svl) / (d2a * i2 + 0.5f);
            float mm = fmaxf(fmaxf(fmaxf(t0, t1), fmaxf(t2, t3)), fmaxf(t4, t5));
            float q0 = __expf(t0 - mm), q1 = __expf(t1 - mm), q2 = __expf(t2 - mm);
            float q3 = __expf(t3 - mm), q4 = __expf(t4 - mm), q5 = __expf(t5 - mm);
            float qi = 1.0f / (q0 + q1 + q2 + q3 + q4 + q5);
            if (lane == 0) {
                float* scw = smScal + r * 16;
                scw[9]  = q0 * qi; scw[10] = q1 * qi; scw[11] = q2 * qi;
                scw[12] = q3 * qi; scw[13] = q4 * qi; scw[14] = q5 * qi;
            }

            float n0 = sc[0], n1 = sc[1], n2v = sc[2];
            float4 av = make_float4(tanh_fast(n0 * g0.x), tanh_fast(n0 * g0.y), tanh_fast(n0 * g0.z), tanh_fast(n0 * g0.w));
            float4 al = make_float4(tanh_fast(n1 * g1.x), tanh_fast(n1 * g1.y), tanh_fast(n1 * g1.z), tanh_fast(n1 * g1.w));
            float4 vl = make_float4(tanh_fast(n2v * g2.x), tanh_fast(n2v * g2.y), tanh_fast(n2v * g2.z), tanh_fast(n2v * g2.w));
            ((float4*)(sm + OFF_G0 + r * SA))[lane] = r4(av);
            ((float4*)(sm + OFF_G1 + r * SA))[lane] = r4(al);
            ((float4*)(sm + OFF_G2 + r * SA))[lane] = r4(vl);
            float4 bm = make_float4(av.x + al.x + vl.x, av.y + al.y + vl.y,
                                    av.z + al.z + vl.z, av.w + al.w + vl.w);
            ((float4*)(smFus + r * SF + 128))[lane] = r4(bm);
        }
    }
    __syncthreads();

    // ======== merged gf2 GEMM1 (6 pairs): [192x256]@[256x64] -> raw H ========
    {
        const int mh = wid >> 2, nt = wid & 3;
        FragC acc[3];
#pragma unroll
        for (int i = 0; i < 3; ++i) wmma::fill_fragment(acc[i], 0.0f);
        FragA af; FragB bf;
        for (int kt = 0; kt < 32; ++kt) {
            wmma::load_matrix_sync(bf, g_w + WO_G21 + kt * 8 * 64 + nt * 16, 64);
#pragma unroll
            for (int i = 0; i < 3; ++i) {
                int mt = mh * 3 + i;
                int p = mt >> 1, rr = (mt & 1) * 16;
                const float* xs = gf2_src(sm, p, kt < 16);
                wmma::load_matrix_sync(af, xs + rr * SA + (kt & 15) * 8, SA);
                wmma::mma_sync(acc[i], af, bf, acc[i]);
            }
        }
#pragma unroll
        for (int i = 0; i < 3; ++i)
            wmma::store_matrix_sync(sm + OFF_H + (mh * 3 + i) * 16 * SH + nt * 16, acc[i], SH, wmma::mem_row_major);
    }
    __syncthreads();
    for (int idx = tid; idx < 192 * 64; idx += NT) {
        int r = idx >> 6, c = idx & 63;
        float v = sm[OFF_H + r * SH + c] + __ldg(gf2_b1 + c);
        v = (v >= 0.0f) ? v : 0.2f * v;
        sm[OFF_H + r * SH + c] = rna(v);
    }
    __syncthreads();

    // ======== merged gf2 GEMM2: [192x64]@[64x128] -> raw into G/A/V/L ========
    {
        const int mh = wid >> 3, nt = wid & 7;
        FragC acc[6];
#pragma unroll
        for (int i = 0; i < 6; ++i) wmma::fill_fragment(acc[i], 0.0f);
        FragA af; FragB bf;
        for (int kt = 0; kt < 8; ++kt) {
            wmma::load_matrix_sync(bf, g_w + WO_G22 + kt * 8 * 128 + nt * 16, 128);
#pragma unroll
            for (int i = 0; i < 6; ++i) {
                int mt = mh * 6 + i;
                wmma::load_matrix_sync(af, sm + OFF_H + mt * 16 * SH + kt * 8, SH);
                wmma::mma_sync(acc[i], af, bf, acc[i]);
            }
        }
#pragma unroll
        for (int i = 0; i < 6; ++i) {
            int mt = mh * 6 + i;
            int p = mt >> 1, rr = (mt & 1) * 16;
            int base = (p < 3) ? (OFF_G0 + p * R * SA) : (OFF_A + (p - 3) * R * SA);
            wmma::store_matrix_sync(sm + base + rr * SA + nt * 16, acc[i], SA, wmma::mem_row_major);
        }
    }
    __syncthreads();
    // trimodal epilogue: fus[r][256+c] = rna( sum_p tanh(n2[p]*tanh(Cp + b2[c])) )
    for (int idx = tid; idx < 32 * 128; idx += NT) {
        int r = idx >> 7, c = idx & 127;
        const float* sc = smScal + r * 16 + 9;
        float b = __ldg(gf2_b2 + c);
        float s = 0.0f;
#pragma unroll
        for (int p = 0; p < 6; ++p) {
            int base = (p < 3) ? (OFF_G0 + p * R * SA) : (OFF_A + (p - 3) * R * SA);
            s += tanh_fast(sc[p] * tanh_fast(sm[base + r * SA + c] + b));
        }
        smFus[r * SF + 256 + c] = rna(s);
    }
    __syncthreads();

    // ================= ll1: [32x384]@[384x64] =================
    if (wid < 8) {
        const int mt = wid >> 2, nt = wid & 3;
        FragC acc;
        wmma::fill_fragment(acc, 0.0f);
        FragA af; FragB bf;
        for (int kt = 0; kt < 48; ++kt) {
            wmma::load_matrix_sync(bf, g_w + WO_LL1 + kt * 8 * 64 + nt * 16, 64);
            wmma::load_matrix_sync(af, smFus + mt * 16 * SF + kt * 8, SF);
            wmma::mma_sync(acc, af, bf, acc);
        }
        wmma::store_matrix_sync(sm + OFF_G1 + mt * 16 * SA + nt * 16, acc, SA, wmma::mem_row_major);
    }
    __syncthreads();
    for (int idx = tid; idx < 32 * 64; idx += NT) {
        int r = idx >> 6, c = idx & 63;
        sm[OFF_H2 + r * SH + c] = rna(tanh_fast(sm[OFF_G1 + r * SA + c] + __ldg(ll_b1 + c)));
    }
    __syncthreads();

    // ================= ll2: [32x64]@[64x64] =================
    if (wid < 8) {
        const int mt = wid >> 2, nt = wid & 3;
        FragC acc;
        wmma::fill_fragment(acc, 0.0f);
        FragA af; FragB bf;
        for (int kt = 0; kt < 8; ++kt) {
            wmma::load_matrix_sync(bf, g_w + WO_LL2 + kt * 8 * 64 + nt * 16, 64);
            wmma::load_matrix_sync(af, sm + OFF_H2 + mt * 16 * SH + kt * 8, SH);
            wmma::mma_sync(acc, af, bf, acc);
        }
        wmma::store_matrix_sync(sm + OFF_G1 + mt * 16 * SA + nt * 16, acc, SA, wmma::mem_row_major);
    }
    __syncthreads();
    for (int idx = tid; idx < 32 * 64; idx += NT) {
        int r = idx >> 6, c = idx & 63;
        sm[OFF_H + r * SH + c] = rna(tanh_fast(sm[OFF_G1 + r * SA + c] + __ldg(ll_b2 + c)));
    }
    __syncthreads();

    // ================= ll3: [32x64]@[64x128] =================
    {
        const int mt = wid >> 3, nt = wid & 7;
        FragC acc;
        wmma::fill_fragment(acc, 0.0f);
        FragA af; FragB bf;
        for (int kt = 0; kt < 8; ++kt) {
            wmma::load_matrix_sync(bf, g_w + WO_LL3 + kt * 8 * 128 + nt * 16, 128);
            wmma::load_matrix_sync(af, sm + OFF_H + mt * 16 * SH + kt * 8, SH);
            wmma::mma_sync(acc, af, bf, acc);
        }
        wmma::store_matrix_sync(sm + OFF_G0 + mt * 16 * SA + nt * 16, acc, SA, wmma::mem_row_major);
    }
    __syncthreads();
    // output: out = tanh(C + b3), accurate tanh, coalesced float4 stores
    for (int idx = tid; idx < 32 * 32; idx += NT) {
        int r = idx >> 5, c = (idx & 31) * 4;
        float4 b = __ldg((const float4*)(ll_b3 + c));
        const float* gp = sm + OFF_G0 + r * SA + c;
        float4 o = make_float4(tanhf(gp[0] + b.x), tanhf(gp[1] + b.y),
                               tanhf(gp[2] + b.z), tanhf(gp[3] + b.w));
        ((float4*)(out + ((size_t)blockIdx.x * R + r) * D + c))[0] = o;
    }
}

extern "C" void kernel_launch(void* const* d_in, const int* in_sizes, int n_in,
                              void* d_out, int out_size) {
    const float* Lm     = (const float*)d_in[0];
    const float* Am     = (const float*)d_in[1];
    const float* Vm     = (const float*)d_in[2];
    const float* att_w  = (const float*)d_in[3];
    const float* att_b  = (const float*)d_in[4];
    const float* gf_w1  = (const float*)d_in[5];
    const float* gf_b1  = (const float*)d_in[6];
    const float* gf_w2  = (const float*)d_in[7];
    const float* gf_b2  = (const float*)d_in[8];
    const float* gf2_w1 = (const float*)d_in[9];
    const float* gf2_b1 = (const float*)d_in[10];
    const float* gf2_w2 = (const float*)d_in[11];
    const float* gf2_b2 = (const float*)d_in[12];
    const float* ll_w1  = (const float*)d_in[13];
    const float* ll_b1  = (const float*)d_in[14];
    const float* ll_w2  = (const float*)d_in[15];
    const float* ll_b2  = (const float*)d_in[16];
    const float* ll_w3  = (const float*)d_in[17];
    const float* ll_b3  = (const float*)d_in[18];

    convert_weights<<<(WTOT + 255) / 256, 256>>>(gf_w1, gf_w2, gf2_w1, gf2_w2,
                                                 ll_w1, ll_w2, ll_w3);

    int nrows = in_sizes[0] / D;
    int grid = nrows / R;
    size_t smem = (size_t)SMEM_FLOATS * sizeof(float);
    cudaFuncSetAttribute(graphfusion_kernel,
                         cudaFuncAttributeMaxDynamicSharedMemorySize, (int)smem);
    graphfusion_kernel<<<grid, NT, smem>>>(
        Lm, Am, Vm, att_w, att_b,
        gf_b1, gf_b2, gf2_b1, gf2_b2,
        ll_b1, ll_b2, ll_b3,
        (float*)d_out);
}

// round 7
// speedup vs baseline: 2.4896x; 1.1249x over previous
#include <cuda_runtime.h>
#include <mma.h>
#include <math.h>

using namespace nvcuda;

namespace {
constexpr int D = 128;
constexpr int R = 16;           // rows per block
constexpr int NT = 256;         // 8 warps
constexpr int SA = 136;         // activation stride ([16][128] + const cols 128..135)
constexpr int SF = 392;         // fusion stride ([16][384] + const cols 384..391)
constexpr int SH = 72;          // H stride ([.][64] + const cols 64..71)
constexpr int OFF_A   = 0;                  // buffers: A(0) V(1) L(2) G0(3) G1(4) G2(5), each [16][SA]
constexpr int OFF_G0  = OFF_A + 3 * R * SA;
constexpr int OFF_FUS = OFF_A + 6 * R * SA; // [16][SF]
constexpr int OFF_H   = OFF_FUS + R * SF;   // [96][SH]
constexpr int OFF_H2  = OFF_H + 96 * SH;    // [16][SH]
constexpr int OFF_AW  = OFF_H2 + R * SH;    // [128]
constexpr int OFF_SC  = OFF_AW + 128;       // [16][16]
constexpr int SMEM_FLOATS = OFF_SC + R * 16;   // 27776 floats = 111104 B

// tf32 weight images with bias row folded in (K padded to multiple of 8)
constexpr int WO_GF1 = 0;                        // [264 x  64]
constexpr int WO_GF2 = WO_GF1 + 264 * 64;        // [ 72 x 128]
constexpr int WO_G21 = WO_GF2 + 72 * 128;        // [264 x  64]
constexpr int WO_G22 = WO_G21 + 264 * 64;        // [ 72 x 128]
constexpr int WO_LL1 = WO_G22 + 72 * 128;        // [392 x  64]
constexpr int WO_LL2 = WO_LL1 + 392 * 64;        // [ 72 x  64]
constexpr int WO_LL3 = WO_LL2 + 72 * 64;         // [ 72 x 128]
constexpr int WTOT   = WO_LL3 + 72 * 128;        // 91136
}

__device__ float g_w[WTOT];

__device__ __forceinline__ float warp_sum(float x) {
#pragma unroll
    for (int o = 16; o > 0; o >>= 1) x += __shfl_xor_sync(0xffffffffu, x, o);
    return x;
}
__device__ __forceinline__ float warp_max(float x) {
#pragma unroll
    for (int o = 16; o > 0; o >>= 1) x = fmaxf(x, __shfl_xor_sync(0xffffffffu, x, o));
    return x;
}
__device__ __forceinline__ float tanh_fast(float x) {
    float y;
    asm("tanh.approx.f32 %0, %1;" : "=f"(y) : "f"(x));
    return y;
}
__device__ __forceinline__ float rna(float x) {
    unsigned u;
    asm("cvt.rna.tf32.f32 %0, %1;" : "=r"(u) : "f"(x));
    return __uint_as_float(u);
}
__device__ __forceinline__ float4 r4(float4 v) {
    return make_float4(rna(v.x), rna(v.y), rna(v.z), rna(v.w));
}

__global__ void convert_weights(
    const float* __restrict__ gf_w1, const float* __restrict__ gf_b1,
    const float* __restrict__ gf_w2, const float* __restrict__ gf_b2,
    const float* __restrict__ gf2_w1, const float* __restrict__ gf2_b1,
    const float* __restrict__ gf2_w2, const float* __restrict__ gf2_b2,
    const float* __restrict__ ll_w1, const float* __restrict__ ll_b1,
    const float* __restrict__ ll_w2, const float* __restrict__ ll_b2,
    const float* __restrict__ ll_w3, const float* __restrict__ ll_b3)
{
    int i = blockIdx.x * 256 + threadIdx.x;
    if (i >= WTOT) return;
    float v = 0.0f;
    if (i < WO_GF2) {
        int j = i - WO_GF1, r = j >> 6, c = j & 63;
        v = (r < 256) ? gf_w1[r * 64 + c] : ((r == 256) ? gf_b1[c] : 0.0f);
    } else if (i < WO_G21) {
        int j = i - WO_GF2, r = j >> 7, c = j & 127;
        v = (r < 64) ? gf_w2[r * 128 + c] : ((r == 64) ? gf_b2[c] : 0.0f);
    } else if (i < WO_G22) {
        int j = i - WO_G21, r = j >> 6, c = j & 63;
        v = (r < 256) ? gf2_w1[r * 64 + c] : ((r == 256) ? gf2_b1[c] : 0.0f);
    } else if (i < WO_LL1) {
        int j = i - WO_G22, r = j >> 7, c = j & 127;
        v = (r < 64) ? gf2_w2[r * 128 + c] : ((r == 64) ? gf2_b2[c] : 0.0f);
    } else if (i < WO_LL2) {
        int j = i - WO_LL1, r = j >> 6, c = j & 63;
        v = (r < 384) ? ll_w1[r * 64 + c] : ((r == 384) ? ll_b1[c] : 0.0f);
    } else if (i < WO_LL3) {
        int j = i - WO_LL2, r = j >> 6, c = j & 63;
        v = (r < 64) ? ll_w2[r * 64 + c] : ((r == 64) ? ll_b2[c] : 0.0f);
    } else {
        int j = i - WO_LL3, r = j >> 7, c = j & 127;
        v = (r < 64) ? ll_w3[r * 128 + c] : ((r == 64) ? ll_b3[c] : 0.0f);
    }
    g_w[i] = rna(v);
}

typedef wmma::fragment<wmma::matrix_a, 16, 16, 8, wmma::precision::tf32, wmma::row_major> FragA;
typedef wmma::fragment<wmma::matrix_b, 16, 16, 8, wmma::precision::tf32, wmma::row_major> FragB;
typedef wmma::fragment<wmma::accumulator, 16, 16, 8, float> FragC;

__global__ void __launch_bounds__(NT, 2)
graphfusion_kernel(
    const float* __restrict__ Lm, const float* __restrict__ Am, const float* __restrict__ Vm,
    const float* __restrict__ att_w, const float* __restrict__ att_b,
    float* __restrict__ out)
{
    extern __shared__ float sm[];
    const int tid  = threadIdx.x;
    const int lane = tid & 31;
    const int wid  = tid >> 5;   // 0..7

    // ---- init: att_w + constant bias columns ([1,0,0,0,0,0,0,0]) ----
    if (tid < D) sm[OFF_AW + tid] = att_w[tid];
    for (int idx = tid; idx < 1792; idx += NT) {
        int addr, c;
        if (idx < 768)       { int b = idx >> 7, rem = idx & 127; int r = rem >> 3; c = rem & 7;
                               addr = b * (R * SA) + r * SA + 128 + c; }
        else if (idx < 896)  { int i = idx - 768;  int r = i >> 3; c = i & 7; addr = OFF_FUS + r * SF + 384 + c; }
        else if (idx < 1664) { int i = idx - 896;  int r = i >> 3; c = i & 7; addr = OFF_H  + r * SH + 64 + c; }
        else                 { int i = idx - 1664; int r = i >> 3; c = i & 7; addr = OFF_H2 + r * SH + 64 + c; }
        sm[addr] = (c == 0) ? 1.0f : 0.0f;
    }
    __syncthreads();
    const float attb = __ldg(att_b);

    // ================= Phase A: scalars + softmaxes + unimodal =================
    {
        float4 aw = ((const float4*)(sm + OFF_AW))[lane];
#pragma unroll
        for (int rr = 0; rr < 2; ++rr) {
            int r = wid * 2 + rr;
            size_t grow = (size_t)blockIdx.x * R + r;
            float4 a4 = ((const float4*)(Am + grow * D))[lane];
            float4 v4 = ((const float4*)(Vm + grow * D))[lane];
            float4 l4 = ((const float4*)(Lm + grow * D))[lane];

            float sa = tanh_fast(warp_sum(a4.x * aw.x + a4.y * aw.y + a4.z * aw.z + a4.w * aw.w) + attb);
            float sv = tanh_fast(warp_sum(v4.x * aw.x + v4.y * aw.y + v4.z * aw.z + v4.w * aw.w) + attb);
            float sl = tanh_fast(warp_sum(l4.x * aw.x + l4.y * aw.y + l4.z * aw.z + l4.w * aw.w) + attb);

            float4 u;
            u.x = (sa * a4.x + sv * v4.x + sl * l4.x) * (1.0f / 3.0f);
            u.y = (sa * a4.y + sv * v4.y + sl * l4.y) * (1.0f / 3.0f);
            u.z = (sa * a4.z + sv * v4.z + sl * l4.z) * (1.0f / 3.0f);
            u.w = (sa * a4.w + sv * v4.w + sl * l4.w) * (1.0f / 3.0f);
            ((float4*)(sm + OFF_FUS + r * SF))[lane] = r4(u);

            float ma = warp_max(fmaxf(fmaxf(a4.x, a4.y), fmaxf(a4.z, a4.w)));
            float4 ea = make_float4(__expf(a4.x - ma), __expf(a4.y - ma), __expf(a4.z - ma), __expf(a4.w - ma));
            float ia = 1.0f / warp_sum(ea.x + ea.y + ea.z + ea.w);
            float4 pa = make_float4(ea.x * ia, ea.y * ia, ea.z * ia, ea.w * ia);

            float mv = warp_max(fmaxf(fmaxf(v4.x, v4.y), fmaxf(v4.z, v4.w)));
            float4 ev = make_float4(__expf(v4.x - mv), __expf(v4.y - mv), __expf(v4.z - mv), __expf(v4.w - mv));
            float iv = 1.0f / warp_sum(ev.x + ev.y + ev.z + ev.w);
            float4 pv = make_float4(ev.x * iv, ev.y * iv, ev.z * iv, ev.w * iv);

            float ml = warp_max(fmaxf(fmaxf(l4.x, l4.y), fmaxf(l4.z, l4.w)));
            float4 el = make_float4(__expf(l4.x - ml), __expf(l4.y - ml), __expf(l4.z - ml), __expf(l4.w - ml));
            float il = 1.0f / warp_sum(el.x + el.y + el.z + el.w);
            float4 pl = make_float4(el.x * il, el.y * il, el.z * il, el.w * il);

            ((float4*)(sm + OFF_A + 0 * R * SA + r * SA))[lane] = r4(pa);
            ((float4*)(sm + OFF_A + 1 * R * SA + r * SA))[lane] = r4(pv);
            ((float4*)(sm + OFF_A + 2 * R * SA + r * SA))[lane] = r4(pl);

            float dav = warp_sum(pa.x * pv.x + pa.y * pv.y + pa.z * pv.z + pa.w * pv.w);
            float dal = warp_sum(pa.x * pl.x + pa.y * pl.y + pa.z * pl.z + pa.w * pl.w);
            float dvl = warp_sum(pv.x * pl.x + pv.y * pl.y + pv.z * pl.z + pv.w * pl.w);

            float sav = (sa + sv) / (dav + 0.5f);
            float sal = (sa + sl) / (dal + 0.5f);
            float svl = (sl + sv) / (dvl + 0.5f);
            float mx = fmaxf(sav, fmaxf(sal, svl));
            float e0 = __expf(sav - mx), e1 = __expf(sal - mx), e2 = __expf(svl - mx);
            float is = 1.0f / (e0 + e1 + e2);
            if (lane == 0) {
                float* sc = sm + OFF_SC + r * 16;
                sc[0] = e0 * is; sc[1] = e1 * is; sc[2] = e2 * is;
                sc[3] = sav; sc[4] = sal; sc[5] = svl;
                sc[6] = sa;  sc[7] = sv;  sc[8] = sl;
            }
        }
    }
    __syncthreads();

    // ===== gf GEMM1: [48 x 264] @ [264 x 64], bias in K-pad; leaky_relu in fragment =====
    {
        const int gfx[3] = {0, 0, 1}, gfy[3] = {1, 2, 2};   // pairs (a,v)(a,l)(v,l)
        FragA af; FragB bf;
        for (int t = wid; t < 12; t += 8) {
            int mt = t >> 2, nt = t & 3;
            FragC acc; wmma::fill_fragment(acc, 0.0f);
            for (int kt = 0; kt < 33; ++kt) {
                wmma::load_matrix_sync(bf, g_w + WO_GF1 + kt * 8 * 64 + nt * 16, 64);
                int b   = (kt < 16) ? gfx[mt] : ((kt < 32) ? gfy[mt] : gfx[mt]);
                int off = (kt < 16) ? kt * 8  : ((kt < 32) ? (kt - 16) * 8 : 128);
                wmma::load_matrix_sync(af, sm + b * (R * SA) + off, SA);
                wmma::mma_sync(acc, af, bf, acc);
            }
#pragma unroll
            for (int e = 0; e < acc.num_elements; ++e) {
                float v = acc.x[e];
                acc.x[e] = rna((v >= 0.0f) ? v : 0.2f * v);
            }
            wmma::store_matrix_sync(sm + OFF_H + mt * 16 * SH + nt * 16, acc, SH, wmma::mem_row_major);
        }
    }
    __syncthreads();

    // ===== gf GEMM2: [48 x 72] @ [72 x 128]; tanh in fragment -> G0/G1/G2 =====
    {
        const int nt = wid;
        FragC acc[3];
#pragma unroll
        for (int i = 0; i < 3; ++i) wmma::fill_fragment(acc[i], 0.0f);
        FragA af; FragB bf;
        for (int kt = 0; kt < 9; ++kt) {
            wmma::load_matrix_sync(bf, g_w + WO_GF2 + kt * 8 * 128 + nt * 16, 128);
#pragma unroll
            for (int i = 0; i < 3; ++i) {
                wmma::load_matrix_sync(af, sm + OFF_H + i * 16 * SH + kt * 8, SH);
                wmma::mma_sync(acc[i], af, bf, acc[i]);
            }
        }
#pragma unroll
        for (int i = 0; i < 3; ++i) {
#pragma unroll
            for (int e = 0; e < acc[i].num_elements; ++e)
                acc[i].x[e] = rna(tanh_fast(acc[i].x[e]));
            wmma::store_matrix_sync(sm + OFF_G0 + i * (R * SA) + nt * 16, acc[i], SA, wmma::mem_row_major);
        }
    }
    __syncthreads();

    // ============ Phase C: softmax(g) dots, n2, a_v/a_l/v_l, bimodal ============
    {
#pragma unroll
        for (int rr = 0; rr < 2; ++rr) {
            int r = wid * 2 + rr;
            float4 g0 = ((const float4*)(sm + OFF_A + 3 * R * SA + r * SA))[lane];
            float4 g1 = ((const float4*)(sm + OFF_A + 4 * R * SA + r * SA))[lane];
            float4 g2 = ((const float4*)(sm + OFF_A + 5 * R * SA + r * SA))[lane];
            float4 pa = ((const float4*)(sm + OFF_A + 0 * R * SA + r * SA))[lane];
            float4 pv = ((const float4*)(sm + OFF_A + 1 * R * SA + r * SA))[lane];
            float4 pl = ((const float4*)(sm + OFF_A + 2 * R * SA + r * SA))[lane];

            float m0 = warp_max(fmaxf(fmaxf(g0.x, g0.y), fmaxf(g0.z, g0.w)));
            float m1 = warp_max(fmaxf(fmaxf(g1.x, g1.y), fmaxf(g1.z, g1.w)));
            float m2 = warp_max(fmaxf(fmaxf(g2.x, g2.y), fmaxf(g2.z, g2.w)));
            float4 e0 = make_float4(__expf(g0.x - m0), __expf(g0.y - m0), __expf(g0.z - m0), __expf(g0.w - m0));
            float4 e1 = make_float4(__expf(g1.x - m1), __expf(g1.y - m1), __expf(g1.z - m1), __expf(g1.w - m1));
            float4 e2 = make_float4(__expf(g2.x - m2), __expf(g2.y - m2), __expf(g2.z - m2), __expf(g2.w - m2));
            float i0 = 1.0f / warp_sum(e0.x + e0.y + e0.z + e0.w);
            float i1 = 1.0f / warp_sum(e1.x + e1.y + e1.z + e1.w);
            float i2 = 1.0f / warp_sum(e2.x + e2.y + e2.z + e2.w);

            float d01 = warp_sum(e0.x * e1.x + e0.y * e1.y + e0.z * e1.z + e0.w * e1.w);
            float d02 = warp_sum(e0.x * e2.x + e0.y * e2.y + e0.z * e2.z + e0.w * e2.w);
            float d12 = warp_sum(e1.x * e2.x + e1.y * e2.y + e1.z * e2.z + e1.w * e2.w);
            float d0l = warp_sum(e0.x * pl.x + e0.y * pl.y + e0.z * pl.z + e0.w * pl.w);
            float d1v = warp_sum(e1.x * pv.x + e1.y * pv.y + e1.z * pv.z + e1.w * pv.w);
            float d2a = warp_sum(e2.x * pa.x + e2.y * pa.y + e2.z * pa.z + e2.w * pa.w);

            const float* sc = sm + OFF_SC + r * 16;
            float sav = sc[3], sal = sc[4], svl = sc[5];
            float sa = sc[6], sv = sc[7], sl = sc[8];
            float t0 = (sav + svl) / (d02 * i0 * i2 + 0.5f);
            float t1 = (sav + sal) / (d01 * i0 * i1 + 0.5f);
            float t2 = (sal + svl) / (d12 * i1 * i2 + 0.5f);
            float t3 = (sav + sl)  / (d0l * i0 + 0.5f);
            float t4 = (sal + sv)  / (d1v * i1 + 0.5f);
            float t5 = (sa  + svl) / (d2a * i2 + 0.5f);
            float mm = fmaxf(fmaxf(fmaxf(t0, t1), fmaxf(t2, t3)), fmaxf(t4, t5));
            float q0 = __expf(t0 - mm), q1 = __expf(t1 - mm), q2 = __expf(t2 - mm);
            float q3 = __expf(t3 - mm), q4 = __expf(t4 - mm), q5 = __expf(t5 - mm);
            float qi = 1.0f / (q0 + q1 + q2 + q3 + q4 + q5);
            if (lane == 0) {
                float* scw = sm + OFF_SC + r * 16;
                scw[9]  = q0 * qi; scw[10] = q1 * qi; scw[11] = q2 * qi;
                scw[12] = q3 * qi; scw[13] = q4 * qi; scw[14] = q5 * qi;
            }

            float n0 = sc[0], n1 = sc[1], n2v = sc[2];
            float4 av = make_float4(tanh_fast(n0 * g0.x), tanh_fast(n0 * g0.y), tanh_fast(n0 * g0.z), tanh_fast(n0 * g0.w));
            float4 al = make_float4(tanh_fast(n1 * g1.x), tanh_fast(n1 * g1.y), tanh_fast(n1 * g1.z), tanh_fast(n1 * g1.w));
            float4 vl = make_float4(tanh_fast(n2v * g2.x), tanh_fast(n2v * g2.y), tanh_fast(n2v * g2.z), tanh_fast(n2v * g2.w));
            ((float4*)(sm + OFF_A + 3 * R * SA + r * SA))[lane] = r4(av);
            ((float4*)(sm + OFF_A + 4 * R * SA + r * SA))[lane] = r4(al);
            ((float4*)(sm + OFF_A + 5 * R * SA + r * SA))[lane] = r4(vl);
            float4 bm = make_float4(av.x + al.x + vl.x, av.y + al.y + vl.y,
                                    av.z + al.z + vl.z, av.w + al.w + vl.w);
            ((float4*)(sm + OFF_FUS + r * SF + 128))[lane] = r4(bm);
        }
    }
    __syncthreads();

    // ===== gf2 GEMM1 (6 pairs merged): [96 x 264] @ [264 x 64]; leaky in fragment =====
    {
        const int g2x[6] = {3, 3, 5, 3, 4, 5}, g2y[6] = {5, 4, 4, 2, 1, 0};
        const int mh = wid >> 2, nt = wid & 3;
        FragC acc[3];
#pragma unroll
        for (int i = 0; i < 3; ++i) wmma::fill_fragment(acc[i], 0.0f);
        FragA af; FragB bf;
        for (int kt = 0; kt < 33; ++kt) {
            wmma::load_matrix_sync(bf, g_w + WO_G21 + kt * 8 * 64 + nt * 16, 64);
#pragma unroll
            for (int i = 0; i < 3; ++i) {
                int mt = mh * 3 + i;
                int b   = (kt < 16) ? g2x[mt] : ((kt < 32) ? g2y[mt] : g2x[mt]);
                int off = (kt < 16) ? kt * 8  : ((kt < 32) ? (kt - 16) * 8 : 128);
                wmma::load_matrix_sync(af, sm + b * (R * SA) + off, SA);
                wmma::mma_sync(acc[i], af, bf, acc[i]);
            }
        }
#pragma unroll
        for (int i = 0; i < 3; ++i) {
#pragma unroll
            for (int e = 0; e < acc[i].num_elements; ++e) {
                float v = acc[i].x[e];
                acc[i].x[e] = rna((v >= 0.0f) ? v : 0.2f * v);
            }
            wmma::store_matrix_sync(sm + OFF_H + (mh * 3 + i) * 16 * SH + nt * 16, acc[i], SH, wmma::mem_row_major);
        }
    }
    __syncthreads();

    // ===== gf2 GEMM2: [96 x 72] @ [72 x 128] raw -> scratch (G0,G1,G2,A,V,L) =====
    {
        const int nt = wid;
        FragC acc[6];
#pragma unroll
        for (int i = 0; i < 6; ++i) wmma::fill_fragment(acc[i], 0.0f);
        FragA af; FragB bf;
        for (int kt = 0; kt < 9; ++kt) {
            wmma::load_matrix_sync(bf, g_w + WO_G22 + kt * 8 * 128 + nt * 16, 128);
#pragma unroll
            for (int i = 0; i < 6; ++i) {
                wmma::load_matrix_sync(af, sm + OFF_H + i * 16 * SH + kt * 8, SH);
                wmma::mma_sync(acc[i], af, bf, acc[i]);
            }
        }
#pragma unroll
        for (int i = 0; i < 6; ++i) {
            int bidx = (i < 3) ? (3 + i) : (i - 3);
            wmma::store_matrix_sync(sm + bidx * (R * SA) + nt * 16, acc[i], SA, wmma::mem_row_major);
        }
    }
    __syncthreads();

    // ===== trimodal epilogue: fus[r][256+c] = sum_p tanh(n2[p]*tanh(raw_p)) =====
    for (int idx = tid; idx < 16 * 128; idx += NT) {
        int r = idx >> 7, c = idx & 127;
        const float* sc = sm + OFF_SC + r * 16 + 9;
        float s = 0.0f;
#pragma unroll
        for (int p = 0; p < 6; ++p) {
            int bidx = (p < 3) ? (3 + p) : (p - 3);
            s += tanh_fast(sc[p] * tanh_fast(sm[bidx * (R * SA) + r * SA + c]));
        }
        sm[OFF_FUS + r * SF + 256 + c] = rna(s);
    }
    __syncthreads();

    // ===== ll1: [16 x 392] @ [392 x 64], 2-way k-split, raw partials in H =====
    {
        const int part = wid >> 2, nt = wid & 3;
        FragC acc; wmma::fill_fragment(acc, 0.0f);
        FragA af; FragB bf;
        const int k0 = part ? 25 : 0, k1 = part ? 49 : 25;
        for (int kt = k0; kt < k1; ++kt) {
            wmma::load_matrix_sync(bf, g_w + WO_LL1 + kt * 8 * 64 + nt * 16, 64);
            wmma::load_matrix_sync(af, sm + OFF_FUS + kt * 8, SF);
            wmma::mma_sync(acc, af, bf, acc);
        }
        wmma::store_matrix_sync(sm + OFF_H + part * 16 * SH + nt * 16, acc, SH, wmma::mem_row_major);
    }
    __syncthreads();
    for (int idx = tid; idx < 16 * 64; idx += NT) {
        int r = idx >> 6, c = idx & 63;
        float v = sm[OFF_H + r * SH + c] + sm[OFF_H + (16 + r) * SH + c];
        sm[OFF_H2 + r * SH + c] = rna(tanh_fast(v));
    }
    __syncthreads();

    // ===== ll2: [16 x 72] @ [72 x 64]; tanh in fragment -> H rows 0..15 =====
    if (wid < 4) {
        const int nt = wid;
        FragC acc; wmma::fill_fragment(acc, 0.0f);
        FragA af; FragB bf;
        for (int kt = 0; kt < 9; ++kt) {
            wmma::load_matrix_sync(bf, g_w + WO_LL2 + kt * 8 * 64 + nt * 16, 64);
            wmma::load_matrix_sync(af, sm + OFF_H2 + kt * 8, SH);
            wmma::mma_sync(acc, af, bf, acc);
        }
#pragma unroll
        for (int e = 0; e < acc.num_elements; ++e)
            acc.x[e] = rna(tanh_fast(acc.x[e]));
        wmma::store_matrix_sync(sm + OFF_H + nt * 16, acc, SH, wmma::mem_row_major);
    }
    __syncthreads();

    // ===== ll3: [16 x 72] @ [72 x 128]; accurate tanh in fragment -> gmem =====
    {
        const int nt = wid;
        FragC acc; wmma::fill_fragment(acc, 0.0f);
        FragA af; FragB bf;
        for (int kt = 0; kt < 9; ++kt) {
            wmma::load_matrix_sync(bf, g_w + WO_LL3 + kt * 8 * 128 + nt * 16, 128);
            wmma::load_matrix_sync(af, sm + OFF_H + kt * 8, SH);
            wmma::mma_sync(acc, af, bf, acc);
        }
#pragma unroll
        for (int e = 0; e < acc.num_elements; ++e)
            acc.x[e] = tanhf(acc.x[e]);
        wmma::store_matrix_sync(out + (size_t)blockIdx.x * R * D + nt * 16, acc, D, wmma::mem_row_major);
    }
}

extern "C" void kernel_launch(void* const* d_in, const int* in_sizes, int n_in,
                              void* d_out, int out_size) {
    const float* Lm     = (const float*)d_in[0];
    const float* Am     = (const float*)d_in[1];
    const float* Vm     = (const float*)d_in[2];
    const float* att_w  = (const float*)d_in[3];
    const float* att_b  = (const float*)d_in[4];
    const float* gf_w1  = (const float*)d_in[5];
    const float* gf_b1  = (const float*)d_in[6];
    const float* gf_w2  = (const float*)d_in[7];
    const float* gf_b2  = (const float*)d_in[8];
    const float* gf2_w1 = (const float*)d_in[9];
    const float* gf2_b1 = (const float*)d_in[10];
    const float* gf2_w2 = (const float*)d_in[11];
    const float* gf2_b2 = (const float*)d_in[12];
    const float* ll_w1  = (const float*)d_in[13];
    const float* ll_b1  = (const float*)d_in[14];
    const float* ll_w2  = (const float*)d_in[15];
    const float* ll_b2  = (const float*)d_in[16];
    const float* ll_w3  = (const float*)d_in[17];
    const float* ll_b3  = (const float*)d_in[18];

    convert_weights<<<(WTOT + 255) / 256, 256>>>(
        gf_w1, gf_b1, gf_w2, gf_b2, gf2_w1, gf2_b1, gf2_w2, gf2_b2,
        ll_w1, ll_b1, ll_w2, ll_b2, ll_w3, ll_b3);

    int nrows = in_sizes[0] / D;
    int grid = nrows / R;
    size_t smem = (size_t)SMEM_FLOATS * sizeof(float);
    cudaFuncSetAttribute(graphfusion_kernel,
                         cudaFuncAttributeMaxDynamicSharedMemorySize, (int)smem);
    graphfusion_kernel<<<grid, NT, smem>>>(Lm, Am, Vm, att_w, att_b, (float*)d_out);
}

// round 8
// speedup vs baseline: 2.8722x; 1.1537x over previous
#include <cuda_runtime.h>
#include <mma.h>
#include <math.h>

using namespace nvcuda;

namespace {
constexpr int D = 128;
constexpr int R = 16;           // rows per block
constexpr int NT = 256;         // 8 warps
constexpr int SA = 136;         // activation stride ([16][128] + const cols 128..135)
constexpr int SF = 392;         // fusion stride ([16][384] + const cols 384..391)
constexpr int SH = 72;          // H stride ([.][64] + const cols 64..71)
constexpr int OFF_A   = 0;                  // buffers: A(0) V(1) L(2) G0(3) G1(4) G2(5), each [16][SA]
constexpr int OFF_G0  = OFF_A + 3 * R * SA;
constexpr int OFF_FUS = OFF_A + 6 * R * SA; // [16][SF]
constexpr int OFF_H   = OFF_FUS + R * SF;   // [96][SH]
constexpr int OFF_H2  = OFF_H + 96 * SH;    // [16][SH]
constexpr int OFF_AW  = OFF_H2 + R * SH;    // [128]
constexpr int OFF_SC  = OFF_AW + 128;       // [16][16]
constexpr int SMEM_FLOATS = OFF_SC + R * 16;   // 27776 floats = 111104 B

// tf32 weight images with bias row folded in (K padded to multiple of 8)
constexpr int WO_GF1 = 0;                        // [264 x  64]
constexpr int WO_GF2 = WO_GF1 + 264 * 64;        // [ 72 x 128]
constexpr int WO_G21 = WO_GF2 + 72 * 128;        // [264 x  64]
constexpr int WO_G22 = WO_G21 + 264 * 64;        // [ 72 x 128]
constexpr int WO_LL1 = WO_G22 + 72 * 128;        // [392 x  64]
constexpr int WO_LL2 = WO_LL1 + 392 * 64;        // [ 72 x  64]
constexpr int WO_LL3 = WO_LL2 + 72 * 64;         // [ 72 x 128]
constexpr int WTOT   = WO_LL3 + 72 * 128;        // 91136
}

__device__ float g_w[WTOT];

__device__ __forceinline__ float warp_sum(float x) {
#pragma unroll
    for (int o = 16; o > 0; o >>= 1) x += __shfl_xor_sync(0xffffffffu, x, o);
    return x;
}
__device__ __forceinline__ float warp_max(float x) {
#pragma unroll
    for (int o = 16; o > 0; o >>= 1) x = fmaxf(x, __shfl_xor_sync(0xffffffffu, x, o));
    return x;
}
__device__ __forceinline__ float tanh_fast(float x) {
    float y;
    asm("tanh.approx.f32 %0, %1;" : "=f"(y) : "f"(x));
    return y;
}
__device__ __forceinline__ float rna(float x) {
    unsigned u;
    asm("cvt.rna.tf32.f32 %0, %1;" : "=r"(u) : "f"(x));
    return __uint_as_float(u);
}
__device__ __forceinline__ float4 r4(float4 v) {
    return make_float4(rna(v.x), rna(v.y), rna(v.z), rna(v.w));
}

__global__ void convert_weights(
    const float* __restrict__ gf_w1, const float* __restrict__ gf_b1,
    const float* __restrict__ gf_w2, const float* __restrict__ gf_b2,
    const float* __restrict__ gf2_w1, const float* __restrict__ gf2_b1,
    const float* __restrict__ gf2_w2, const float* __restrict__ gf2_b2,
    const float* __restrict__ ll_w1, const float* __restrict__ ll_b1,
    const float* __restrict__ ll_w2, const float* __restrict__ ll_b2,
    const float* __restrict__ ll_w3, const float* __restrict__ ll_b3)
{
    int i = blockIdx.x * 256 + threadIdx.x;
    if (i >= WTOT) return;
    float v = 0.0f;
    if (i < WO_GF2) {
        int j = i - WO_GF1, r = j >> 6, c = j & 63;
        v = (r < 256) ? gf_w1[r * 64 + c] : ((r == 256) ? gf_b1[c] : 0.0f);
    } else if (i < WO_G21) {
        int j = i - WO_GF2, r = j >> 7, c = j & 127;
        v = (r < 64) ? gf_w2[r * 128 + c] : ((r == 64) ? gf_b2[c] : 0.0f);
    } else if (i < WO_G22) {
        int j = i - WO_G21, r = j >> 6, c = j & 63;
        v = (r < 256) ? gf2_w1[r * 64 + c] : ((r == 256) ? gf2_b1[c] : 0.0f);
    } else if (i < WO_LL1) {
        int j = i - WO_G22, r = j >> 7, c = j & 127;
        v = (r < 64) ? gf2_w2[r * 128 + c] : ((r == 64) ? gf2_b2[c] : 0.0f);
    } else if (i < WO_LL2) {
        int j = i - WO_LL1, r = j >> 6, c = j & 63;
        v = (r < 384) ? ll_w1[r * 64 + c] : ((r == 384) ? ll_b1[c] : 0.0f);
    } else if (i < WO_LL3) {
        int j = i - WO_LL2, r = j >> 6, c = j & 63;
        v = (r < 64) ? ll_w2[r * 64 + c] : ((r == 64) ? ll_b2[c] : 0.0f);
    } else {
        int j = i - WO_LL3, r = j >> 7, c = j & 127;
        v = (r < 64) ? ll_w3[r * 128 + c] : ((r == 64) ? ll_b3[c] : 0.0f);
    }
    g_w[i] = rna(v);
}

typedef wmma::fragment<wmma::matrix_a, 16, 16, 8, wmma::precision::tf32, wmma::row_major> FragA;
typedef wmma::fragment<wmma::matrix_b, 16, 16, 8, wmma::precision::tf32, wmma::row_major> FragB;
typedef wmma::fragment<wmma::accumulator, 16, 16, 8, float> FragC;

__global__ void __launch_bounds__(NT, 2)
graphfusion_kernel(
    const float* __restrict__ Lm, const float* __restrict__ Am, const float* __restrict__ Vm,
    const float* __restrict__ att_w, const float* __restrict__ att_b,
    float* __restrict__ out)
{
    extern __shared__ float sm[];
    const int tid  = threadIdx.x;
    const int lane = tid & 31;
    const int wid  = tid >> 5;   // 0..7

    // ---- init: att_w + constant bias columns ([1,0,0,0,0,0,0,0]) ----
    if (tid < D) sm[OFF_AW + tid] = att_w[tid];
    for (int idx = tid; idx < 1792; idx += NT) {
        int addr, c;
        if (idx < 768)       { int b = idx >> 7, rem = idx & 127; int r = rem >> 3; c = rem & 7;
                               addr = b * (R * SA) + r * SA + 128 + c; }
        else if (idx < 896)  { int i = idx - 768;  int r = i >> 3; c = i & 7; addr = OFF_FUS + r * SF + 384 + c; }
        else if (idx < 1664) { int i = idx - 896;  int r = i >> 3; c = i & 7; addr = OFF_H  + r * SH + 64 + c; }
        else                 { int i = idx - 1664; int r = i >> 3; c = i & 7; addr = OFF_H2 + r * SH + 64 + c; }
        sm[addr] = (c == 0) ? 1.0f : 0.0f;
    }
    __syncthreads();
    const float attb = __ldg(att_b);

    // ================= Phase A: scalars + softmaxes + unimodal =================
    {
        float4 aw = ((const float4*)(sm + OFF_AW))[lane];
#pragma unroll
        for (int rr = 0; rr < 2; ++rr) {
            int r = wid * 2 + rr;
            size_t grow = (size_t)blockIdx.x * R + r;
            float4 a4 = ((const float4*)(Am + grow * D))[lane];
            float4 v4 = ((const float4*)(Vm + grow * D))[lane];
            float4 l4 = ((const float4*)(Lm + grow * D))[lane];

            float sa = tanh_fast(warp_sum(a4.x * aw.x + a4.y * aw.y + a4.z * aw.z + a4.w * aw.w) + attb);
            float sv = tanh_fast(warp_sum(v4.x * aw.x + v4.y * aw.y + v4.z * aw.z + v4.w * aw.w) + attb);
            float sl = tanh_fast(warp_sum(l4.x * aw.x + l4.y * aw.y + l4.z * aw.z + l4.w * aw.w) + attb);

            float4 u;
            u.x = (sa * a4.x + sv * v4.x + sl * l4.x) * (1.0f / 3.0f);
            u.y = (sa * a4.y + sv * v4.y + sl * l4.y) * (1.0f / 3.0f);
            u.z = (sa * a4.z + sv * v4.z + sl * l4.z) * (1.0f / 3.0f);
            u.w = (sa * a4.w + sv * v4.w + sl * l4.w) * (1.0f / 3.0f);
            ((float4*)(sm + OFF_FUS + r * SF))[lane] = r4(u);

            float ma = warp_max(fmaxf(fmaxf(a4.x, a4.y), fmaxf(a4.z, a4.w)));
            float4 ea = make_float4(__expf(a4.x - ma), __expf(a4.y - ma), __expf(a4.z - ma), __expf(a4.w - ma));
            float ia = 1.0f / warp_sum(ea.x + ea.y + ea.z + ea.w);
            float4 pa = make_float4(ea.x * ia, ea.y * ia, ea.z * ia, ea.w * ia);

            float mv = warp_max(fmaxf(fmaxf(v4.x, v4.y), fmaxf(v4.z, v4.w)));
            float4 ev = make_float4(__expf(v4.x - mv), __expf(v4.y - mv), __expf(v4.z - mv), __expf(v4.w - mv));
            float iv = 1.0f / warp_sum(ev.x + ev.y + ev.z + ev.w);
            float4 pv = make_float4(ev.x * iv, ev.y * iv, ev.z * iv, ev.w * iv);

            float ml = warp_max(fmaxf(fmaxf(l4.x, l4.y), fmaxf(l4.z, l4.w)));
            float4 el = make_float4(__expf(l4.x - ml), __expf(l4.y - ml), __expf(l4.z - ml), __expf(l4.w - ml));
            float il = 1.0f / warp_sum(el.x + el.y + el.z + el.w);
            float4 pl = make_float4(el.x * il, el.y * il, el.z * il, el.w * il);

            ((float4*)(sm + OFF_A + 0 * R * SA + r * SA))[lane] = r4(pa);
            ((float4*)(sm + OFF_A + 1 * R * SA + r * SA))[lane] = r4(pv);
            ((float4*)(sm + OFF_A + 2 * R * SA + r * SA))[lane] = r4(pl);

            float dav = warp_sum(pa.x * pv.x + pa.y * pv.y + pa.z * pv.z + pa.w * pv.w);
            float dal = warp_sum(pa.x * pl.x + pa.y * pl.y + pa.z * pl.z + pa.w * pl.w);
            float dvl = warp_sum(pv.x * pl.x + pv.y * pl.y + pv.z * pl.z + pv.w * pl.w);

            float sav = (sa + sv) / (dav + 0.5f);
            float sal = (sa + sl) / (dal + 0.5f);
            float svl = (sl + sv) / (dvl + 0.5f);
            float mx = fmaxf(sav, fmaxf(sal, svl));
            float e0 = __expf(sav - mx), e1 = __expf(sal - mx), e2 = __expf(svl - mx);
            float is = 1.0f / (e0 + e1 + e2);
            if (lane == 0) {
                float* sc = sm + OFF_SC + r * 16;
                sc[0] = e0 * is; sc[1] = e1 * is; sc[2] = e2 * is;
                sc[3] = sav; sc[4] = sal; sc[5] = svl;
                sc[6] = sa;  sc[7] = sv;  sc[8] = sl;
            }
        }
    }
    __syncthreads();

    // ===== gf GEMM1: [48 x 264] @ [264 x 64] =====
    // 12 tiles = 3 mt x 4 nt. Warps 0-3: nt=wid, chains mt={0,2} sharing B; warps 4-7: nt=wid-4, mt=1.
    // pairs: mt0=(a,v) mt1=(a,l) mt2=(v,l); buffers a=0 v=1 l=2
    {
        const int nt = wid & 3;
        const float* wb = g_w + WO_GF1 + nt * 16;
        if (wid < 4) {
            FragA af0, af2; FragB bf;
            FragC acc0, acc2;
            wmma::fill_fragment(acc0, 0.0f);
            wmma::fill_fragment(acc2, 0.0f);
            const float* x0 = sm + 0 * (R * SA);   // a
            const float* y0 = sm + 1 * (R * SA);   // v
            const float* x2 = sm + 1 * (R * SA);   // v
            const float* y2 = sm + 2 * (R * SA);   // l
#pragma unroll
            for (int kt = 0; kt < 16; ++kt) {
                wmma::load_matrix_sync(bf, wb + kt * 8 * 64, 64);
                wmma::load_matrix_sync(af0, x0 + kt * 8, SA);
                wmma::load_matrix_sync(af2, x2 + kt * 8, SA);
                wmma::mma_sync(acc0, af0, bf, acc0);
                wmma::mma_sync(acc2, af2, bf, acc2);
            }
#pragma unroll
            for (int kt = 0; kt < 16; ++kt) {
                wmma::load_matrix_sync(bf, wb + (16 + kt) * 8 * 64, 64);
                wmma::load_matrix_sync(af0, y0 + kt * 8, SA);
                wmma::load_matrix_sync(af2, y2 + kt * 8, SA);
                wmma::mma_sync(acc0, af0, bf, acc0);
                wmma::mma_sync(acc2, af2, bf, acc2);
            }
            // bias step: const cols at offset 128
            wmma::load_matrix_sync(bf, wb + 32 * 8 * 64, 64);
            wmma::load_matrix_sync(af0, x0 + 128, SA);
            wmma::load_matrix_sync(af2, x2 + 128, SA);
            wmma::mma_sync(acc0, af0, bf, acc0);
            wmma::mma_sync(acc2, af2, bf, acc2);
#pragma unroll
            for (int e = 0; e < acc0.num_elements; ++e) {
                float v0 = acc0.x[e];
                acc0.x[e] = rna((v0 >= 0.0f) ? v0 : 0.2f * v0);
                float v2 = acc2.x[e];
                acc2.x[e] = rna((v2 >= 0.0f) ? v2 : 0.2f * v2);
            }
            wmma::store_matrix_sync(sm + OFF_H + 0 * 16 * SH + nt * 16, acc0, SH, wmma::mem_row_major);
            wmma::store_matrix_sync(sm + OFF_H + 2 * 16 * SH + nt * 16, acc2, SH, wmma::mem_row_major);
        } else {
            FragA af; FragB bf;
            FragC acc;
            wmma::fill_fragment(acc, 0.0f);
            const float* x1 = sm + 0 * (R * SA);   // a
            const float* y1 = sm + 2 * (R * SA);   // l
#pragma unroll
            for (int kt = 0; kt < 16; ++kt) {
                wmma::load_matrix_sync(bf, wb + kt * 8 * 64, 64);
                wmma::load_matrix_sync(af, x1 + kt * 8, SA);
                wmma::mma_sync(acc, af, bf, acc);
            }
#pragma unroll
            for (int kt = 0; kt < 16; ++kt) {
                wmma::load_matrix_sync(bf, wb + (16 + kt) * 8 * 64, 64);
                wmma::load_matrix_sync(af, y1 + kt * 8, SA);
                wmma::mma_sync(acc, af, bf, acc);
            }
            wmma::load_matrix_sync(bf, wb + 32 * 8 * 64, 64);
            wmma::load_matrix_sync(af, x1 + 128, SA);
            wmma::mma_sync(acc, af, bf, acc);
#pragma unroll
            for (int e = 0; e < acc.num_elements; ++e) {
                float v = acc.x[e];
                acc.x[e] = rna((v >= 0.0f) ? v : 0.2f * v);
            }
            wmma::store_matrix_sync(sm + OFF_H + 1 * 16 * SH + nt * 16, acc, SH, wmma::mem_row_major);
        }
    }
    __syncthreads();

    // ===== gf GEMM2: [48 x 72] @ [72 x 128]; tanh in fragment -> G0/G1/G2 =====
    {
        const int nt = wid;
        FragC acc[3];
#pragma unroll
        for (int i = 0; i < 3; ++i) wmma::fill_fragment(acc[i], 0.0f);
        FragA af; FragB bf;
        const float* wb = g_w + WO_GF2 + nt * 16;
#pragma unroll
        for (int kt = 0; kt < 9; ++kt) {
            wmma::load_matrix_sync(bf, wb + kt * 8 * 128, 128);
#pragma unroll
            for (int i = 0; i < 3; ++i) {
                wmma::load_matrix_sync(af, sm + OFF_H + i * 16 * SH + kt * 8, SH);
                wmma::mma_sync(acc[i], af, bf, acc[i]);
            }
        }
#pragma unroll
        for (int i = 0; i < 3; ++i) {
#pragma unroll
            for (int e = 0; e < acc[i].num_elements; ++e)
                acc[i].x[e] = rna(tanh_fast(acc[i].x[e]));
            wmma::store_matrix_sync(sm + OFF_G0 + i * (R * SA) + nt * 16, acc[i], SA, wmma::mem_row_major);
        }
    }
    __syncthreads();

    // ============ Phase C: softmax(g) dots, n2, a_v/a_l/v_l, bimodal ============
    {
#pragma unroll
        for (int rr = 0; rr < 2; ++rr) {
            int r = wid * 2 + rr;
            float4 g0 = ((const float4*)(sm + OFF_A + 3 * R * SA + r * SA))[lane];
            float4 g1 = ((const float4*)(sm + OFF_A + 4 * R * SA + r * SA))[lane];
            float4 g2 = ((const float4*)(sm + OFF_A + 5 * R * SA + r * SA))[lane];
            float4 pa = ((const float4*)(sm + OFF_A + 0 * R * SA + r * SA))[lane];
            float4 pv = ((const float4*)(sm + OFF_A + 1 * R * SA + r * SA))[lane];
            float4 pl = ((const float4*)(sm + OFF_A + 2 * R * SA + r * SA))[lane];

            float m0 = warp_max(fmaxf(fmaxf(g0.x, g0.y), fmaxf(g0.z, g0.w)));
            float m1 = warp_max(fmaxf(fmaxf(g1.x, g1.y), fmaxf(g1.z, g1.w)));
            float m2 = warp_max(fmaxf(fmaxf(g2.x, g2.y), fmaxf(g2.z, g2.w)));
            float4 e0 = make_float4(__expf(g0.x - m0), __expf(g0.y - m0), __expf(g0.z - m0), __expf(g0.w - m0));
            float4 e1 = make_float4(__expf(g1.x - m1), __expf(g1.y - m1), __expf(g1.z - m1), __expf(g1.w - m1));
            float4 e2 = make_float4(__expf(g2.x - m2), __expf(g2.y - m2), __expf(g2.z - m2), __expf(g2.w - m2));
            float i0 = 1.0f / warp_sum(e0.x + e0.y + e0.z + e0.w);
            float i1 = 1.0f / warp_sum(e1.x + e1.y + e1.z + e1.w);
            float i2 = 1.0f / warp_sum(e2.x + e2.y + e2.z + e2.w);

            float d01 = warp_sum(e0.x * e1.x + e0.y * e1.y + e0.z * e1.z + e0.w * e1.w);
            float d02 = warp_sum(e0.x * e2.x + e0.y * e2.y + e0.z * e2.z + e0.w * e2.w);
            float d12 = warp_sum(e1.x * e2.x + e1.y * e2.y + e1.z * e2.z + e1.w * e2.w);
            float d0l = warp_sum(e0.x * pl.x + e0.y * pl.y + e0.z * pl.z + e0.w * pl.w);
            float d1v = warp_sum(e1.x * pv.x + e1.y * pv.y + e1.z * pv.z + e1.w * pv.w);
            float d2a = warp_sum(e2.x * pa.x + e2.y * pa.y + e2.z * pa.z + e2.w * pa.w);

            const float* sc = sm + OFF_SC + r * 16;
            float sav = sc[3], sal = sc[4], svl = sc[5];
            float sa = sc[6], sv = sc[7], sl = sc[8];
            float t0 = (sav + svl) / (d02 * i0 * i2 + 0.5f);
            float t1 = (sav + sal) / (d01 * i0 * i1 + 0.5f);
            float t2 = (sal + svl) / (d12 * i1 * i2 + 0.5f);
            float t3 = (sav + sl)  / (d0l * i0 + 0.5f);
            float t4 = (sal + sv)  / (d1v * i1 + 0.5f);
            float t5 = (sa  + svl) / (d2a * i2 + 0.5f);
            float mm = fmaxf(fmaxf(fmaxf(t0, t1), fmaxf(t2, t3)), fmaxf(t4, t5));
            float q0 = __expf(t0 - mm), q1 = __expf(t1 - mm), q2 = __expf(t2 - mm);
            float q3 = __expf(t3 - mm), q4 = __expf(t4 - mm), q5 = __expf(t5 - mm);
            float qi = 1.0f / (q0 + q1 + q2 + q3 + q4 + q5);
            if (lane == 0) {
                float* scw = sm + OFF_SC + r * 16;
                scw[9]  = q0 * qi; scw[10] = q1 * qi; scw[11] = q2 * qi;
                scw[12] = q3 * qi; scw[13] = q4 * qi; scw[14] = q5 * qi;
            }

            float n0 = sc[0], n1 = sc[1], n2v = sc[2];
            float4 av = make_float4(tanh_fast(n0 * g0.x), tanh_fast(n0 * g0.y), tanh_fast(n0 * g0.z), tanh_fast(n0 * g0.w));
            float4 al = make_float4(tanh_fast(n1 * g1.x), tanh_fast(n1 * g1.y), tanh_fast(n1 * g1.z), tanh_fast(n1 * g1.w));
            float4 vl = make_float4(tanh_fast(n2v * g2.x), tanh_fast(n2v * g2.y), tanh_fast(n2v * g2.z), tanh_fast(n2v * g2.w));
            ((float4*)(sm + OFF_A + 3 * R * SA + r * SA))[lane] = r4(av);
            ((float4*)(sm + OFF_A + 4 * R * SA + r * SA))[lane] = r4(al);
            ((float4*)(sm + OFF_A + 5 * R * SA + r * SA))[lane] = r4(vl);
            float4 bm = make_float4(av.x + al.x + vl.x, av.y + al.y + vl.y,
                                    av.z + al.z + vl.z, av.w + al.w + vl.w);
            ((float4*)(sm + OFF_FUS + r * SF + 128))[lane] = r4(bm);
        }
    }
    __syncthreads();

    // ===== gf2 GEMM1 (6 pairs merged): [96 x 264] @ [264 x 64]; leaky in fragment =====
    {
        const int g2x[6] = {3, 3, 5, 3, 4, 5}, g2y[6] = {5, 4, 4, 2, 1, 0};
        const int mh = wid >> 2, nt = wid & 3;
        const float* xs[3]; const float* ys[3];
#pragma unroll
        for (int i = 0; i < 3; ++i) {
            xs[i] = sm + g2x[mh * 3 + i] * (R * SA);
            ys[i] = sm + g2y[mh * 3 + i] * (R * SA);
        }
        FragC acc[3];
#pragma unroll
        for (int i = 0; i < 3; ++i) wmma::fill_fragment(acc[i], 0.0f);
        FragA af; FragB bf;
        const float* wb = g_w + WO_G21 + nt * 16;
#pragma unroll
        for (int kt = 0; kt < 16; ++kt) {
            wmma::load_matrix_sync(bf, wb + kt * 8 * 64, 64);
#pragma unroll
            for (int i = 0; i < 3; ++i) {
                wmma::load_matrix_sync(af, xs[i] + kt * 8, SA);
                wmma::mma_sync(acc[i], af, bf, acc[i]);
            }
        }
#pragma unroll
        for (int kt = 0; kt < 16; ++kt) {
            wmma::load_matrix_sync(bf, wb + (16 + kt) * 8 * 64, 64);
#pragma unroll
            for (int i = 0; i < 3; ++i) {
                wmma::load_matrix_sync(af, ys[i] + kt * 8, SA);
                wmma::mma_sync(acc[i], af, bf, acc[i]);
            }
        }
        wmma::load_matrix_sync(bf, wb + 32 * 8 * 64, 64);
#pragma unroll
        for (int i = 0; i < 3; ++i) {
            wmma::load_matrix_sync(af, xs[i] + 128, SA);
            wmma::mma_sync(acc[i], af, bf, acc[i]);
        }
#pragma unroll
        for (int i = 0; i < 3; ++i) {
#pragma unroll
            for (int e = 0; e < acc[i].num_elements; ++e) {
                float v = acc[i].x[e];
                acc[i].x[e] = rna((v >= 0.0f) ? v : 0.2f * v);
            }
            wmma::store_matrix_sync(sm + OFF_H + (mh * 3 + i) * 16 * SH + nt * 16, acc[i], SH, wmma::mem_row_major);
        }
    }
    __syncthreads();

    // ===== gf2 GEMM2: [96 x 72] @ [72 x 128] raw -> scratch (G0,G1,G2,A,V,L) =====
    {
        const int nt = wid;
        FragC acc[6];
#pragma unroll
        for (int i = 0; i < 6; ++i) wmma::fill_fragment(acc[i], 0.0f);
        FragA af; FragB bf;
        const float* wb = g_w + WO_G22 + nt * 16;
#pragma unroll
        for (int kt = 0; kt < 9; ++kt) {
            wmma::load_matrix_sync(bf, wb + kt * 8 * 128, 128);
#pragma unroll
            for (int i = 0; i < 6; ++i) {
                wmma::load_matrix_sync(af, sm + OFF_H + i * 16 * SH + kt * 8, SH);
                wmma::mma_sync(acc[i], af, bf, acc[i]);
            }
        }
#pragma unroll
        for (int i = 0; i < 6; ++i) {
            int bidx = (i < 3) ? (3 + i) : (i - 3);
            wmma::store_matrix_sync(sm + bidx * (R * SA) + nt * 16, acc[i], SA, wmma::mem_row_major);
        }
    }
    __syncthreads();

    // ===== trimodal epilogue: fus[r][256+c] = sum_p tanh(n2[p]*tanh(raw_p)) =====
    for (int idx = tid; idx < 16 * 128; idx += NT) {
        int r = idx >> 7, c = idx & 127;
        const float* sc = sm + OFF_SC + r * 16 + 9;
        float s = 0.0f;
#pragma unroll
        for (int p = 0; p < 6; ++p) {
            int bidx = (p < 3) ? (3 + p) : (p - 3);
            s += tanh_fast(sc[p] * tanh_fast(sm[bidx * (R * SA) + r * SA + c]));
        }
        sm[OFF_FUS + r * SF + 256 + c] = rna(s);
    }
    __syncthreads();

    // ===== ll1: [16 x 392] @ [392 x 64], 2-way k-split, raw partials in H =====
    {
        const int part = wid >> 2, nt = wid & 3;
        FragC acc; wmma::fill_fragment(acc, 0.0f);
        FragA af; FragB bf;
        const float* wb = g_w + WO_LL1 + nt * 16;
        if (part == 0) {
#pragma unroll
            for (int kt = 0; kt < 25; ++kt) {
                wmma::load_matrix_sync(bf, wb + kt * 8 * 64, 64);
                wmma::load_matrix_sync(af, sm + OFF_FUS + kt * 8, SF);
                wmma::mma_sync(acc, af, bf, acc);
            }
        } else {
#pragma unroll
            for (int kt = 25; kt < 49; ++kt) {
                wmma::load_matrix_sync(bf, wb + kt * 8 * 64, 64);
                wmma::load_matrix_sync(af, sm + OFF_FUS + kt * 8, SF);
                wmma::mma_sync(acc, af, bf, acc);
            }
        }
        wmma::store_matrix_sync(sm + OFF_H + part * 16 * SH + nt * 16, acc, SH, wmma::mem_row_major);
    }
    __syncthreads();
    for (int idx = tid; idx < 16 * 64; idx += NT) {
        int r = idx >> 6, c = idx & 63;
        float v = sm[OFF_H + r * SH + c] + sm[OFF_H + (16 + r) * SH + c];
        sm[OFF_H2 + r * SH + c] = rna(tanh_fast(v));
    }
    __syncthreads();

    // ===== ll2: [16 x 72] @ [72 x 64]; tanh in fragment -> H rows 0..15 =====
    if (wid < 4) {
        const int nt = wid;
        FragC acc; wmma::fill_fragment(acc, 0.0f);
        FragA af; FragB bf;
        const float* wb = g_w + WO_LL2 + nt * 16;
#pragma unroll
        for (int kt = 0; kt < 9; ++kt) {
            wmma::load_matrix_sync(bf, wb + kt * 8 * 64, 64);
            wmma::load_matrix_sync(af, sm + OFF_H2 + kt * 8, SH);
            wmma::mma_sync(acc, af, bf, acc);
        }
#pragma unroll
        for (int e = 0; e < acc.num_elements; ++e)
            acc.x[e] = rna(tanh_fast(acc.x[e]));
        wmma::store_matrix_sync(sm + OFF_H + nt * 16, acc, SH, wmma::mem_row_major);
    }
    __syncthreads();

    // ===== ll3: [16 x 72] @ [72 x 128]; accurate tanh in fragment -> gmem =====
    {
        const int nt = wid;
        FragC acc; wmma::fill_fragment(acc, 0.0f);
        FragA af; FragB bf;
        const float* wb = g_w + WO_LL3 + nt * 16;
#pragma unroll
        for (int kt = 0; kt < 9; ++kt) {
            wmma::load_matrix_sync(bf, wb + kt * 8 * 128, 128);
            wmma::load_matrix_sync(af, sm + OFF_H + kt * 8, SH);
            wmma::mma_sync(acc, af, bf, acc);
        }
#pragma unroll
        for (int e = 0; e < acc.num_elements; ++e)
            acc.x[e] = tanhf(acc.x[e]);
        wmma::store_matrix_sync(out + (size_t)blockIdx.x * R * D + nt * 16, acc, D, wmma::mem_row_major);
    }
}

extern "C" void kernel_launch(void* const* d_in, const int* in_sizes, int n_in,
                              void* d_out, int out_size) {
    const float* Lm     = (const float*)d_in[0];
    const float* Am     = (const float*)d_in[1];
    const float* Vm     = (const float*)d_in[2];
    const float* att_w  = (const float*)d_in[3];
    const float* att_b  = (const float*)d_in[4];
    const float* gf_w1  = (const float*)d_in[5];
    const float* gf_b1  = (const float*)d_in[6];
    const float* gf_w2  = (const float*)d_in[7];
    const float* gf_b2  = (const float*)d_in[8];
    const float* gf2_w1 = (const float*)d_in[9];
    const float* gf2_b1 = (const float*)d_in[10];
    const float* gf2_w2 = (const float*)d_in[11];
    const float* gf2_b2 = (const float*)d_in[12];
    const float* ll_w1  = (const float*)d_in[13];
    const float* ll_b1  = (const float*)d_in[14];
    const float* ll_w2  = (const float*)d_in[15];
    const float* ll_b2  = (const float*)d_in[16];
    const float* ll_w3  = (const float*)d_in[17];
    const float* ll_b3  = (const float*)d_in[18];

    convert_weights<<<(WTOT + 255) / 256, 256>>>(
        gf_w1, gf_b1, gf_w2, gf_b2, gf2_w1, gf2_b1, gf2_w2, gf2_b2,
        ll_w1, ll_b1, ll_w2, ll_b2, ll_w3, ll_b3);

    int nrows = in_sizes[0] / D;
    int grid = nrows / R;
    size_t smem = (size_t)SMEM_FLOATS * sizeof(float);
    cudaFuncSetAttribute(graphfusion_kernel,
                         cudaFuncAttributeMaxDynamicSharedMemorySize, (int)smem);
    graphfusion_kernel<<<grid, NT, smem>>>(Lm, Am, Vm, att_w, att_b, (float*)d_out);
}

// round 9
// speedup vs baseline: 3.0184x; 1.0509x over previous
#include <cuda_runtime.h>
#include <mma.h>
#include <math.h>

using namespace nvcuda;

namespace {
constexpr int D = 128;
constexpr int R = 16;           // rows per block
constexpr int NT = 256;         // 8 warps
constexpr int SA = 140;         // activation stride: 140%32==12 -> conflict-free wmma ld/st
constexpr int SF = 396;         // fusion stride: 396%32==12
constexpr int SH = 76;          // H stride: 76%32==12
constexpr int OFF_A   = 0;                  // buffers: A(0) V(1) L(2) G0(3) G1(4) G2(5), each [16][SA]
constexpr int OFF_G0  = OFF_A + 3 * R * SA;
constexpr int OFF_FUS = OFF_A + 6 * R * SA; // [16][SF]
constexpr int OFF_H   = OFF_FUS + R * SF;   // [96][SH]
constexpr int OFF_H2  = OFF_H + 96 * SH;    // [16][SH]
constexpr int OFF_AW  = OFF_H2 + R * SH;    // [128]
constexpr int OFF_SC  = OFF_AW + 128;       // [16][16]
constexpr int SMEM_FLOATS = OFF_SC + R * 16;   // 28672 floats = 114688 B (x2 CTAs = 229376 B)

// tf32 weight images with bias row folded in (K padded to multiple of 8)
constexpr int WO_GF1 = 0;                        // [264 x  64]
constexpr int WO_GF2 = WO_GF1 + 264 * 64;        // [ 72 x 128]
constexpr int WO_G21 = WO_GF2 + 72 * 128;        // [264 x  64]
constexpr int WO_G22 = WO_G21 + 264 * 64;        // [ 72 x 128]
constexpr int WO_LL1 = WO_G22 + 72 * 128;        // [392 x  64]
constexpr int WO_LL2 = WO_LL1 + 392 * 64;        // [ 72 x  64]
constexpr int WO_LL3 = WO_LL2 + 72 * 64;         // [ 72 x 128]
constexpr int WTOT   = WO_LL3 + 72 * 128;        // 91136
}

__device__ float g_w[WTOT];

__device__ __forceinline__ float warp_sum(float x) {
#pragma unroll
    for (int o = 16; o > 0; o >>= 1) x += __shfl_xor_sync(0xffffffffu, x, o);
    return x;
}
__device__ __forceinline__ float warp_max(float x) {
#pragma unroll
    for (int o = 16; o > 0; o >>= 1) x = fmaxf(x, __shfl_xor_sync(0xffffffffu, x, o));
    return x;
}
__device__ __forceinline__ float tanh_fast(float x) {
    float y;
    asm("tanh.approx.f32 %0, %1;" : "=f"(y) : "f"(x));
    return y;
}
__device__ __forceinline__ float rna(float x) {
    unsigned u;
    asm("cvt.rna.tf32.f32 %0, %1;" : "=r"(u) : "f"(x));
    return __uint_as_float(u);
}
__device__ __forceinline__ float4 r4(float4 v) {
    return make_float4(rna(v.x), rna(v.y), rna(v.z), rna(v.w));
}

__global__ void convert_weights(
    const float* __restrict__ gf_w1, const float* __restrict__ gf_b1,
    const float* __restrict__ gf_w2, const float* __restrict__ gf_b2,
    const float* __restrict__ gf2_w1, const float* __restrict__ gf2_b1,
    const float* __restrict__ gf2_w2, const float* __restrict__ gf2_b2,
    const float* __restrict__ ll_w1, const float* __restrict__ ll_b1,
    const float* __restrict__ ll_w2, const float* __restrict__ ll_b2,
    const float* __restrict__ ll_w3, const float* __restrict__ ll_b3)
{
    int i = blockIdx.x * 256 + threadIdx.x;
    if (i >= WTOT) return;
    float v = 0.0f;
    if (i < WO_GF2) {
        int j = i - WO_GF1, r = j >> 6, c = j & 63;
        v = (r < 256) ? gf_w1[r * 64 + c] : ((r == 256) ? gf_b1[c] : 0.0f);
    } else if (i < WO_G21) {
        int j = i - WO_GF2, r = j >> 7, c = j & 127;
        v = (r < 64) ? gf_w2[r * 128 + c] : ((r == 64) ? gf_b2[c] : 0.0f);
    } else if (i < WO_G22) {
        int j = i - WO_G21, r = j >> 6, c = j & 63;
        v = (r < 256) ? gf2_w1[r * 64 + c] : ((r == 256) ? gf2_b1[c] : 0.0f);
    } else if (i < WO_LL1) {
        int j = i - WO_G22, r = j >> 7, c = j & 127;
        v = (r < 64) ? gf2_w2[r * 128 + c] : ((r == 64) ? gf2_b2[c] : 0.0f);
    } else if (i < WO_LL2) {
        int j = i - WO_LL1, r = j >> 6, c = j & 63;
        v = (r < 384) ? ll_w1[r * 64 + c] : ((r == 384) ? ll_b1[c] : 0.0f);
    } else if (i < WO_LL3) {
        int j = i - WO_LL2, r = j >> 6, c = j & 63;
        v = (r < 64) ? ll_w2[r * 64 + c] : ((r == 64) ? ll_b2[c] : 0.0f);
    } else {
        int j = i - WO_LL3, r = j >> 7, c = j & 127;
        v = (r < 64) ? ll_w3[r * 128 + c] : ((r == 64) ? ll_b3[c] : 0.0f);
    }
    g_w[i] = rna(v);
}

typedef wmma::fragment<wmma::matrix_a, 16, 16, 8, wmma::precision::tf32, wmma::row_major> FragA;
typedef wmma::fragment<wmma::matrix_b, 16, 16, 8, wmma::precision::tf32, wmma::row_major> FragB;
typedef wmma::fragment<wmma::accumulator, 16, 16, 8, float> FragC;

__global__ void __launch_bounds__(NT, 2)
graphfusion_kernel(
    const float* __restrict__ Lm, const float* __restrict__ Am, const float* __restrict__ Vm,
    const float* __restrict__ att_w, const float* __restrict__ att_b,
    float* __restrict__ out)
{
    extern __shared__ float sm[];
    const int tid  = threadIdx.x;
    const int lane = tid & 31;
    const int wid  = tid >> 5;   // 0..7

    // ---- init: att_w + constant bias columns ([1,0,0,0,0,0,0,0]) ----
    if (tid < D) sm[OFF_AW + tid] = att_w[tid];
    for (int idx = tid; idx < 1792; idx += NT) {
        int addr, c;
        if (idx < 768)       { int b = idx >> 7, rem = idx & 127; int r = rem >> 3; c = rem & 7;
                               addr = b * (R * SA) + r * SA + 128 + c; }
        else if (idx < 896)  { int i = idx - 768;  int r = i >> 3; c = i & 7; addr = OFF_FUS + r * SF + 384 + c; }
        else if (idx < 1664) { int i = idx - 896;  int r = i >> 3; c = i & 7; addr = OFF_H  + r * SH + 64 + c; }
        else                 { int i = idx - 1664; int r = i >> 3; c = i & 7; addr = OFF_H2 + r * SH + 64 + c; }
        sm[addr] = (c == 0) ? 1.0f : 0.0f;
    }
    __syncthreads();
    const float attb = __ldg(att_b);

    // ================= Phase A: scalars + softmaxes + unimodal =================
    {
        float4 aw = ((const float4*)(sm + OFF_AW))[lane];
#pragma unroll
        for (int rr = 0; rr < 2; ++rr) {
            int r = wid * 2 + rr;
            size_t grow = (size_t)blockIdx.x * R + r;
            float4 a4 = ((const float4*)(Am + grow * D))[lane];
            float4 v4 = ((const float4*)(Vm + grow * D))[lane];
            float4 l4 = ((const float4*)(Lm + grow * D))[lane];

            float sa = tanh_fast(warp_sum(a4.x * aw.x + a4.y * aw.y + a4.z * aw.z + a4.w * aw.w) + attb);
            float sv = tanh_fast(warp_sum(v4.x * aw.x + v4.y * aw.y + v4.z * aw.z + v4.w * aw.w) + attb);
            float sl = tanh_fast(warp_sum(l4.x * aw.x + l4.y * aw.y + l4.z * aw.z + l4.w * aw.w) + attb);

            float4 u;
            u.x = (sa * a4.x + sv * v4.x + sl * l4.x) * (1.0f / 3.0f);
            u.y = (sa * a4.y + sv * v4.y + sl * l4.y) * (1.0f / 3.0f);
            u.z = (sa * a4.z + sv * v4.z + sl * l4.z) * (1.0f / 3.0f);
            u.w = (sa * a4.w + sv * v4.w + sl * l4.w) * (1.0f / 3.0f);
            ((float4*)(sm + OFF_FUS + r * SF))[lane] = r4(u);

            float ma = warp_max(fmaxf(fmaxf(a4.x, a4.y), fmaxf(a4.z, a4.w)));
            float4 ea = make_float4(__expf(a4.x - ma), __expf(a4.y - ma), __expf(a4.z - ma), __expf(a4.w - ma));
            float ia = 1.0f / warp_sum(ea.x + ea.y + ea.z + ea.w);
            float4 pa = make_float4(ea.x * ia, ea.y * ia, ea.z * ia, ea.w * ia);

            float mv = warp_max(fmaxf(fmaxf(v4.x, v4.y), fmaxf(v4.z, v4.w)));
            float4 ev = make_float4(__expf(v4.x - mv), __expf(v4.y - mv), __expf(v4.z - mv), __expf(v4.w - mv));
            float iv = 1.0f / warp_sum(ev.x + ev.y + ev.z + ev.w);
            float4 pv = make_float4(ev.x * iv, ev.y * iv, ev.z * iv, ev.w * iv);

            float ml = warp_max(fmaxf(fmaxf(l4.x, l4.y), fmaxf(l4.z, l4.w)));
            float4 el = make_float4(__expf(l4.x - ml), __expf(l4.y - ml), __expf(l4.z - ml), __expf(l4.w - ml));
            float il = 1.0f / warp_sum(el.x + el.y + el.z + el.w);
            float4 pl = make_float4(el.x * il, el.y * il, el.z * il, el.w * il);

            ((float4*)(sm + OFF_A + 0 * R * SA + r * SA))[lane] = r4(pa);
            ((float4*)(sm + OFF_A + 1 * R * SA + r * SA))[lane] = r4(pv);
            ((float4*)(sm + OFF_A + 2 * R * SA + r * SA))[lane] = r4(pl);

            float dav = warp_sum(pa.x * pv.x + pa.y * pv.y + pa.z * pv.z + pa.w * pv.w);
            float dal = warp_sum(pa.x * pl.x + pa.y * pl.y + pa.z * pl.z + pa.w * pl.w);
            float dvl = warp_sum(pv.x * pl.x + pv.y * pl.y + pv.z * pl.z + pv.w * pl.w);

            float sav = (sa + sv) / (dav + 0.5f);
            float sal = (sa + sl) / (dal + 0.5f);
            float svl = (sl + sv) / (dvl + 0.5f);
            float mx = fmaxf(sav, fmaxf(sal, svl));
            float e0 = __expf(sav - mx), e1 = __expf(sal - mx), e2 = __expf(svl - mx);
            float is = 1.0f / (e0 + e1 + e2);
            if (lane == 0) {
                float* sc = sm + OFF_SC + r * 16;
                sc[0] = e0 * is; sc[1] = e1 * is; sc[2] = e2 * is;
                sc[3] = sav; sc[4] = sal; sc[5] = svl;
                sc[6] = sa;  sc[7] = sv;  sc[8] = sl;
            }
        }
    }
    __syncthreads();

    // ===== gf GEMM1: [48 x 264] @ [264 x 64] =====
    // 12 tiles = 3 mt x 4 nt. Warps 0-3: nt=wid, chains mt={0,2} sharing B; warps 4-7: nt=wid-4, mt=1.
    // pairs: mt0=(a,v) mt1=(a,l) mt2=(v,l); buffers a=0 v=1 l=2
    {
        const int nt = wid & 3;
        const float* wb = g_w + WO_GF1 + nt * 16;
        if (wid < 4) {
            FragA af0, af2; FragB bf;
            FragC acc0, acc2;
            wmma::fill_fragment(acc0, 0.0f);
            wmma::fill_fragment(acc2, 0.0f);
            const float* x0 = sm + 0 * (R * SA);   // a
            const float* y0 = sm + 1 * (R * SA);   // v
            const float* x2 = sm + 1 * (R * SA);   // v
            const float* y2 = sm + 2 * (R * SA);   // l
#pragma unroll
            for (int kt = 0; kt < 16; ++kt) {
                wmma::load_matrix_sync(bf, wb + kt * 8 * 64, 64);
                wmma::load_matrix_sync(af0, x0 + kt * 8, SA);
                wmma::load_matrix_sync(af2, x2 + kt * 8, SA);
                wmma::mma_sync(acc0, af0, bf, acc0);
                wmma::mma_sync(acc2, af2, bf, acc2);
            }
#pragma unroll
            for (int kt = 0; kt < 16; ++kt) {
                wmma::load_matrix_sync(bf, wb + (16 + kt) * 8 * 64, 64);
                wmma::load_matrix_sync(af0, y0 + kt * 8, SA);
                wmma::load_matrix_sync(af2, y2 + kt * 8, SA);
                wmma::mma_sync(acc0, af0, bf, acc0);
                wmma::mma_sync(acc2, af2, bf, acc2);
            }
            // bias step: const cols at offset 128
            wmma::load_matrix_sync(bf, wb + 32 * 8 * 64, 64);
            wmma::load_matrix_sync(af0, x0 + 128, SA);
            wmma::load_matrix_sync(af2, x2 + 128, SA);
            wmma::mma_sync(acc0, af0, bf, acc0);
            wmma::mma_sync(acc2, af2, bf, acc2);
#pragma unroll
            for (int e = 0; e < acc0.num_elements; ++e) {
                float v0 = acc0.x[e];
                acc0.x[e] = rna((v0 >= 0.0f) ? v0 : 0.2f * v0);
                float v2 = acc2.x[e];
                acc2.x[e] = rna((v2 >= 0.0f) ? v2 : 0.2f * v2);
            }
            wmma::store_matrix_sync(sm + OFF_H + 0 * 16 * SH + nt * 16, acc0, SH, wmma::mem_row_major);
            wmma::store_matrix_sync(sm + OFF_H + 2 * 16 * SH + nt * 16, acc2, SH, wmma::mem_row_major);
        } else {
            FragA af; FragB bf;
            FragC acc;
            wmma::fill_fragment(acc, 0.0f);
            const float* x1 = sm + 0 * (R * SA);   // a
            const float* y1 = sm + 2 * (R * SA);   // l
#pragma unroll
            for (int kt = 0; kt < 16; ++kt) {
                wmma::load_matrix_sync(bf, wb + kt * 8 * 64, 64);
                wmma::load_matrix_sync(af, x1 + kt * 8, SA);
                wmma::mma_sync(acc, af, bf, acc);
            }
#pragma unroll
            for (int kt = 0; kt < 16; ++kt) {
                wmma::load_matrix_sync(bf, wb + (16 + kt) * 8 * 64, 64);
                wmma::load_matrix_sync(af, y1 + kt * 8, SA);
                wmma::mma_sync(acc, af, bf, acc);
            }
            wmma::load_matrix_sync(bf, wb + 32 * 8 * 64, 64);
            wmma::load_matrix_sync(af, x1 + 128, SA);
            wmma::mma_sync(acc, af, bf, acc);
#pragma unroll
            for (int e = 0; e < acc.num_elements; ++e) {
                float v = acc.x[e];
                acc.x[e] = rna((v >= 0.0f) ? v : 0.2f * v);
            }
            wmma::store_matrix_sync(sm + OFF_H + 1 * 16 * SH + nt * 16, acc, SH, wmma::mem_row_major);
        }
    }
    __syncthreads();

    // ===== gf GEMM2: [48 x 72] @ [72 x 128]; tanh in fragment -> G0/G1/G2 =====
    {
        const int nt = wid;
        FragC acc[3];
#pragma unroll
        for (int i = 0; i < 3; ++i) wmma::fill_fragment(acc[i], 0.0f);
        FragA af; FragB bf;
        const float* wb = g_w + WO_GF2 + nt * 16;
#pragma unroll
        for (int kt = 0; kt < 9; ++kt) {
            wmma::load_matrix_sync(bf, wb + kt * 8 * 128, 128);
#pragma unroll
            for (int i = 0; i < 3; ++i) {
                wmma::load_matrix_sync(af, sm + OFF_H + i * 16 * SH + kt * 8, SH);
                wmma::mma_sync(acc[i], af, bf, acc[i]);
            }
        }
#pragma unroll
        for (int i = 0; i < 3; ++i) {
#pragma unroll
            for (int e = 0; e < acc[i].num_elements; ++e)
                acc[i].x[e] = rna(tanh_fast(acc[i].x[e]));
            wmma::store_matrix_sync(sm + OFF_G0 + i * (R * SA) + nt * 16, acc[i], SA, wmma::mem_row_major);
        }
    }
    __syncthreads();

    // ============ Phase C: softmax(g) dots, n2, a_v/a_l/v_l, bimodal ============
    {
#pragma unroll
        for (int rr = 0; rr < 2; ++rr) {
            int r = wid * 2 + rr;
            float4 g0 = ((const float4*)(sm + OFF_A + 3 * R * SA + r * SA))[lane];
            float4 g1 = ((const float4*)(sm + OFF_A + 4 * R * SA + r * SA))[lane];
            float4 g2 = ((const float4*)(sm + OFF_A + 5 * R * SA + r * SA))[lane];
            float4 pa = ((const float4*)(sm + OFF_A + 0 * R * SA + r * SA))[lane];
            float4 pv = ((const float4*)(sm + OFF_A + 1 * R * SA + r * SA))[lane];
            float4 pl = ((const float4*)(sm + OFF_A + 2 * R * SA + r * SA))[lane];

            float m0 = warp_max(fmaxf(fmaxf(g0.x, g0.y), fmaxf(g0.z, g0.w)));
            float m1 = warp_max(fmaxf(fmaxf(g1.x, g1.y), fmaxf(g1.z, g1.w)));
            float m2 = warp_max(fmaxf(fmaxf(g2.x, g2.y), fmaxf(g2.z, g2.w)));
            float4 e0 = make_float4(__expf(g0.x - m0), __expf(g0.y - m0), __expf(g0.z - m0), __expf(g0.w - m0));
            float4 e1 = make_float4(__expf(g1.x - m1), __expf(g1.y - m1), __expf(g1.z - m1), __expf(g1.w - m1));
            float4 e2 = make_float4(__expf(g2.x - m2), __expf(g2.y - m2), __expf(g2.z - m2), __expf(g2.w - m2));
            float i0 = 1.0f / warp_sum(e0.x + e0.y + e0.z + e0.w);
            float i1 = 1.0f / warp_sum(e1.x + e1.y + e1.z + e1.w);
            float i2 = 1.0f / warp_sum(e2.x + e2.y + e2.z + e2.w);

            float d01 = warp_sum(e0.x * e1.x + e0.y * e1.y + e0.z * e1.z + e0.w * e1.w);
            float d02 = warp_sum(e0.x * e2.x + e0.y * e2.y + e0.z * e2.z + e0.w * e2.w);
            float d12 = warp_sum(e1.x * e2.x + e1.y * e2.y + e1.z * e2.z + e1.w * e2.w);
            float d0l = warp_sum(e0.x * pl.x + e0.y * pl.y + e0.z * pl.z + e0.w * pl.w);
            float d1v = warp_sum(e1.x * pv.x + e1.y * pv.y + e1.z * pv.z + e1.w * pv.w);
            float d2a = warp_sum(e2.x * pa.x + e2.y * pa.y + e2.z * pa.z + e2.w * pa.w);

            const float* sc = sm + OFF_SC + r * 16;
            float sav = sc[3], sal = sc[4], svl = sc[5];
            float sa = sc[6], sv = sc[7], sl = sc[8];
            float t0 = (sav + svl) / (d02 * i0 * i2 + 0.5f);
            float t1 = (sav + sal) / (d01 * i0 * i1 + 0.5f);
            float t2 = (sal + svl) / (d12 * i1 * i2 + 0.5f);
            float t3 = (sav + sl)  / (d0l * i0 + 0.5f);
            float t4 = (sal + sv)  / (d1v * i1 + 0.5f);
            float t5 = (sa  + svl) / (d2a * i2 + 0.5f);
            float mm = fmaxf(fmaxf(fmaxf(t0, t1), fmaxf(t2, t3)), fmaxf(t4, t5));
            float q0 = __expf(t0 - mm), q1 = __expf(t1 - mm), q2 = __expf(t2 - mm);
            float q3 = __expf(t3 - mm), q4 = __expf(t4 - mm), q5 = __expf(t5 - mm);
            float qi = 1.0f / (q0 + q1 + q2 + q3 + q4 + q5);
            if (lane == 0) {
                float* scw = sm + OFF_SC + r * 16;
                scw[9]  = q0 * qi; scw[10] = q1 * qi; scw[11] = q2 * qi;
                scw[12] = q3 * qi; scw[13] = q4 * qi; scw[14] = q5 * qi;
            }

            float n0 = sc[0], n1 = sc[1], n2v = sc[2];
            float4 av = make_float4(tanh_fast(n0 * g0.x), tanh_fast(n0 * g0.y), tanh_fast(n0 * g0.z), tanh_fast(n0 * g0.w));
            float4 al = make_float4(tanh_fast(n1 * g1.x), tanh_fast(n1 * g1.y), tanh_fast(n1 * g1.z), tanh_fast(n1 * g1.w));
            float4 vl = make_float4(tanh_fast(n2v * g2.x), tanh_fast(n2v * g2.y), tanh_fast(n2v * g2.z), tanh_fast(n2v * g2.w));
            ((float4*)(sm + OFF_A + 3 * R * SA + r * SA))[lane] = r4(av);
            ((float4*)(sm + OFF_A + 4 * R * SA + r * SA))[lane] = r4(al);
            ((float4*)(sm + OFF_A + 5 * R * SA + r * SA))[lane] = r4(vl);
            float4 bm = make_float4(av.x + al.x + vl.x, av.y + al.y + vl.y,
                                    av.z + al.z + vl.z, av.w + al.w + vl.w);
            ((float4*)(sm + OFF_FUS + r * SF + 128))[lane] = r4(bm);
        }
    }
    __syncthreads();

    // ===== gf2 GEMM1 (6 pairs merged): [96 x 264] @ [264 x 64]; leaky in fragment =====
    {
        const int g2x[6] = {3, 3, 5, 3, 4, 5}, g2y[6] = {5, 4, 4, 2, 1, 0};
        const int mh = wid >> 2, nt = wid & 3;
        const float* xs[3]; const float* ys[3];
#pragma unroll
        for (int i = 0; i < 3; ++i) {
            xs[i] = sm + g2x[mh * 3 + i] * (R * SA);
            ys[i] = sm + g2y[mh * 3 + i] * (R * SA);
        }
        FragC acc[3];
#pragma unroll
        for (int i = 0; i < 3; ++i) wmma::fill_fragment(acc[i], 0.0f);
        FragA af; FragB bf;
        const float* wb = g_w + WO_G21 + nt * 16;
#pragma unroll
        for (int kt = 0; kt < 16; ++kt) {
            wmma::load_matrix_sync(bf, wb + kt * 8 * 64, 64);
#pragma unroll
            for (int i = 0; i < 3; ++i) {
                wmma::load_matrix_sync(af, xs[i] + kt * 8, SA);
                wmma::mma_sync(acc[i], af, bf, acc[i]);
            }
        }
#pragma unroll
        for (int kt = 0; kt < 16; ++kt) {
            wmma::load_matrix_sync(bf, wb + (16 + kt) * 8 * 64, 64);
#pragma unroll
            for (int i = 0; i < 3; ++i) {
                wmma::load_matrix_sync(af, ys[i] + kt * 8, SA);
                wmma::mma_sync(acc[i], af, bf, acc[i]);
            }
        }
        wmma::load_matrix_sync(bf, wb + 32 * 8 * 64, 64);
#pragma unroll
        for (int i = 0; i < 3; ++i) {
            wmma::load_matrix_sync(af, xs[i] + 128, SA);
            wmma::mma_sync(acc[i], af, bf, acc[i]);
        }
#pragma unroll
        for (int i = 0; i < 3; ++i) {
#pragma unroll
            for (int e = 0; e < acc[i].num_elements; ++e) {
                float v = acc[i].x[e];
                acc[i].x[e] = rna((v >= 0.0f) ? v : 0.2f * v);
            }
            wmma::store_matrix_sync(sm + OFF_H + (mh * 3 + i) * 16 * SH + nt * 16, acc[i], SH, wmma::mem_row_major);
        }
    }
    __syncthreads();

    // ===== gf2 GEMM2: [96 x 72] @ [72 x 128] raw -> scratch (G0,G1,G2,A,V,L) =====
    {
        const int nt = wid;
        FragC acc[6];
#pragma unroll
        for (int i = 0; i < 6; ++i) wmma::fill_fragment(acc[i], 0.0f);
        FragA af; FragB bf;
        const float* wb = g_w + WO_G22 + nt * 16;
#pragma unroll
        for (int kt = 0; kt < 9; ++kt) {
            wmma::load_matrix_sync(bf, wb + kt * 8 * 128, 128);
#pragma unroll
            for (int i = 0; i < 6; ++i) {
                wmma::load_matrix_sync(af, sm + OFF_H + i * 16 * SH + kt * 8, SH);
                wmma::mma_sync(acc[i], af, bf, acc[i]);
            }
        }
#pragma unroll
        for (int i = 0; i < 6; ++i) {
            int bidx = (i < 3) ? (3 + i) : (i - 3);
            wmma::store_matrix_sync(sm + bidx * (R * SA) + nt * 16, acc[i], SA, wmma::mem_row_major);
        }
    }
    __syncthreads();

    // ===== trimodal epilogue: fus[r][256+c] = sum_p tanh(n2[p]*tanh(raw_p)) =====
    for (int idx = tid; idx < 16 * 128; idx += NT) {
        int r = idx >> 7, c = idx & 127;
        const float* sc = sm + OFF_SC + r * 16 + 9;
        float s = 0.0f;
#pragma unroll
        for (int p = 0; p < 6; ++p) {
            int bidx = (p < 3) ? (3 + p) : (p - 3);
            s += tanh_fast(sc[p] * tanh_fast(sm[bidx * (R * SA) + r * SA + c]));
        }
        sm[OFF_FUS + r * SF + 256 + c] = rna(s);
    }
    __syncthreads();

    // ===== ll1: [16 x 392] @ [392 x 64], 2-way k-split, raw partials in H =====
    {
        const int part = wid >> 2, nt = wid & 3;
        FragC acc; wmma::fill_fragment(acc, 0.0f);
        FragA af; FragB bf;
        const float* wb = g_w + WO_LL1 + nt * 16;
        if (part == 0) {
#pragma unroll
            for (int kt = 0; kt < 25; ++kt) {
                wmma::load_matrix_sync(bf, wb + kt * 8 * 64, 64);
                wmma::load_matrix_sync(af, sm + OFF_FUS + kt * 8, SF);
                wmma::mma_sync(acc, af, bf, acc);
            }
        } else {
#pragma unroll
            for (int kt = 25; kt < 49; ++kt) {
                wmma::load_matrix_sync(bf, wb + kt * 8 * 64, 64);
                wmma::load_matrix_sync(af, sm + OFF_FUS + kt * 8, SF);
                wmma::mma_sync(acc, af, bf, acc);
            }
        }
        wmma::store_matrix_sync(sm + OFF_H + part * 16 * SH + nt * 16, acc, SH, wmma::mem_row_major);
    }
    __syncthreads();
    for (int idx = tid; idx < 16 * 64; idx += NT) {
        int r = idx >> 6, c = idx & 63;
        float v = sm[OFF_H + r * SH + c] + sm[OFF_H + (16 + r) * SH + c];
        sm[OFF_H2 + r * SH + c] = rna(tanh_fast(v));
    }
    __syncthreads();

    // ===== ll2: [16 x 72] @ [72 x 64]; tanh in fragment -> H rows 0..15 =====
    if (wid < 4) {
        const int nt = wid;
        FragC acc; wmma::fill_fragment(acc, 0.0f);
        FragA af; FragB bf;
        const float* wb = g_w + WO_LL2 + nt * 16;
#pragma unroll
        for (int kt = 0; kt < 9; ++kt) {
            wmma::load_matrix_sync(bf, wb + kt * 8 * 64, 64);
            wmma::load_matrix_sync(af, sm + OFF_H2 + kt * 8, SH);
            wmma::mma_sync(acc, af, bf, acc);
        }
#pragma unroll
        for (int e = 0; e < acc.num_elements; ++e)
            acc.x[e] = rna(tanh_fast(acc.x[e]));
        wmma::store_matrix_sync(sm + OFF_H + nt * 16, acc, SH, wmma::mem_row_major);
    }
    __syncthreads();

    // ===== ll3: [16 x 72] @ [72 x 128]; accurate tanh in fragment -> gmem =====
    {
        const int nt = wid;
        FragC acc; wmma::fill_fragment(acc, 0.0f);
        FragA af; FragB bf;
        const float* wb = g_w + WO_LL3 + nt * 16;
#pragma unroll
        for (int kt = 0; kt < 9; ++kt) {
            wmma::load_matrix_sync(bf, wb + kt * 8 * 128, 128);
            wmma::load_matrix_sync(af, sm + OFF_H + kt * 8, SH);
            wmma::mma_sync(acc, af, bf, acc);
        }
#pragma unroll
        for (int e = 0; e < acc.num_elements; ++e)
            acc.x[e] = tanhf(acc.x[e]);
        wmma::store_matrix_sync(out + (size_t)blockIdx.x * R * D + nt * 16, acc, D, wmma::mem_row_major);
    }
}

extern "C" void kernel_launch(void* const* d_in, const int* in_sizes, int n_in,
                              void* d_out, int out_size) {
    const float* Lm     = (const float*)d_in[0];
    const float* Am     = (const float*)d_in[1];
    const float* Vm     = (const float*)d_in[2];
    const float* att_w  = (const float*)d_in[3];
    const float* att_b  = (const float*)d_in[4];
    const float* gf_w1  = (const float*)d_in[5];
    const float* gf_b1  = (const float*)d_in[6];
    const float* gf_w2  = (const float*)d_in[7];
    const float* gf_b2  = (const float*)d_in[8];
    const float* gf2_w1 = (const float*)d_in[9];
    const float* gf2_b1 = (const float*)d_in[10];
    const float* gf2_w2 = (const float*)d_in[11];
    const float* gf2_b2 = (const float*)d_in[12];
    const float* ll_w1  = (const float*)d_in[13];
    const float* ll_b1  = (const float*)d_in[14];
    const float* ll_w2  = (const float*)d_in[15];
    const float* ll_b2  = (const float*)d_in[16];
    const float* ll_w3  = (const float*)d_in[17];
    const float* ll_b3  = (const float*)d_in[18];

    convert_weights<<<(WTOT + 255) / 256, 256>>>(
        gf_w1, gf_b1, gf_w2, gf_b2, gf2_w1, gf2_b1, gf2_w2, gf2_b2,
        ll_w1, ll_b1, ll_w2, ll_b2, ll_w3, ll_b3);

    int nrows = in_sizes[0] / D;
    int grid = nrows / R;
    size_t smem = (size_t)SMEM_FLOATS * sizeof(float);
    cudaFuncSetAttribute(graphfusion_kernel,
                         cudaFuncAttributeMaxDynamicSharedMemorySize, (int)smem);
    graphfusion_kernel<<<grid, NT, smem>>>(Lm, Am, Vm, att_w, att_b, (float*)d_out);
}

// round 10
// speedup vs baseline: 3.5747x; 1.1843x over previous
#include <cuda_runtime.h>
#include <mma.h>
#include <math.h>

using namespace nvcuda;

namespace {
constexpr int D = 128;
constexpr int R = 16;           // rows per block
constexpr int NT = 256;         // 8 warps
constexpr int SA = 140;         // activation stride: 140%32==12 -> conflict-free wmma ld/st
constexpr int SF = 396;         // fusion stride: 396%32==12
constexpr int SH = 76;          // H stride: 76%32==12
constexpr int OFF_A   = 0;                  // buffers: A(0) V(1) L(2) G0(3) G1(4) G2(5), each [16][SA]
constexpr int OFF_G0  = OFF_A + 3 * R * SA;
constexpr int OFF_FUS = OFF_A + 6 * R * SA; // [16][SF]
constexpr int OFF_H   = OFF_FUS + R * SF;   // [96][SH]
constexpr int OFF_H2  = OFF_H + 96 * SH;    // [16][SH]
constexpr int OFF_AW  = OFF_H2 + R * SH;    // [128]
constexpr int OFF_SC  = OFF_AW + 128;       // [16][16]
constexpr int SMEM_FLOATS = OFF_SC + R * 16;   // 28672 floats = 114688 B (x2 CTAs = 229376 B)

// Packed B-fragment tiles (8x16 each, stored in per-lane register order, 128 floats/tile).
// Tile ranges (contiguous, in this order):
constexpr int TB_GF1 = 0;            // gf_w1 : kt 0..32, nt 0..3  -> 132 tiles
constexpr int TB_GF2 = 132;          // gf_w2 : kt 0..8,  nt 0..7  ->  72
constexpr int TB_G21 = 204;          // gf2_w1: kt 0..32, nt 0..3  -> 132
constexpr int TB_G22 = 336;          // gf2_w2: kt 0..8,  nt 0..7  ->  72
constexpr int TB_LL1 = 408;          // ll_w1 : kt 0..48, nt 0..3  -> 196
constexpr int TB_LL2 = 604;          // ll_w2 : kt 0..8,  nt 0..3  ->  36
constexpr int TB_LL3 = 640;          // ll_w3 : kt 0..8,  nt 0..7  ->  72
constexpr int N_TILES = 712;
}

__device__ float g_w[N_TILES * 128];

__device__ __forceinline__ float warp_sum(float x) {
#pragma unroll
    for (int o = 16; o > 0; o >>= 1) x += __shfl_xor_sync(0xffffffffu, x, o);
    return x;
}
__device__ __forceinline__ float warp_max(float x) {
#pragma unroll
    for (int o = 16; o > 0; o >>= 1) x = fmaxf(x, __shfl_xor_sync(0xffffffffu, x, o));
    return x;
}
__device__ __forceinline__ float tanh_fast(float x) {
    float y;
    asm("tanh.approx.f32 %0, %1;" : "=f"(y) : "f"(x));
    return y;
}
__device__ __forceinline__ float rna(float x) {
    unsigned u;
    asm("cvt.rna.tf32.f32 %0, %1;" : "=r"(u) : "f"(x));
    return __uint_as_float(u);
}
__device__ __forceinline__ float4 r4(float4 v) {
    return make_float4(rna(v.x), rna(v.y), rna(v.z), rna(v.w));
}

typedef wmma::fragment<wmma::matrix_a, 16, 16, 8, wmma::precision::tf32, wmma::row_major> FragA;
typedef wmma::fragment<wmma::matrix_b, 16, 16, 8, wmma::precision::tf32, wmma::row_major> FragB;
typedef wmma::fragment<wmma::accumulator, 16, 16, 8, float> FragC;

// Load a pre-packed B fragment: one float4 LDG per lane.
__device__ __forceinline__ void load_bfrag(FragB& bf, int tile, int lane) {
    float4 q = __ldg((const float4*)(g_w + tile * 128 + lane * 4));
    bf.x[0] = q.x; bf.x[1] = q.y; bf.x[2] = q.z; bf.x[3] = q.w;
}

// Convert kernel: build canonical 8x16 B tile (weights + bias row + zero pad, tf32-rounded),
// pass it through wmma::load_matrix_sync, store the lane-register image packed.
__global__ void convert_weights(
    const float* __restrict__ gf_w1, const float* __restrict__ gf_b1,
    const float* __restrict__ gf_w2, const float* __restrict__ gf_b2,
    const float* __restrict__ gf2_w1, const float* __restrict__ gf2_b1,
    const float* __restrict__ gf2_w2, const float* __restrict__ gf2_b2,
    const float* __restrict__ ll_w1, const float* __restrict__ ll_b1,
    const float* __restrict__ ll_w2, const float* __restrict__ ll_b2,
    const float* __restrict__ ll_w3, const float* __restrict__ ll_b3)
{
    __shared__ float tile[8][128];
    const int w = threadIdx.x >> 5, lane = threadIdx.x & 31;
    const int t = blockIdx.x * 8 + w;
    if (t >= N_TILES) return;   // warp-uniform

    int t2 = t;
    const float* wsrc; const float* bsrc; int nNT, rmax;
    if      (t2 < TB_GF2) { t2 -= TB_GF1; wsrc = gf_w1;  bsrc = gf_b1;  nNT = 4; rmax = 256; }
    else if (t2 < TB_G21) { t2 -= TB_GF2; wsrc = gf_w2;  bsrc = gf_b2;  nNT = 8; rmax = 64;  }
    else if (t2 < TB_G22) { t2 -= TB_G21; wsrc = gf2_w1; bsrc = gf2_b1; nNT = 4; rmax = 256; }
    else if (t2 < TB_LL1) { t2 -= TB_G22; wsrc = gf2_w2; bsrc = gf2_b2; nNT = 8; rmax = 64;  }
    else if (t2 < TB_LL2) { t2 -= TB_LL1; wsrc = ll_w1;  bsrc = ll_b1;  nNT = 4; rmax = 384; }
    else if (t2 < TB_LL3) { t2 -= TB_LL2; wsrc = ll_w2;  bsrc = ll_b2;  nNT = 4; rmax = 64;  }
    else                  { t2 -= TB_LL3; wsrc = ll_w3;  bsrc = ll_b3;  nNT = 8; rmax = 64;  }
    const int kt = t2 / nNT, nt = t2 % nNT;
    const int ncols = nNT * 16;

#pragma unroll
    for (int j = 0; j < 4; ++j) {
        int idx = lane * 4 + j;            // 0..127 = rr*16+cc
        int rr = idx >> 4, cc = idx & 15;
        int r = kt * 8 + rr, c = nt * 16 + cc;
        float v = 0.0f;
        if (r < rmax)       v = wsrc[r * ncols + c];
        else if (r == rmax) v = bsrc[c];
        tile[w][idx] = rna(v);
    }
    __syncwarp();
    FragB bf;
    wmma::load_matrix_sync(bf, tile[w], 16);
    float4 q = make_float4(bf.x[0], bf.x[1], bf.x[2], bf.x[3]);
    ((float4*)(g_w + t * 128))[lane] = q;
}

__global__ void __launch_bounds__(NT, 2)
graphfusion_kernel(
    const float* __restrict__ Lm, const float* __restrict__ Am, const float* __restrict__ Vm,
    const float* __restrict__ att_w, const float* __restrict__ att_b,
    float* __restrict__ out)
{
    extern __shared__ float sm[];
    const int tid  = threadIdx.x;
    const int lane = tid & 31;
    const int wid  = tid >> 5;   // 0..7

    // ---- init: att_w + constant bias columns ([1,0,0,0,0,0,0,0]) ----
    if (tid < D) sm[OFF_AW + tid] = att_w[tid];
    for (int idx = tid; idx < 1792; idx += NT) {
        int addr, c;
        if (idx < 768)       { int b = idx >> 7, rem = idx & 127; int r = rem >> 3; c = rem & 7;
                               addr = b * (R * SA) + r * SA + 128 + c; }
        else if (idx < 896)  { int i = idx - 768;  int r = i >> 3; c = i & 7; addr = OFF_FUS + r * SF + 384 + c; }
        else if (idx < 1664) { int i = idx - 896;  int r = i >> 3; c = i & 7; addr = OFF_H  + r * SH + 64 + c; }
        else                 { int i = idx - 1664; int r = i >> 3; c = i & 7; addr = OFF_H2 + r * SH + 64 + c; }
        sm[addr] = (c == 0) ? 1.0f : 0.0f;
    }
    __syncthreads();
    const float attb = __ldg(att_b);

    // ================= Phase A: scalars + softmaxes + unimodal =================
    {
        float4 aw = ((const float4*)(sm + OFF_AW))[lane];
#pragma unroll
        for (int rr = 0; rr < 2; ++rr) {
            int r = wid * 2 + rr;
            size_t grow = (size_t)blockIdx.x * R + r;
            float4 a4 = ((const float4*)(Am + grow * D))[lane];
            float4 v4 = ((const float4*)(Vm + grow * D))[lane];
            float4 l4 = ((const float4*)(Lm + grow * D))[lane];

            float sa = tanh_fast(warp_sum(a4.x * aw.x + a4.y * aw.y + a4.z * aw.z + a4.w * aw.w) + attb);
            float sv = tanh_fast(warp_sum(v4.x * aw.x + v4.y * aw.y + v4.z * aw.z + v4.w * aw.w) + attb);
            float sl = tanh_fast(warp_sum(l4.x * aw.x + l4.y * aw.y + l4.z * aw.z + l4.w * aw.w) + attb);

            float4 u;
            u.x = (sa * a4.x + sv * v4.x + sl * l4.x) * (1.0f / 3.0f);
            u.y = (sa * a4.y + sv * v4.y + sl * l4.y) * (1.0f / 3.0f);
            u.z = (sa * a4.z + sv * v4.z + sl * l4.z) * (1.0f / 3.0f);
            u.w = (sa * a4.w + sv * v4.w + sl * l4.w) * (1.0f / 3.0f);
            ((float4*)(sm + OFF_FUS + r * SF))[lane] = r4(u);

            float ma = warp_max(fmaxf(fmaxf(a4.x, a4.y), fmaxf(a4.z, a4.w)));
            float4 ea = make_float4(__expf(a4.x - ma), __expf(a4.y - ma), __expf(a4.z - ma), __expf(a4.w - ma));
            float ia = 1.0f / warp_sum(ea.x + ea.y + ea.z + ea.w);
            float4 pa = make_float4(ea.x * ia, ea.y * ia, ea.z * ia, ea.w * ia);

            float mv = warp_max(fmaxf(fmaxf(v4.x, v4.y), fmaxf(v4.z, v4.w)));
            float4 ev = make_float4(__expf(v4.x - mv), __expf(v4.y - mv), __expf(v4.z - mv), __expf(v4.w - mv));
            float iv = 1.0f / warp_sum(ev.x + ev.y + ev.z + ev.w);
            float4 pv = make_float4(ev.x * iv, ev.y * iv, ev.z * iv, ev.w * iv);

            float ml = warp_max(fmaxf(fmaxf(l4.x, l4.y), fmaxf(l4.z, l4.w)));
            float4 el = make_float4(__expf(l4.x - ml), __expf(l4.y - ml), __expf(l4.z - ml), __expf(l4.w - ml));
            float il = 1.0f / warp_sum(el.x + el.y + el.z + el.w);
            float4 pl = make_float4(el.x * il, el.y * il, el.z * il, el.w * il);

            ((float4*)(sm + OFF_A + 0 * R * SA + r * SA))[lane] = r4(pa);
            ((float4*)(sm + OFF_A + 1 * R * SA + r * SA))[lane] = r4(pv);
            ((float4*)(sm + OFF_A + 2 * R * SA + r * SA))[lane] = r4(pl);

            float dav = warp_sum(pa.x * pv.x + pa.y * pv.y + pa.z * pv.z + pa.w * pv.w);
            float dal = warp_sum(pa.x * pl.x + pa.y * pl.y + pa.z * pl.z + pa.w * pl.w);
            float dvl = warp_sum(pv.x * pl.x + pv.y * pl.y + pv.z * pl.z + pv.w * pl.w);

            float sav = (sa + sv) / (dav + 0.5f);
            float sal = (sa + sl) / (dal + 0.5f);
            float svl = (sl + sv) / (dvl + 0.5f);
            float mx = fmaxf(sav, fmaxf(sal, svl));
            float e0 = __expf(sav - mx), e1 = __expf(sal - mx), e2 = __expf(svl - mx);
            float is = 1.0f / (e0 + e1 + e2);
            if (lane == 0) {
                float* sc = sm + OFF_SC + r * 16;
                sc[0] = e0 * is; sc[1] = e1 * is; sc[2] = e2 * is;
                sc[3] = sav; sc[4] = sal; sc[5] = svl;
                sc[6] = sa;  sc[7] = sv;  sc[8] = sl;
            }
        }
    }
    __syncthreads();

    // ===== gf GEMM1: [48 x 264] @ [264 x 64] =====
    // 12 tiles = 3 mt x 4 nt. Warps 0-3: nt=wid, chains mt={0,2} sharing B; warps 4-7: nt=wid-4, mt=1.
    {
        const int nt = wid & 3;
        if (wid < 4) {
            FragA af0, af2; FragB bf;
            FragC acc0, acc2;
            wmma::fill_fragment(acc0, 0.0f);
            wmma::fill_fragment(acc2, 0.0f);
            const float* x0 = sm + 0 * (R * SA);   // a
            const float* y0 = sm + 1 * (R * SA);   // v
            const float* x2 = sm + 1 * (R * SA);   // v
            const float* y2 = sm + 2 * (R * SA);   // l
#pragma unroll
            for (int kt = 0; kt < 16; ++kt) {
                load_bfrag(bf, TB_GF1 + kt * 4 + nt, lane);
                wmma::load_matrix_sync(af0, x0 + kt * 8, SA);
                wmma::load_matrix_sync(af2, x2 + kt * 8, SA);
                wmma::mma_sync(acc0, af0, bf, acc0);
                wmma::mma_sync(acc2, af2, bf, acc2);
            }
#pragma unroll
            for (int kt = 0; kt < 16; ++kt) {
                load_bfrag(bf, TB_GF1 + (16 + kt) * 4 + nt, lane);
                wmma::load_matrix_sync(af0, y0 + kt * 8, SA);
                wmma::load_matrix_sync(af2, y2 + kt * 8, SA);
                wmma::mma_sync(acc0, af0, bf, acc0);
                wmma::mma_sync(acc2, af2, bf, acc2);
            }
            load_bfrag(bf, TB_GF1 + 32 * 4 + nt, lane);
            wmma::load_matrix_sync(af0, x0 + 128, SA);
            wmma::load_matrix_sync(af2, x2 + 128, SA);
            wmma::mma_sync(acc0, af0, bf, acc0);
            wmma::mma_sync(acc2, af2, bf, acc2);
#pragma unroll
            for (int e = 0; e < acc0.num_elements; ++e) {
                float v0 = acc0.x[e];
                acc0.x[e] = rna((v0 >= 0.0f) ? v0 : 0.2f * v0);
                float v2 = acc2.x[e];
                acc2.x[e] = rna((v2 >= 0.0f) ? v2 : 0.2f * v2);
            }
            wmma::store_matrix_sync(sm + OFF_H + 0 * 16 * SH + nt * 16, acc0, SH, wmma::mem_row_major);
            wmma::store_matrix_sync(sm + OFF_H + 2 * 16 * SH + nt * 16, acc2, SH, wmma::mem_row_major);
        } else {
            FragA af; FragB bf;
            FragC acc;
            wmma::fill_fragment(acc, 0.0f);
            const float* x1 = sm + 0 * (R * SA);   // a
            const float* y1 = sm + 2 * (R * SA);   // l
#pragma unroll
            for (int kt = 0; kt < 16; ++kt) {
                load_bfrag(bf, TB_GF1 + kt * 4 + nt, lane);
                wmma::load_matrix_sync(af, x1 + kt * 8, SA);
                wmma::mma_sync(acc, af, bf, acc);
            }
#pragma unroll
            for (int kt = 0; kt < 16; ++kt) {
                load_bfrag(bf, TB_GF1 + (16 + kt) * 4 + nt, lane);
                wmma::load_matrix_sync(af, y1 + kt * 8, SA);
                wmma::mma_sync(acc, af, bf, acc);
            }
            load_bfrag(bf, TB_GF1 + 32 * 4 + nt, lane);
            wmma::load_matrix_sync(af, x1 + 128, SA);
            wmma::mma_sync(acc, af, bf, acc);
#pragma unroll
            for (int e = 0; e < acc.num_elements; ++e) {
                float v = acc.x[e];
                acc.x[e] = rna((v >= 0.0f) ? v : 0.2f * v);
            }
            wmma::store_matrix_sync(sm + OFF_H + 1 * 16 * SH + nt * 16, acc, SH, wmma::mem_row_major);
        }
    }
    __syncthreads();

    // ===== gf GEMM2: [48 x 72] @ [72 x 128]; tanh in fragment -> G0/G1/G2 =====
    {
        const int nt = wid;
        FragC acc[3];
#pragma unroll
        for (int i = 0; i < 3; ++i) wmma::fill_fragment(acc[i], 0.0f);
        FragA af; FragB bf;
#pragma unroll
        for (int kt = 0; kt < 9; ++kt) {
            load_bfrag(bf, TB_GF2 + kt * 8 + nt, lane);
#pragma unroll
            for (int i = 0; i < 3; ++i) {
                wmma::load_matrix_sync(af, sm + OFF_H + i * 16 * SH + kt * 8, SH);
                wmma::mma_sync(acc[i], af, bf, acc[i]);
            }
        }
#pragma unroll
        for (int i = 0; i < 3; ++i) {
#pragma unroll
            for (int e = 0; e < acc[i].num_elements; ++e)
                acc[i].x[e] = rna(tanh_fast(acc[i].x[e]));
            wmma::store_matrix_sync(sm + OFF_G0 + i * (R * SA) + nt * 16, acc[i], SA, wmma::mem_row_major);
        }
    }
    __syncthreads();

    // ============ Phase C: softmax(g) dots, n2, a_v/a_l/v_l, bimodal ============
    {
#pragma unroll
        for (int rr = 0; rr < 2; ++rr) {
            int r = wid * 2 + rr;
            float4 g0 = ((const float4*)(sm + OFF_A + 3 * R * SA + r * SA))[lane];
            float4 g1 = ((const float4*)(sm + OFF_A + 4 * R * SA + r * SA))[lane];
            float4 g2 = ((const float4*)(sm + OFF_A + 5 * R * SA + r * SA))[lane];
            float4 pa = ((const float4*)(sm + OFF_A + 0 * R * SA + r * SA))[lane];
            float4 pv = ((const float4*)(sm + OFF_A + 1 * R * SA + r * SA))[lane];
            float4 pl = ((const float4*)(sm + OFF_A + 2 * R * SA + r * SA))[lane];

            float m0 = warp_max(fmaxf(fmaxf(g0.x, g0.y), fmaxf(g0.z, g0.w)));
            float m1 = warp_max(fmaxf(fmaxf(g1.x, g1.y), fmaxf(g1.z, g1.w)));
            float m2 = warp_max(fmaxf(fmaxf(g2.x, g2.y), fmaxf(g2.z, g2.w)));
            float4 e0 = make_float4(__expf(g0.x - m0), __expf(g0.y - m0), __expf(g0.z - m0), __expf(g0.w - m0));
            float4 e1 = make_float4(__expf(g1.x - m1), __expf(g1.y - m1), __expf(g1.z - m1), __expf(g1.w - m1));
            float4 e2 = make_float4(__expf(g2.x - m2), __expf(g2.y - m2), __expf(g2.z - m2), __expf(g2.w - m2));
            float i0 = 1.0f / warp_sum(e0.x + e0.y + e0.z + e0.w);
            float i1 = 1.0f / warp_sum(e1.x + e1.y + e1.z + e1.w);
            float i2 = 1.0f / warp_sum(e2.x + e2.y + e2.z + e2.w);

            float d01 = warp_sum(e0.x * e1.x + e0.y * e1.y + e0.z * e1.z + e0.w * e1.w);
            float d02 = warp_sum(e0.x * e2.x + e0.y * e2.y + e0.z * e2.z + e0.w * e2.w);
            float d12 = warp_sum(e1.x * e2.x + e1.y * e2.y + e1.z * e2.z + e1.w * e2.w);
            float d0l = warp_sum(e0.x * pl.x + e0.y * pl.y + e0.z * pl.z + e0.w * pl.w);
            float d1v = warp_sum(e1.x * pv.x + e1.y * pv.y + e1.z * pv.z + e1.w * pv.w);
            float d2a = warp_sum(e2.x * pa.x + e2.y * pa.y + e2.z * pa.z + e2.w * pa.w);

            const float* sc = sm + OFF_SC + r * 16;
            float sav = sc[3], sal = sc[4], svl = sc[5];
            float sa = sc[6], sv = sc[7], sl = sc[8];
            float t0 = (sav + svl) / (d02 * i0 * i2 + 0.5f);
            float t1 = (sav + sal) / (d01 * i0 * i1 + 0.5f);
            float t2 = (sal + svl) / (d12 * i1 * i2 + 0.5f);
            float t3 = (sav + sl)  / (d0l * i0 + 0.5f);
            float t4 = (sal + sv)  / (d1v * i1 + 0.5f);
            float t5 = (sa  + svl) / (d2a * i2 + 0.5f);
            float mm = fmaxf(fmaxf(fmaxf(t0, t1), fmaxf(t2, t3)), fmaxf(t4, t5));
            float q0 = __expf(t0 - mm), q1 = __expf(t1 - mm), q2 = __expf(t2 - mm);
            float q3 = __expf(t3 - mm), q4 = __expf(t4 - mm), q5 = __expf(t5 - mm);
            float qi = 1.0f / (q0 + q1 + q2 + q3 + q4 + q5);
            if (lane == 0) {
                float* scw = sm + OFF_SC + r * 16;
                scw[9]  = q0 * qi; scw[10] = q1 * qi; scw[11] = q2 * qi;
                scw[12] = q3 * qi; scw[13] = q4 * qi; scw[14] = q5 * qi;
            }

            float n0 = sc[0], n1 = sc[1], n2v = sc[2];
            float4 av = make_float4(tanh_fast(n0 * g0.x), tanh_fast(n0 * g0.y), tanh_fast(n0 * g0.z), tanh_fast(n0 * g0.w));
            float4 al = make_float4(tanh_fast(n1 * g1.x), tanh_fast(n1 * g1.y), tanh_fast(n1 * g1.z), tanh_fast(n1 * g1.w));
            float4 vl = make_float4(tanh_fast(n2v * g2.x), tanh_fast(n2v * g2.y), tanh_fast(n2v * g2.z), tanh_fast(n2v * g2.w));
            ((float4*)(sm + OFF_A + 3 * R * SA + r * SA))[lane] = r4(av);
            ((float4*)(sm + OFF_A + 4 * R * SA + r * SA))[lane] = r4(al);
            ((float4*)(sm + OFF_A + 5 * R * SA + r * SA))[lane] = r4(vl);
            float4 bm = make_float4(av.x + al.x + vl.x, av.y + al.y + vl.y,
                                    av.z + al.z + vl.z, av.w + al.w + vl.w);
            ((float4*)(sm + OFF_FUS + r * SF + 128))[lane] = r4(bm);
        }
    }
    __syncthreads();

    // ===== gf2 GEMM1 (6 pairs merged): [96 x 264] @ [264 x 64]; leaky in fragment =====
    {
        const int g2x[6] = {3, 3, 5, 3, 4, 5}, g2y[6] = {5, 4, 4, 2, 1, 0};
        const int mh = wid >> 2, nt = wid & 3;
        const float* xs[3]; const float* ys[3];
#pragma unroll
        for (int i = 0; i < 3; ++i) {
            xs[i] = sm + g2x[mh * 3 + i] * (R * SA);
            ys[i] = sm + g2y[mh * 3 + i] * (R * SA);
        }
        FragC acc[3];
#pragma unroll
        for (int i = 0; i < 3; ++i) wmma::fill_fragment(acc[i], 0.0f);
        FragA af; FragB bf;
#pragma unroll
        for (int kt = 0; kt < 16; ++kt) {
            load_bfrag(bf, TB_G21 + kt * 4 + nt, lane);
#pragma unroll
            for (int i = 0; i < 3; ++i) {
                wmma::load_matrix_sync(af, xs[i] + kt * 8, SA);
                wmma::mma_sync(acc[i], af, bf, acc[i]);
            }
        }
#pragma unroll
        for (int kt = 0; kt < 16; ++kt) {
            load_bfrag(bf, TB_G21 + (16 + kt) * 4 + nt, lane);
#pragma unroll
            for (int i = 0; i < 3; ++i) {
                wmma::load_matrix_sync(af, ys[i] + kt * 8, SA);
                wmma::mma_sync(acc[i], af, bf, acc[i]);
            }
        }
        load_bfrag(bf, TB_G21 + 32 * 4 + nt, lane);
#pragma unroll
        for (int i = 0; i < 3; ++i) {
            wmma::load_matrix_sync(af, xs[i] + 128, SA);
            wmma::mma_sync(acc[i], af, bf, acc[i]);
        }
#pragma unroll
        for (int i = 0; i < 3; ++i) {
#pragma unroll
            for (int e = 0; e < acc[i].num_elements; ++e) {
                float v = acc[i].x[e];
                acc[i].x[e] = rna((v >= 0.0f) ? v : 0.2f * v);
            }
            wmma::store_matrix_sync(sm + OFF_H + (mh * 3 + i) * 16 * SH + nt * 16, acc[i], SH, wmma::mem_row_major);
        }
    }
    __syncthreads();

    // ===== gf2 GEMM2: [96 x 72] @ [72 x 128] raw -> scratch (G0,G1,G2,A,V,L) =====
    {
        const int nt = wid;
        FragC acc[6];
#pragma unroll
        for (int i = 0; i < 6; ++i) wmma::fill_fragment(acc[i], 0.0f);
        FragA af; FragB bf;
#pragma unroll
        for (int kt = 0; kt < 9; ++kt) {
            load_bfrag(bf, TB_G22 + kt * 8 + nt, lane);
#pragma unroll
            for (int i = 0; i < 6; ++i) {
                wmma::load_matrix_sync(af, sm + OFF_H + i * 16 * SH + kt * 8, SH);
                wmma::mma_sync(acc[i], af, bf, acc[i]);
            }
        }
#pragma unroll
        for (int i = 0; i < 6; ++i) {
            int bidx = (i < 3) ? (3 + i) : (i - 3);
            wmma::store_matrix_sync(sm + bidx * (R * SA) + nt * 16, acc[i], SA, wmma::mem_row_major);
        }
    }
    __syncthreads();

    // ===== trimodal epilogue: fus[r][256+c] = sum_p tanh(n2[p]*tanh(raw_p)) =====
    for (int idx = tid; idx < 16 * 128; idx += NT) {
        int r = idx >> 7, c = idx & 127;
        const float* sc = sm + OFF_SC + r * 16 + 9;
        float s = 0.0f;
#pragma unroll
        for (int p = 0; p < 6; ++p) {
            int bidx = (p < 3) ? (3 + p) : (p - 3);
            s += tanh_fast(sc[p] * tanh_fast(sm[bidx * (R * SA) + r * SA + c]));
        }
        sm[OFF_FUS + r * SF + 256 + c] = rna(s);
    }
    __syncthreads();

    // ===== ll1: [16 x 392] @ [392 x 64], 2-way k-split, raw partials in H =====
    {
        const int part = wid >> 2, nt = wid & 3;
        FragC acc; wmma::fill_fragment(acc, 0.0f);
        FragA af; FragB bf;
        if (part == 0) {
#pragma unroll
            for (int kt = 0; kt < 25; ++kt) {
                load_bfrag(bf, TB_LL1 + kt * 4 + nt, lane);
                wmma::load_matrix_sync(af, sm + OFF_FUS + kt * 8, SF);
                wmma::mma_sync(acc, af, bf, acc);
            }
        } else {
#pragma unroll
            for (int kt = 25; kt < 49; ++kt) {
                load_bfrag(bf, TB_LL1 + kt * 4 + nt, lane);
                wmma::load_matrix_sync(af, sm + OFF_FUS + kt * 8, SF);
                wmma::mma_sync(acc, af, bf, acc);
            }
        }
        wmma::store_matrix_sync(sm + OFF_H + part * 16 * SH + nt * 16, acc, SH, wmma::mem_row_major);
    }
    __syncthreads();
    for (int idx = tid; idx < 16 * 64; idx += NT) {
        int r = idx >> 6, c = idx & 63;
        float v = sm[OFF_H + r * SH + c] + sm[OFF_H + (16 + r) * SH + c];
        sm[OFF_H2 + r * SH + c] = rna(tanh_fast(v));
    }
    __syncthreads();

    // ===== ll2: [16 x 72] @ [72 x 64]; tanh in fragment -> H rows 0..15 =====
    if (wid < 4) {
        const int nt = wid;
        FragC acc; wmma::fill_fragment(acc, 0.0f);
        FragA af; FragB bf;
#pragma unroll
        for (int kt = 0; kt < 9; ++kt) {
            load_bfrag(bf, TB_LL2 + kt * 4 + nt, lane);
            wmma::load_matrix_sync(af, sm + OFF_H2 + kt * 8, SH);
            wmma::mma_sync(acc, af, bf, acc);
        }
#pragma unroll
        for (int e = 0; e < acc.num_elements; ++e)
            acc.x[e] = rna(tanh_fast(acc.x[e]));
        wmma::store_matrix_sync(sm + OFF_H + nt * 16, acc, SH, wmma::mem_row_major);
    }
    __syncthreads();

    // ===== ll3: [16 x 72] @ [72 x 128]; accurate tanh in fragment -> gmem =====
    {
        const int nt = wid;
        FragC acc; wmma::fill_fragment(acc, 0.0f);
        FragA af; FragB bf;
#pragma unroll
        for (int kt = 0; kt < 9; ++kt) {
            load_bfrag(bf, TB_LL3 + kt * 8 + nt, lane);
            wmma::load_matrix_sync(af, sm + OFF_H + kt * 8, SH);
            wmma::mma_sync(acc, af, bf, acc);
        }
#pragma unroll
        for (int e = 0; e < acc.num_elements; ++e)
            acc.x[e] = tanhf(acc.x[e]);
        wmma::store_matrix_sync(out + (size_t)blockIdx.x * R * D + nt * 16, acc, D, wmma::mem_row_major);
    }
}

extern "C" void kernel_launch(void* const* d_in, const int* in_sizes, int n_in,
                              void* d_out, int out_size) {
    const float* Lm     = (const float*)d_in[0];
    const float* Am     = (const float*)d_in[1];
    const float* Vm     = (const float*)d_in[2];
    const float* att_w  = (const float*)d_in[3];
    const float* att_b  = (const float*)d_in[4];
    const float* gf_w1  = (const float*)d_in[5];
    const float* gf_b1  = (const float*)d_in[6];
    const float* gf_w2  = (const float*)d_in[7];
    const float* gf_b2  = (const float*)d_in[8];
    const float* gf2_w1 = (const float*)d_in[9];
    const float* gf2_b1 = (const float*)d_in[10];
    const float* gf2_w2 = (const float*)d_in[11];
    const float* gf2_b2 = (const float*)d_in[12];
    const float* ll_w1  = (const float*)d_in[13];
    const float* ll_b1  = (const float*)d_in[14];
    const float* ll_w2  = (const float*)d_in[15];
    const float* ll_b2  = (const float*)d_in[16];
    const float* ll_w3  = (const float*)d_in[17];
    const float* ll_b3  = (const float*)d_in[18];

    convert_weights<<<(N_TILES + 7) / 8, 256>>>(
        gf_w1, gf_b1, gf_w2, gf_b2, gf2_w1, gf2_b1, gf2_w2, gf2_b2,
        ll_w1, ll_b1, ll_w2, ll_b2, ll_w3, ll_b3);

    int nrows = in_sizes[0] / D;
    int grid = nrows / R;
    size_t smem = (size_t)SMEM_FLOATS * sizeof(float);
    cudaFuncSetAttribute(graphfusion_kernel,
                         cudaFuncAttributeMaxDynamicSharedMemorySize, (int)smem);
    graphfusion_kernel<<<grid, NT, smem>>>(Lm, Am, Vm, att_w, att_b, (float*)d_out);
}

// round 11
// speedup vs baseline: 4.0175x; 1.1239x over previous
#include <cuda_runtime.h>
#include <mma.h>
#include <math.h>

using namespace nvcuda;

namespace {
constexpr int D = 128;
constexpr int R = 16;           // rows per block
constexpr int NT = 256;         // 8 warps
constexpr int SA = 140;         // activation stride: 140%32==12 -> conflict-free wmma ld/st
constexpr int SF = 396;         // fusion stride: 396%32==12
constexpr int SH = 76;          // H stride: 76%32==12
constexpr int OFF_A   = 0;                  // buffers: A(0) V(1) L(2) G0(3) G1(4) G2(5), each [16][SA]
constexpr int OFF_G0  = OFF_A + 3 * R * SA;
constexpr int OFF_FUS = OFF_A + 6 * R * SA; // [16][SF]
constexpr int OFF_H   = OFF_FUS + R * SF;   // [96][SH]
constexpr int OFF_H2  = OFF_H + 96 * SH;    // [16][SH]
constexpr int OFF_AW  = OFF_H2 + R * SH;    // [128]
constexpr int OFF_SC  = OFF_AW + 128;       // [16][16]
constexpr int SMEM_FLOATS = OFF_SC + R * 16;   // 28672 floats = 114688 B (x2 CTAs = 229376 B)

// Packed B-fragment tiles (8x16 each, stored in per-lane register order, 128 floats/tile).
constexpr int TB_GF1 = 0;            // gf_w1 : kt 0..32, nt 0..3  -> 132 tiles
constexpr int TB_GF2 = 132;          // gf_w2 : kt 0..8,  nt 0..7  ->  72
constexpr int TB_G21 = 204;          // gf2_w1: kt 0..32, nt 0..3  -> 132
constexpr int TB_G22 = 336;          // gf2_w2: kt 0..8,  nt 0..7  ->  72
constexpr int TB_LL1 = 408;          // ll_w1 : kt 0..48, nt 0..3  -> 196
constexpr int TB_LL2 = 604;          // ll_w2 : kt 0..8,  nt 0..3  ->  36
constexpr int TB_LL3 = 640;          // ll_w3 : kt 0..8,  nt 0..7  ->  72
constexpr int N_TILES = 712;
}

__device__ float g_w[N_TILES * 128];

__device__ __forceinline__ float warp_sum(float x) {
#pragma unroll
    for (int o = 16; o > 0; o >>= 1) x += __shfl_xor_sync(0xffffffffu, x, o);
    return x;
}
__device__ __forceinline__ float warp_max(float x) {
#pragma unroll
    for (int o = 16; o > 0; o >>= 1) x = fmaxf(x, __shfl_xor_sync(0xffffffffu, x, o));
    return x;
}
__device__ __forceinline__ float tanh_fast(float x) {
    float y;
    asm("tanh.approx.f32 %0, %1;" : "=f"(y) : "f"(x));
    return y;
}
__device__ __forceinline__ float rna(float x) {
    unsigned u;
    asm("cvt.rna.tf32.f32 %0, %1;" : "=r"(u) : "f"(x));
    return __uint_as_float(u);
}
__device__ __forceinline__ float4 r4(float4 v) {
    return make_float4(rna(v.x), rna(v.y), rna(v.z), rna(v.w));
}

typedef wmma::fragment<wmma::matrix_a, 16, 16, 8, wmma::precision::tf32, wmma::row_major> FragA;
typedef wmma::fragment<wmma::matrix_b, 16, 16, 8, wmma::precision::tf32, wmma::row_major> FragB;
typedef wmma::fragment<wmma::accumulator, 16, 16, 8, float> FragC;

__device__ __forceinline__ void copy_frag(FragC& d, const FragC& s) {
#pragma unroll
    for (int e = 0; e < d.num_elements; ++e) d.x[e] = s.x[e];
}

// Load a pre-packed B fragment: one float4 LDG per lane.
__device__ __forceinline__ void load_bfrag(FragB& bf, int tile, int lane) {
    float4 q = __ldg((const float4*)(g_w + tile * 128 + lane * 4));
    bf.x[0] = q.x; bf.x[1] = q.y; bf.x[2] = q.z; bf.x[3] = q.w;
}

// Convert kernel: build canonical 8x16 B tile (weights + bias row + zero pad, tf32-rounded),
// pass it through wmma::load_matrix_sync, store the lane-register image packed.
__global__ void convert_weights(
    const float* __restrict__ gf_w1, const float* __restrict__ gf_b1,
    const float* __restrict__ gf_w2, const float* __restrict__ gf_b2,
    const float* __restrict__ gf2_w1, const float* __restrict__ gf2_b1,
    const float* __restrict__ gf2_w2, const float* __restrict__ gf2_b2,
    const float* __restrict__ ll_w1, const float* __restrict__ ll_b1,
    const float* __restrict__ ll_w2, const float* __restrict__ ll_b2,
    const float* __restrict__ ll_w3, const float* __restrict__ ll_b3)
{
    __shared__ float tile[8][128];
    const int w = threadIdx.x >> 5, lane = threadIdx.x & 31;
    const int t = blockIdx.x * 8 + w;
    if (t >= N_TILES) return;   // warp-uniform

    int t2 = t;
    const float* wsrc; const float* bsrc; int nNT, rmax;
    if      (t2 < TB_GF2) { t2 -= TB_GF1; wsrc = gf_w1;  bsrc = gf_b1;  nNT = 4; rmax = 256; }
    else if (t2 < TB_G21) { t2 -= TB_GF2; wsrc = gf_w2;  bsrc = gf_b2;  nNT = 8; rmax = 64;  }
    else if (t2 < TB_G22) { t2 -= TB_G21; wsrc = gf2_w1; bsrc = gf2_b1; nNT = 4; rmax = 256; }
    else if (t2 < TB_LL1) { t2 -= TB_G22; wsrc = gf2_w2; bsrc = gf2_b2; nNT = 8; rmax = 64;  }
    else if (t2 < TB_LL2) { t2 -= TB_LL1; wsrc = ll_w1;  bsrc = ll_b1;  nNT = 4; rmax = 384; }
    else if (t2 < TB_LL3) { t2 -= TB_LL2; wsrc = ll_w2;  bsrc = ll_b2;  nNT = 4; rmax = 64;  }
    else                  { t2 -= TB_LL3; wsrc = ll_w3;  bsrc = ll_b3;  nNT = 8; rmax = 64;  }
    const int kt = t2 / nNT, nt = t2 % nNT;
    const int ncols = nNT * 16;

#pragma unroll
    for (int j = 0; j < 4; ++j) {
        int idx = lane * 4 + j;            // 0..127 = rr*16+cc
        int rr = idx >> 4, cc = idx & 15;
        int r = kt * 8 + rr, c = nt * 16 + cc;
        float v = 0.0f;
        if (r < rmax)       v = wsrc[r * ncols + c];
        else if (r == rmax) v = bsrc[c];
        tile[w][idx] = rna(v);
    }
    __syncwarp();
    FragB bf;
    wmma::load_matrix_sync(bf, tile[w], 16);
    float4 q = make_float4(bf.x[0], bf.x[1], bf.x[2], bf.x[3]);
    ((float4*)(g_w + t * 128))[lane] = q;
}

__global__ void __launch_bounds__(NT, 2)
graphfusion_kernel(
    const float* __restrict__ Lm, const float* __restrict__ Am, const float* __restrict__ Vm,
    const float* __restrict__ att_w, const float* __restrict__ att_b,
    float* __restrict__ out)
{
    extern __shared__ float sm[];
    const int tid  = threadIdx.x;
    const int lane = tid & 31;
    const int wid  = tid >> 5;   // 0..7

    // ---- init: att_w + constant bias columns ([1,0,0,0,0,0,0,0]) ----
    if (tid < D) sm[OFF_AW + tid] = att_w[tid];
    for (int idx = tid; idx < 1792; idx += NT) {
        int addr, c;
        if (idx < 768)       { int b = idx >> 7, rem = idx & 127; int r = rem >> 3; c = rem & 7;
                               addr = b * (R * SA) + r * SA + 128 + c; }
        else if (idx < 896)  { int i = idx - 768;  int r = i >> 3; c = i & 7; addr = OFF_FUS + r * SF + 384 + c; }
        else if (idx < 1664) { int i = idx - 896;  int r = i >> 3; c = i & 7; addr = OFF_H  + r * SH + 64 + c; }
        else                 { int i = idx - 1664; int r = i >> 3; c = i & 7; addr = OFF_H2 + r * SH + 64 + c; }
        sm[addr] = (c == 0) ? 1.0f : 0.0f;
    }
    __syncthreads();
    const float attb = __ldg(att_b);

    // ================= Phase A: scalars + softmaxes + unimodal =================
    {
        float4 aw = ((const float4*)(sm + OFF_AW))[lane];
#pragma unroll
        for (int rr = 0; rr < 2; ++rr) {
            int r = wid * 2 + rr;
            size_t grow = (size_t)blockIdx.x * R + r;
            float4 a4 = ((const float4*)(Am + grow * D))[lane];
            float4 v4 = ((const float4*)(Vm + grow * D))[lane];
            float4 l4 = ((const float4*)(Lm + grow * D))[lane];

            float sa = tanh_fast(warp_sum(a4.x * aw.x + a4.y * aw.y + a4.z * aw.z + a4.w * aw.w) + attb);
            float sv = tanh_fast(warp_sum(v4.x * aw.x + v4.y * aw.y + v4.z * aw.z + v4.w * aw.w) + attb);
            float sl = tanh_fast(warp_sum(l4.x * aw.x + l4.y * aw.y + l4.z * aw.z + l4.w * aw.w) + attb);

            float4 u;
            u.x = (sa * a4.x + sv * v4.x + sl * l4.x) * (1.0f / 3.0f);
            u.y = (sa * a4.y + sv * v4.y + sl * l4.y) * (1.0f / 3.0f);
            u.z = (sa * a4.z + sv * v4.z + sl * l4.z) * (1.0f / 3.0f);
            u.w = (sa * a4.w + sv * v4.w + sl * l4.w) * (1.0f / 3.0f);
            ((float4*)(sm + OFF_FUS + r * SF))[lane] = r4(u);

            float ma = warp_max(fmaxf(fmaxf(a4.x, a4.y), fmaxf(a4.z, a4.w)));
            float4 ea = make_float4(__expf(a4.x - ma), __expf(a4.y - ma), __expf(a4.z - ma), __expf(a4.w - ma));
            float ia = 1.0f / warp_sum(ea.x + ea.y + ea.z + ea.w);
            float4 pa = make_float4(ea.x * ia, ea.y * ia, ea.z * ia, ea.w * ia);

            float mv = warp_max(fmaxf(fmaxf(v4.x, v4.y), fmaxf(v4.z, v4.w)));
            float4 ev = make_float4(__expf(v4.x - mv), __expf(v4.y - mv), __expf(v4.z - mv), __expf(v4.w - mv));
            float iv = 1.0f / warp_sum(ev.x + ev.y + ev.z + ev.w);
            float4 pv = make_float4(ev.x * iv, ev.y * iv, ev.z * iv, ev.w * iv);

            float ml = warp_max(fmaxf(fmaxf(l4.x, l4.y), fmaxf(l4.z, l4.w)));
            float4 el = make_float4(__expf(l4.x - ml), __expf(l4.y - ml), __expf(l4.z - ml), __expf(l4.w - ml));
            float il = 1.0f / warp_sum(el.x + el.y + el.z + el.w);
            float4 pl = make_float4(el.x * il, el.y * il, el.z * il, el.w * il);

            ((float4*)(sm + OFF_A + 0 * R * SA + r * SA))[lane] = r4(pa);
            ((float4*)(sm + OFF_A + 1 * R * SA + r * SA))[lane] = r4(pv);
            ((float4*)(sm + OFF_A + 2 * R * SA + r * SA))[lane] = r4(pl);

            float dav = warp_sum(pa.x * pv.x + pa.y * pv.y + pa.z * pv.z + pa.w * pv.w);
            float dal = warp_sum(pa.x * pl.x + pa.y * pl.y + pa.z * pl.z + pa.w * pl.w);
            float dvl = warp_sum(pv.x * pl.x + pv.y * pl.y + pv.z * pl.z + pv.w * pl.w);

            float sav = (sa + sv) / (dav + 0.5f);
            float sal = (sa + sl) / (dal + 0.5f);
            float svl = (sl + sv) / (dvl + 0.5f);
            float mx = fmaxf(sav, fmaxf(sal, svl));
            float e0 = __expf(sav - mx), e1 = __expf(sal - mx), e2 = __expf(svl - mx);
            float is = 1.0f / (e0 + e1 + e2);
            if (lane == 0) {
                float* sc = sm + OFF_SC + r * 16;
                sc[0] = e0 * is; sc[1] = e1 * is; sc[2] = e2 * is;
                sc[3] = sav; sc[4] = sal; sc[5] = svl;
                sc[6] = sa;  sc[7] = sv;  sc[8] = sl;
            }
        }
    }
    __syncthreads();

    // ===== gf GEMM1: [48 x 264] @ [264 x 64] with x-half dedup =====
    // pairs: p0=(a,v) p1=(a,l) p2=(v,l). Warps 0-3 (nt=wid): p0,p1 share fx(a)+bias.
    // Warps 4-7 (nt=wid-4): p2. H rows: p0->0-15, p1->16-31, p2->32-47.
    {
        const int nt = wid & 3;
        FragA af; FragB bf;
        if (wid < 4) {
            const float* xa = sm + 0 * (R * SA);   // a
            const float* yv = sm + 1 * (R * SA);   // v
            const float* yl = sm + 2 * (R * SA);   // l
            FragC fx; wmma::fill_fragment(fx, 0.0f);
#pragma unroll
            for (int kt = 0; kt < 16; ++kt) {
                load_bfrag(bf, TB_GF1 + kt * 4 + nt, lane);
                wmma::load_matrix_sync(af, xa + kt * 8, SA);
                wmma::mma_sync(fx, af, bf, fx);
            }
            load_bfrag(bf, TB_GF1 + 32 * 4 + nt, lane);     // bias tile
            wmma::load_matrix_sync(af, xa + 128, SA);
            wmma::mma_sync(fx, af, bf, fx);
            FragC acc0, acc1;
            copy_frag(acc0, fx); copy_frag(acc1, fx);
            FragA af1;
#pragma unroll
            for (int kt = 0; kt < 16; ++kt) {
                load_bfrag(bf, TB_GF1 + (16 + kt) * 4 + nt, lane);
                wmma::load_matrix_sync(af, yv + kt * 8, SA);
                wmma::load_matrix_sync(af1, yl + kt * 8, SA);
                wmma::mma_sync(acc0, af, bf, acc0);
                wmma::mma_sync(acc1, af1, bf, acc1);
            }
#pragma unroll
            for (int e = 0; e < acc0.num_elements; ++e) {
                float v0 = acc0.x[e];
                acc0.x[e] = rna((v0 >= 0.0f) ? v0 : 0.2f * v0);
                float v1 = acc1.x[e];
                acc1.x[e] = rna((v1 >= 0.0f) ? v1 : 0.2f * v1);
            }
            wmma::store_matrix_sync(sm + OFF_H + 0 * 16 * SH + nt * 16, acc0, SH, wmma::mem_row_major);
            wmma::store_matrix_sync(sm + OFF_H + 1 * 16 * SH + nt * 16, acc1, SH, wmma::mem_row_major);
        } else {
            const float* xv = sm + 1 * (R * SA);   // v
            const float* yl = sm + 2 * (R * SA);   // l
            FragC acc; wmma::fill_fragment(acc, 0.0f);
#pragma unroll
            for (int kt = 0; kt < 16; ++kt) {
                load_bfrag(bf, TB_GF1 + kt * 4 + nt, lane);
                wmma::load_matrix_sync(af, xv + kt * 8, SA);
                wmma::mma_sync(acc, af, bf, acc);
            }
            load_bfrag(bf, TB_GF1 + 32 * 4 + nt, lane);
            wmma::load_matrix_sync(af, xv + 128, SA);
            wmma::mma_sync(acc, af, bf, acc);
#pragma unroll
            for (int kt = 0; kt < 16; ++kt) {
                load_bfrag(bf, TB_GF1 + (16 + kt) * 4 + nt, lane);
                wmma::load_matrix_sync(af, yl + kt * 8, SA);
                wmma::mma_sync(acc, af, bf, acc);
            }
#pragma unroll
            for (int e = 0; e < acc.num_elements; ++e) {
                float v = acc.x[e];
                acc.x[e] = rna((v >= 0.0f) ? v : 0.2f * v);
            }
            wmma::store_matrix_sync(sm + OFF_H + 2 * 16 * SH + nt * 16, acc, SH, wmma::mem_row_major);
        }
    }
    __syncthreads();

    // ===== gf GEMM2: [48 x 72] @ [72 x 128]; tanh in fragment -> G0/G1/G2 =====
    {
        const int nt = wid;
        FragC acc[3];
#pragma unroll
        for (int i = 0; i < 3; ++i) wmma::fill_fragment(acc[i], 0.0f);
        FragA af; FragB bf;
#pragma unroll
        for (int kt = 0; kt < 9; ++kt) {
            load_bfrag(bf, TB_GF2 + kt * 8 + nt, lane);
#pragma unroll
            for (int i = 0; i < 3; ++i) {
                wmma::load_matrix_sync(af, sm + OFF_H + i * 16 * SH + kt * 8, SH);
                wmma::mma_sync(acc[i], af, bf, acc[i]);
            }
        }
#pragma unroll
        for (int i = 0; i < 3; ++i) {
#pragma unroll
            for (int e = 0; e < acc[i].num_elements; ++e)
                acc[i].x[e] = rna(tanh_fast(acc[i].x[e]));
            wmma::store_matrix_sync(sm + OFF_G0 + i * (R * SA) + nt * 16, acc[i], SA, wmma::mem_row_major);
        }
    }
    __syncthreads();

    // ============ Phase C: softmax(g) dots, n2, a_v/a_l/v_l, bimodal ============
    {
#pragma unroll
        for (int rr = 0; rr < 2; ++rr) {
            int r = wid * 2 + rr;
            float4 g0 = ((const float4*)(sm + OFF_A + 3 * R * SA + r * SA))[lane];
            float4 g1 = ((const float4*)(sm + OFF_A + 4 * R * SA + r * SA))[lane];
            float4 g2 = ((const float4*)(sm + OFF_A + 5 * R * SA + r * SA))[lane];
            float4 pa = ((const float4*)(sm + OFF_A + 0 * R * SA + r * SA))[lane];
            float4 pv = ((const float4*)(sm + OFF_A + 1 * R * SA + r * SA))[lane];
            float4 pl = ((const float4*)(sm + OFF_A + 2 * R * SA + r * SA))[lane];

            float m0 = warp_max(fmaxf(fmaxf(g0.x, g0.y), fmaxf(g0.z, g0.w)));
            float m1 = warp_max(fmaxf(fmaxf(g1.x, g1.y), fmaxf(g1.z, g1.w)));
            float m2 = warp_max(fmaxf(fmaxf(g2.x, g2.y), fmaxf(g2.z, g2.w)));
            float4 e0 = make_float4(__expf(g0.x - m0), __expf(g0.y - m0), __expf(g0.z - m0), __expf(g0.w - m0));
            float4 e1 = make_float4(__expf(g1.x - m1), __expf(g1.y - m1), __expf(g1.z - m1), __expf(g1.w - m1));
            float4 e2 = make_float4(__expf(g2.x - m2), __expf(g2.y - m2), __expf(g2.z - m2), __expf(g2.w - m2));
            float i0 = 1.0f / warp_sum(e0.x + e0.y + e0.z + e0.w);
            float i1 = 1.0f / warp_sum(e1.x + e1.y + e1.z + e1.w);
            float i2 = 1.0f / warp_sum(e2.x + e2.y + e2.z + e2.w);

            float d01 = warp_sum(e0.x * e1.x + e0.y * e1.y + e0.z * e1.z + e0.w * e1.w);
            float d02 = warp_sum(e0.x * e2.x + e0.y * e2.y + e0.z * e2.z + e0.w * e2.w);
            float d12 = warp_sum(e1.x * e2.x + e1.y * e2.y + e1.z * e2.z + e1.w * e2.w);
            float d0l = warp_sum(e0.x * pl.x + e0.y * pl.y + e0.z * pl.z + e0.w * pl.w);
            float d1v = warp_sum(e1.x * pv.x + e1.y * pv.y + e1.z * pv.z + e1.w * pv.w);
            float d2a = warp_sum(e2.x * pa.x + e2.y * pa.y + e2.z * pa.z + e2.w * pa.w);

            const float* sc = sm + OFF_SC + r * 16;
            float sav = sc[3], sal = sc[4], svl = sc[5];
            float sa = sc[6], sv = sc[7], sl = sc[8];
            float t0 = (sav + svl) / (d02 * i0 * i2 + 0.5f);
            float t1 = (sav + sal) / (d01 * i0 * i1 + 0.5f);
            float t2 = (sal + svl) / (d12 * i1 * i2 + 0.5f);
            float t3 = (sav + sl)  / (d0l * i0 + 0.5f);
            float t4 = (sal + sv)  / (d1v * i1 + 0.5f);
            float t5 = (sa  + svl) / (d2a * i2 + 0.5f);
            float mm = fmaxf(fmaxf(fmaxf(t0, t1), fmaxf(t2, t3)), fmaxf(t4, t5));
            float q0 = __expf(t0 - mm), q1 = __expf(t1 - mm), q2 = __expf(t2 - mm);
            float q3 = __expf(t3 - mm), q4 = __expf(t4 - mm), q5 = __expf(t5 - mm);
            float qi = 1.0f / (q0 + q1 + q2 + q3 + q4 + q5);
            if (lane == 0) {
                float* scw = sm + OFF_SC + r * 16;
                scw[9]  = q0 * qi; scw[10] = q1 * qi; scw[11] = q2 * qi;
                scw[12] = q3 * qi; scw[13] = q4 * qi; scw[14] = q5 * qi;
            }

            float n0 = sc[0], n1 = sc[1], n2v = sc[2];
            float4 av = make_float4(tanh_fast(n0 * g0.x), tanh_fast(n0 * g0.y), tanh_fast(n0 * g0.z), tanh_fast(n0 * g0.w));
            float4 al = make_float4(tanh_fast(n1 * g1.x), tanh_fast(n1 * g1.y), tanh_fast(n1 * g1.z), tanh_fast(n1 * g1.w));
            float4 vl = make_float4(tanh_fast(n2v * g2.x), tanh_fast(n2v * g2.y), tanh_fast(n2v * g2.z), tanh_fast(n2v * g2.w));
            ((float4*)(sm + OFF_A + 3 * R * SA + r * SA))[lane] = r4(av);
            ((float4*)(sm + OFF_A + 4 * R * SA + r * SA))[lane] = r4(al);
            ((float4*)(sm + OFF_A + 5 * R * SA + r * SA))[lane] = r4(vl);
            float4 bm = make_float4(av.x + al.x + vl.x, av.y + al.y + vl.y,
                                    av.z + al.z + vl.z, av.w + al.w + vl.w);
            ((float4*)(sm + OFF_FUS + r * SF + 128))[lane] = r4(bm);
        }
    }
    __syncthreads();

    // ===== gf2 GEMM1 (6 pairs, x-half dedup): [96 x 264] @ [264 x 64] =====
    // pairs: p0=(G0,G2) p1=(G0,G1) p2=(G2,G1) p3=(G0,L) p4=(G1,V) p5=(G2,A)
    // buffers: A=0 V=1 L=2 G0=3 G1=4 G2=5.  H rows: p_i -> rows i*16.
    // Warps 0-3 (nt): pairs {0,1,3} share fx(G0)+bias.
    // Warps 4-7 (nt): pairs {2,4,5}: fx2(G2)+bias (p2,p5), fx1(G1)+bias (p4).
    {
        const int nt = wid & 3;
        FragA af, af1, af2; FragB bf;
        if (wid < 4) {
            const float* x0 = sm + 3 * (R * SA);   // G0
            const float* y0 = sm + 5 * (R * SA);   // G2 (p0)
            const float* y1 = sm + 4 * (R * SA);   // G1 (p1)
            const float* y3 = sm + 2 * (R * SA);   // L  (p3)
            FragC fx; wmma::fill_fragment(fx, 0.0f);
#pragma unroll
            for (int kt = 0; kt < 16; ++kt) {
                load_bfrag(bf, TB_G21 + kt * 4 + nt, lane);
                wmma::load_matrix_sync(af, x0 + kt * 8, SA);
                wmma::mma_sync(fx, af, bf, fx);
            }
            load_bfrag(bf, TB_G21 + 32 * 4 + nt, lane);
            wmma::load_matrix_sync(af, x0 + 128, SA);
            wmma::mma_sync(fx, af, bf, fx);
            FragC acc0, acc1, acc3;
            copy_frag(acc0, fx); copy_frag(acc1, fx); copy_frag(acc3, fx);
#pragma unroll
            for (int kt = 0; kt < 16; ++kt) {
                load_bfrag(bf, TB_G21 + (16 + kt) * 4 + nt, lane);
                wmma::load_matrix_sync(af, y0 + kt * 8, SA);
                wmma::load_matrix_sync(af1, y1 + kt * 8, SA);
                wmma::load_matrix_sync(af2, y3 + kt * 8, SA);
                wmma::mma_sync(acc0, af, bf, acc0);
                wmma::mma_sync(acc1, af1, bf, acc1);
                wmma::mma_sync(acc3, af2, bf, acc3);
            }
#pragma unroll
            for (int e = 0; e < acc0.num_elements; ++e) {
                float v0 = acc0.x[e];
                acc0.x[e] = rna((v0 >= 0.0f) ? v0 : 0.2f * v0);
                float v1 = acc1.x[e];
                acc1.x[e] = rna((v1 >= 0.0f) ? v1 : 0.2f * v1);
                float v3 = acc3.x[e];
                acc3.x[e] = rna((v3 >= 0.0f) ? v3 : 0.2f * v3);
            }
            wmma::store_matrix_sync(sm + OFF_H + 0 * 16 * SH + nt * 16, acc0, SH, wmma::mem_row_major);
            wmma::store_matrix_sync(sm + OFF_H + 1 * 16 * SH + nt * 16, acc1, SH, wmma::mem_row_major);
            wmma::store_matrix_sync(sm + OFF_H + 3 * 16 * SH + nt * 16, acc3, SH, wmma::mem_row_major);
        } else {
            const float* xg2 = sm + 5 * (R * SA);  // G2
            const float* xg1 = sm + 4 * (R * SA);  // G1
            const float* y2 = sm + 4 * (R * SA);   // G1 (p2)
            const float* y4 = sm + 1 * (R * SA);   // V  (p4)
            const float* y5 = sm + 0 * (R * SA);   // A  (p5)
            FragC fx2, fx1;
            wmma::fill_fragment(fx2, 0.0f);
            wmma::fill_fragment(fx1, 0.0f);
#pragma unroll
            for (int kt = 0; kt < 16; ++kt) {
                load_bfrag(bf, TB_G21 + kt * 4 + nt, lane);
                wmma::load_matrix_sync(af, xg2 + kt * 8, SA);
                wmma::load_matrix_sync(af1, xg1 + kt * 8, SA);
                wmma::mma_sync(fx2, af, bf, fx2);
                wmma::mma_sync(fx1, af1, bf, fx1);
            }
            load_bfrag(bf, TB_G21 + 32 * 4 + nt, lane);
            wmma::load_matrix_sync(af, xg2 + 128, SA);
            wmma::load_matrix_sync(af1, xg1 + 128, SA);
            wmma::mma_sync(fx2, af, bf, fx2);
            wmma::mma_sync(fx1, af1, bf, fx1);
            FragC acc2, acc4, acc5;
            copy_frag(acc2, fx2); copy_frag(acc4, fx1); copy_frag(acc5, fx2);
#pragma unroll
            for (int kt = 0; kt < 16; ++kt) {
                load_bfrag(bf, TB_G21 + (16 + kt) * 4 + nt, lane);
                wmma::load_matrix_sync(af, y2 + kt * 8, SA);
                wmma::load_matrix_sync(af1, y4 + kt * 8, SA);
                wmma::load_matrix_sync(af2, y5 + kt * 8, SA);
                wmma::mma_sync(acc2, af, bf, acc2);
                wmma::mma_sync(acc4, af1, bf, acc4);
                wmma::mma_sync(acc5, af2, bf, acc5);
            }
#pragma unroll
            for (int e = 0; e < acc2.num_elements; ++e) {
                float v2 = acc2.x[e];
                acc2.x[e] = rna((v2 >= 0.0f) ? v2 : 0.2f * v2);
                float v4 = acc4.x[e];
                acc4.x[e] = rna((v4 >= 0.0f) ? v4 : 0.2f * v4);
                float v5 = acc5.x[e];
                acc5.x[e] = rna((v5 >= 0.0f) ? v5 : 0.2f * v5);
            }
            wmma::store_matrix_sync(sm + OFF_H + 2 * 16 * SH + nt * 16, acc2, SH, wmma::mem_row_major);
            wmma::store_matrix_sync(sm + OFF_H + 4 * 16 * SH + nt * 16, acc4, SH, wmma::mem_row_major);
            wmma::store_matrix_sync(sm + OFF_H + 5 * 16 * SH + nt * 16, acc5, SH, wmma::mem_row_major);
        }
    }
    __syncthreads();

    // ===== gf2 GEMM2: [96 x 72] @ [72 x 128] raw -> scratch (G0,G1,G2,A,V,L) =====
    {
        const int nt = wid;
        FragC acc[6];
#pragma unroll
        for (int i = 0; i < 6; ++i) wmma::fill_fragment(acc[i], 0.0f);
        FragA af; FragB bf;
#pragma unroll
        for (int kt = 0; kt < 9; ++kt) {
            load_bfrag(bf, TB_G22 + kt * 8 + nt, lane);
#pragma unroll
            for (int i = 0; i < 6; ++i) {
                wmma::load_matrix_sync(af, sm + OFF_H + i * 16 * SH + kt * 8, SH);
                wmma::mma_sync(acc[i], af, bf, acc[i]);
            }
        }
#pragma unroll
        for (int i = 0; i < 6; ++i) {
            int bidx = (i < 3) ? (3 + i) : (i - 3);
            wmma::store_matrix_sync(sm + bidx * (R * SA) + nt * 16, acc[i], SA, wmma::mem_row_major);
        }
    }
    __syncthreads();

    // ===== trimodal epilogue: fus[r][256+c] = sum_p tanh(n2[p]*tanh(raw_p)) =====
    for (int idx = tid; idx < 16 * 128; idx += NT) {
        int r = idx >> 7, c = idx & 127;
        const float* sc = sm + OFF_SC + r * 16 + 9;
        float s = 0.0f;
#pragma unroll
        for (int p = 0; p < 6; ++p) {
            int bidx = (p < 3) ? (3 + p) : (p - 3);
            s += tanh_fast(sc[p] * tanh_fast(sm[bidx * (R * SA) + r * SA + c]));
        }
        sm[OFF_FUS + r * SF + 256 + c] = rna(s);
    }
    __syncthreads();

    // ===== ll1: [16 x 392] @ [392 x 64], 2-way k-split, raw partials in H =====
    {
        const int part = wid >> 2, nt = wid & 3;
        FragC acc; wmma::fill_fragment(acc, 0.0f);
        FragA af; FragB bf;
        if (part == 0) {
#pragma unroll
            for (int kt = 0; kt < 25; ++kt) {
                load_bfrag(bf, TB_LL1 + kt * 4 + nt, lane);
                wmma::load_matrix_sync(af, sm + OFF_FUS + kt * 8, SF);
                wmma::mma_sync(acc, af, bf, acc);
            }
        } else {
#pragma unroll
            for (int kt = 25; kt < 49; ++kt) {
                load_bfrag(bf, TB_LL1 + kt * 4 + nt, lane);
                wmma::load_matrix_sync(af, sm + OFF_FUS + kt * 8, SF);
                wmma::mma_sync(acc, af, bf, acc);
            }
        }
        wmma::store_matrix_sync(sm + OFF_H + part * 16 * SH + nt * 16, acc, SH, wmma::mem_row_major);
    }
    __syncthreads();
    for (int idx = tid; idx < 16 * 64; idx += NT) {
        int r = idx >> 6, c = idx & 63;
        float v = sm[OFF_H + r * SH + c] + sm[OFF_H + (16 + r) * SH + c];
        sm[OFF_H2 + r * SH + c] = rna(tanh_fast(v));
    }
    __syncthreads();

    // ===== ll2: [16 x 72] @ [72 x 64]; tanh in fragment -> H rows 0..15 =====
    if (wid < 4) {
        const int nt = wid;
        FragC acc; wmma::fill_fragment(acc, 0.0f);
        FragA af; FragB bf;
#pragma unroll
        for (int kt = 0; kt < 9; ++kt) {
            load_bfrag(bf, TB_LL2 + kt * 4 + nt, lane);
            wmma::load_matrix_sync(af, sm + OFF_H2 + kt * 8, SH);
            wmma::mma_sync(acc, af, bf, acc);
        }
#pragma unroll
        for (int e = 0; e < acc.num_elements; ++e)
            acc.x[e] = rna(tanh_fast(acc.x[e]));
        wmma::store_matrix_sync(sm + OFF_H + nt * 16, acc, SH, wmma::mem_row_major);
    }
    __syncthreads();

    // ===== ll3: [16 x 72] @ [72 x 128]; accurate tanh in fragment -> gmem =====
    {
        const int nt = wid;
        FragC acc; wmma::fill_fragment(acc, 0.0f);
        FragA af; FragB bf;
#pragma unroll
        for (int kt = 0; kt < 9; ++kt) {
            load_bfrag(bf, TB_LL3 + kt * 8 + nt, lane);
            wmma::load_matrix_sync(af, sm + OFF_H + kt * 8, SH);
            wmma::mma_sync(acc, af, bf, acc);
        }
#pragma unroll
        for (int e = 0; e < acc.num_elements; ++e)
            acc.x[e] = tanhf(acc.x[e]);
        wmma::store_matrix_sync(out + (size_t)blockIdx.x * R * D + nt * 16, acc, D, wmma::mem_row_major);
    }
}

extern "C" void kernel_launch(void* const* d_in, const int* in_sizes, int n_in,
                              void* d_out, int out_size) {
    const float* Lm     = (const float*)d_in[0];
    const float* Am     = (const float*)d_in[1];
    const float* Vm     = (const float*)d_in[2];
    const float* att_w  = (const float*)d_in[3];
    const float* att_b  = (const float*)d_in[4];
    const float* gf_w1  = (const float*)d_in[5];
    const float* gf_b1  = (const float*)d_in[6];
    const float* gf_w2  = (const float*)d_in[7];
    const float* gf_b2  = (const float*)d_in[8];
    const float* gf2_w1 = (const float*)d_in[9];
    const float* gf2_b1 = (const float*)d_in[10];
    const float* gf2_w2 = (const float*)d_in[11];
    const float* gf2_b2 = (const float*)d_in[12];
    const float* ll_w1  = (const float*)d_in[13];
    const float* ll_b1  = (const float*)d_in[14];
    const float* ll_w2  = (const float*)d_in[15];
    const float* ll_b2  = (const float*)d_in[16];
    const float* ll_w3  = (const float*)d_in[17];
    const float* ll_b3  = (const float*)d_in[18];

    convert_weights<<<(N_TILES + 7) / 8, 256>>>(
        gf_w1, gf_b1, gf_w2, gf_b2, gf2_w1, gf2_b1, gf2_w2, gf2_b2,
        ll_w1, ll_b1, ll_w2, ll_b2, ll_w3, ll_b3);

    int nrows = in_sizes[0] / D;
    int grid = nrows / R;
    size_t smem = (size_t)SMEM_FLOATS * sizeof(float);
    cudaFuncSetAttribute(graphfusion_kernel,
                         cudaFuncAttributeMaxDynamicSharedMemorySize, (int)smem);
    graphfusion_kernel<<<grid, NT, smem>>>(Lm, Am, Vm, att_w, att_b, (float*)d_out);
}

// round 12
// speedup vs baseline: 7.2271x; 1.7989x over previous
#include <cuda_runtime.h>
#include <mma.h>
#include <cuda_fp16.h>
#include <math.h>

using namespace nvcuda;

namespace {
constexpr int D = 128;
constexpr int R = 16;            // rows per block
constexpr int NT = 256;          // 8 warps
// Strides in HALVES; word-stride %32 == 12 (conflict-heuristic carried from tf32 layout)
constexpr int SA = 152;          // activation: 128 data + const cols [128..144)
constexpr int SF = 408;          // fusion: 384 data + const [384..400)
constexpr int SH = 88;           // H: 64 data + const [64..80)
constexpr int RSA = R * SA;      // 2432 halves per activation buffer
// Half-region offsets (in halves)
constexpr int OFF_FUS = 6 * RSA;            // 14592
constexpr int OFF_H   = OFF_FUS + R * SF;   // 21120  [96][SH]
constexpr int OFF_H2  = OFF_H + 96 * SH;    // 29568  [16][SH]
constexpr int HALF_END = OFF_H2 + R * SH;   // 30976 halves = 61952 B
// Float-region offsets (in floats)
constexpr int OFF_AW   = HALF_END / 2;          // 15488  [128]
constexpr int OFF_SC   = OFF_AW + 128;          // 15616  [16][16]
constexpr int SHF  = 76;                        // ll1 float partial stride (76%32==12)
constexpr int OFF_LL1F = OFF_SC + R * 16;       // 15872  [32][SHF]
constexpr int SMEM_BYTES = (OFF_LL1F + 32 * SHF) * 4;   // 73216 B (x2 CTAs = 146432)

// Packed fp16 B-fragment tiles (16x16 each). Slot = 512 halves (1 KB).
constexpr int TSLOT = 512;
constexpr int TB_GF1 = 0;            // gf_w1 : kt 0..16, nt 0..3 -> 68
constexpr int TB_GF2 = 68;           // gf_w2 : kt 0..4,  nt 0..7 -> 40
constexpr int TB_G21 = 108;          // gf2_w1: 68
constexpr int TB_G22 = 176;          // gf2_w2: 40
constexpr int TB_LL1 = 216;          // ll_w1 : kt 0..24, nt 0..3 -> 100
constexpr int TB_LL2 = 316;          // ll_w2 : 20
constexpr int TB_LL3 = 336;          // ll_w3 : kt 0..4, nt 0..7 -> 40
constexpr int N_TILES = 376;
}

__device__ __half g_w[N_TILES * TSLOT];

__device__ __forceinline__ float warp_sum(float x) {
#pragma unroll
    for (int o = 16; o > 0; o >>= 1) x += __shfl_xor_sync(0xffffffffu, x, o);
    return x;
}
__device__ __forceinline__ float warp_max(float x) {
#pragma unroll
    for (int o = 16; o > 0; o >>= 1) x = fmaxf(x, __shfl_xor_sync(0xffffffffu, x, o));
    return x;
}
__device__ __forceinline__ float tanh_fast(float x) {
    float y;
    asm("tanh.approx.f32 %0, %1;" : "=f"(y) : "f"(x));
    return y;
}
// store/load 4 consecutive halves <-> float4
__device__ __forceinline__ void st_h4(__half* p, float a, float b, float c, float d) {
    __half2* q = (__half2*)p;
    q[0] = __floats2half2_rn(a, b);
    q[1] = __floats2half2_rn(c, d);
}
__device__ __forceinline__ float4 ld_h4(const __half* p) {
    const __half2* q = (const __half2*)p;
    float2 u = __half22float2(q[0]), v = __half22float2(q[1]);
    return make_float4(u.x, u.y, v.x, v.y);
}

typedef wmma::fragment<wmma::matrix_a, 16, 16, 16, __half, wmma::row_major> FragA;
typedef wmma::fragment<wmma::matrix_b, 16, 16, 16, __half, wmma::row_major> FragB;
typedef wmma::fragment<wmma::accumulator, 16, 16, 16, float> FragC;
typedef wmma::fragment<wmma::accumulator, 16, 16, 16, __half> FragH;

__device__ __forceinline__ void copy_frag(FragC& d, const FragC& s) {
#pragma unroll
    for (int e = 0; e < d.num_elements; ++e) d.x[e] = s.x[e];
}
// Load a pre-packed fp16 B fragment: coalesced 16B chunks per lane.
__device__ __forceinline__ void load_bfrag(FragB& bf, int tile, int lane) {
    const __half* p = g_w + tile * TSLOT + lane * bf.num_elements;
#pragma unroll
    for (int e = 0; e < bf.num_elements; e += 8) {
        uint4 q = __ldg((const uint4*)(p + e));
        const __half* hp = (const __half*)&q;
#pragma unroll
        for (int j = 0; j < 8; ++j) bf.x[e + j] = hp[j];
    }
}

// Convert: build canonical 16x16 fp16 B tile (weights + bias row + zero pad),
// run it through load_matrix_sync, store lane-register image packed.
__global__ void convert_weights(
    const float* __restrict__ gf_w1, const float* __restrict__ gf_b1,
    const float* __restrict__ gf_w2, const float* __restrict__ gf_b2,
    const float* __restrict__ gf2_w1, const float* __restrict__ gf2_b1,
    const float* __restrict__ gf2_w2, const float* __restrict__ gf2_b2,
    const float* __restrict__ ll_w1, const float* __restrict__ ll_b1,
    const float* __restrict__ ll_w2, const float* __restrict__ ll_b2,
    const float* __restrict__ ll_w3, const float* __restrict__ ll_b3)
{
    __shared__ __half tile[8][256];
    const int w = threadIdx.x >> 5, lane = threadIdx.x & 31;
    const int t = blockIdx.x * 8 + w;
    if (t >= N_TILES) return;   // warp-uniform

    int t2 = t;
    const float* wsrc; const float* bsrc; int nNT, rmax;
    if      (t2 < TB_GF2) { t2 -= TB_GF1; wsrc = gf_w1;  bsrc = gf_b1;  nNT = 4; rmax = 256; }
    else if (t2 < TB_G21) { t2 -= TB_GF2; wsrc = gf_w2;  bsrc = gf_b2;  nNT = 8; rmax = 64;  }
    else if (t2 < TB_G22) { t2 -= TB_G21; wsrc = gf2_w1; bsrc = gf2_b1; nNT = 4; rmax = 256; }
    else if (t2 < TB_LL1) { t2 -= TB_G22; wsrc = gf2_w2; bsrc = gf2_b2; nNT = 8; rmax = 64;  }
    else if (t2 < TB_LL2) { t2 -= TB_LL1; wsrc = ll_w1;  bsrc = ll_b1;  nNT = 4; rmax = 384; }
    else if (t2 < TB_LL3) { t2 -= TB_LL2; wsrc = ll_w2;  bsrc = ll_b2;  nNT = 4; rmax = 64;  }
    else                  { t2 -= TB_LL3; wsrc = ll_w3;  bsrc = ll_b3;  nNT = 8; rmax = 64;  }
    const int kt = t2 / nNT, nt = t2 % nNT;
    const int ncols = nNT * 16;

#pragma unroll
    for (int j = 0; j < 8; ++j) {
        int idx = lane * 8 + j;            // 0..255 = rr*16+cc
        int rr = idx >> 4, cc = idx & 15;
        int r = kt * 16 + rr, c = nt * 16 + cc;
        float v = 0.0f;
        if (r < rmax)       v = wsrc[r * ncols + c];
        else if (r == rmax) v = bsrc[c];
        tile[w][idx] = __float2half_rn(v);
    }
    __syncwarp();
    FragB bf;
    wmma::load_matrix_sync(bf, &tile[w][0], 16);
    __half* dst = g_w + t * TSLOT + lane * bf.num_elements;
#pragma unroll
    for (int e = 0; e < bf.num_elements; ++e) dst[e] = bf.x[e];
}

__global__ void __launch_bounds__(NT, 2)
graphfusion_kernel(
    const float* __restrict__ Lm, const float* __restrict__ Am, const float* __restrict__ Vm,
    const float* __restrict__ att_w, const float* __restrict__ att_b,
    float* __restrict__ out)
{
    extern __shared__ __align__(16) char smraw[];
    __half* smh = (__half*)smraw;
    float*  smf = (float*)smraw;
    const int tid  = threadIdx.x;
    const int lane = tid & 31;
    const int wid  = tid >> 5;   // 0..7

    // ---- init: att_w (float) + constant bias columns ([1,0,...,0] x16) ----
    if (tid < D) smf[OFF_AW + tid] = att_w[tid];
    for (int idx = tid; idx < 3584; idx += NT) {
        int addr, c;
        if (idx < 1536)      { int b = idx >> 8, rem = idx & 255; int r = rem >> 4; c = rem & 15;
                               addr = b * RSA + r * SA + 128 + c; }
        else if (idx < 1792) { int i = idx - 1536; int r = i >> 4; c = i & 15; addr = OFF_FUS + r * SF + 384 + c; }
        else if (idx < 3328) { int i = idx - 1792; int r = i >> 4; c = i & 15; addr = OFF_H  + r * SH + 64 + c; }
        else                 { int i = idx - 3328; int r = i >> 4; c = i & 15; addr = OFF_H2 + r * SH + 64 + c; }
        smh[addr] = __float2half((c == 0) ? 1.0f : 0.0f);
    }
    __syncthreads();
    const float attb = __ldg(att_b);

    // ================= Phase A: scalars + softmaxes + unimodal =================
    {
        float4 aw = ((const float4*)(smf + OFF_AW))[lane];
#pragma unroll
        for (int rr = 0; rr < 2; ++rr) {
            int r = wid * 2 + rr;
            size_t grow = (size_t)blockIdx.x * R + r;
            float4 a4 = ((const float4*)(Am + grow * D))[lane];
            float4 v4 = ((const float4*)(Vm + grow * D))[lane];
            float4 l4 = ((const float4*)(Lm + grow * D))[lane];

            float sa = tanh_fast(warp_sum(a4.x * aw.x + a4.y * aw.y + a4.z * aw.z + a4.w * aw.w) + attb);
            float sv = tanh_fast(warp_sum(v4.x * aw.x + v4.y * aw.y + v4.z * aw.z + v4.w * aw.w) + attb);
            float sl = tanh_fast(warp_sum(l4.x * aw.x + l4.y * aw.y + l4.z * aw.z + l4.w * aw.w) + attb);

            st_h4(smh + OFF_FUS + r * SF + lane * 4,
                  (sa * a4.x + sv * v4.x + sl * l4.x) * (1.0f / 3.0f),
                  (sa * a4.y + sv * v4.y + sl * l4.y) * (1.0f / 3.0f),
                  (sa * a4.z + sv * v4.z + sl * l4.z) * (1.0f / 3.0f),
                  (sa * a4.w + sv * v4.w + sl * l4.w) * (1.0f / 3.0f));

            float ma = warp_max(fmaxf(fmaxf(a4.x, a4.y), fmaxf(a4.z, a4.w)));
            float4 ea = make_float4(__expf(a4.x - ma), __expf(a4.y - ma), __expf(a4.z - ma), __expf(a4.w - ma));
            float ia = 1.0f / warp_sum(ea.x + ea.y + ea.z + ea.w);
            float4 pa = make_float4(ea.x * ia, ea.y * ia, ea.z * ia, ea.w * ia);

            float mv = warp_max(fmaxf(fmaxf(v4.x, v4.y), fmaxf(v4.z, v4.w)));
            float4 ev = make_float4(__expf(v4.x - mv), __expf(v4.y - mv), __expf(v4.z - mv), __expf(v4.w - mv));
            float iv = 1.0f / warp_sum(ev.x + ev.y + ev.z + ev.w);
            float4 pv = make_float4(ev.x * iv, ev.y * iv, ev.z * iv, ev.w * iv);

            float ml = warp_max(fmaxf(fmaxf(l4.x, l4.y), fmaxf(l4.z, l4.w)));
            float4 el = make_float4(__expf(l4.x - ml), __expf(l4.y - ml), __expf(l4.z - ml), __expf(l4.w - ml));
            float il = 1.0f / warp_sum(el.x + el.y + el.z + el.w);
            float4 pl = make_float4(el.x * il, el.y * il, el.z * il, el.w * il);

            st_h4(smh + 0 * RSA + r * SA + lane * 4, pa.x, pa.y, pa.z, pa.w);
            st_h4(smh + 1 * RSA + r * SA + lane * 4, pv.x, pv.y, pv.z, pv.w);
            st_h4(smh + 2 * RSA + r * SA + lane * 4, pl.x, pl.y, pl.z, pl.w);

            float dav = warp_sum(pa.x * pv.x + pa.y * pv.y + pa.z * pv.z + pa.w * pv.w);
            float dal = warp_sum(pa.x * pl.x + pa.y * pl.y + pa.z * pl.z + pa.w * pl.w);
            float dvl = warp_sum(pv.x * pl.x + pv.y * pl.y + pv.z * pl.z + pv.w * pl.w);

            float sav = (sa + sv) / (dav + 0.5f);
            float sal = (sa + sl) / (dal + 0.5f);
            float svl = (sl + sv) / (dvl + 0.5f);
            float mx = fmaxf(sav, fmaxf(sal, svl));
            float e0 = __expf(sav - mx), e1 = __expf(sal - mx), e2 = __expf(svl - mx);
            float is = 1.0f / (e0 + e1 + e2);
            if (lane == 0) {
                float* sc = smf + OFF_SC + r * 16;
                sc[0] = e0 * is; sc[1] = e1 * is; sc[2] = e2 * is;
                sc[3] = sav; sc[4] = sal; sc[5] = svl;
                sc[6] = sa;  sc[7] = sv;  sc[8] = sl;
            }
        }
    }
    __syncthreads();

    // ===== gf GEMM1: [48 x 272] @ [272 x 64], fp16 k16, x-half dedup =====
    // pairs: p0=(a,v) p1=(a,l) p2=(v,l). Warps 0-3 (nt): p0,p1 share fx(a)+bias.
    // Warps 4-7 (nt): p2. H rows: p0->0, p1->16, p2->32.
    {
        const int nt = wid & 3;
        FragA af, af1; FragB bf;
        if (wid < 4) {
            const __half* xa = smh + 0 * RSA;
            const __half* yv = smh + 1 * RSA;
            const __half* yl = smh + 2 * RSA;
            FragC fx; wmma::fill_fragment(fx, 0.0f);
#pragma unroll
            for (int kt = 0; kt < 8; ++kt) {
                load_bfrag(bf, TB_GF1 + kt * 4 + nt, lane);
                wmma::load_matrix_sync(af, xa + kt * 16, SA);
                wmma::mma_sync(fx, af, bf, fx);
            }
            load_bfrag(bf, TB_GF1 + 16 * 4 + nt, lane);   // bias tile
            wmma::load_matrix_sync(af, xa + 128, SA);
            wmma::mma_sync(fx, af, bf, fx);
            FragC acc0, acc1;
            copy_frag(acc0, fx); copy_frag(acc1, fx);
#pragma unroll
            for (int kt = 0; kt < 8; ++kt) {
                load_bfrag(bf, TB_GF1 + (8 + kt) * 4 + nt, lane);
                wmma::load_matrix_sync(af, yv + kt * 16, SA);
                wmma::load_matrix_sync(af1, yl + kt * 16, SA);
                wmma::mma_sync(acc0, af, bf, acc0);
                wmma::mma_sync(acc1, af1, bf, acc1);
            }
            FragH h0, h1;
#pragma unroll
            for (int e = 0; e < acc0.num_elements; ++e) {
                float v0 = acc0.x[e];
                h0.x[e] = __float2half((v0 >= 0.0f) ? v0 : 0.2f * v0);
                float v1 = acc1.x[e];
                h1.x[e] = __float2half((v1 >= 0.0f) ? v1 : 0.2f * v1);
            }
            wmma::store_matrix_sync(smh + OFF_H + 0 * 16 * SH + nt * 16, h0, SH, wmma::mem_row_major);
            wmma::store_matrix_sync(smh + OFF_H + 1 * 16 * SH + nt * 16, h1, SH, wmma::mem_row_major);
        } else {
            const __half* xv = smh + 1 * RSA;
            const __half* yl = smh + 2 * RSA;
            FragC acc; wmma::fill_fragment(acc, 0.0f);
#pragma unroll
            for (int kt = 0; kt < 8; ++kt) {
                load_bfrag(bf, TB_GF1 + kt * 4 + nt, lane);
                wmma::load_matrix_sync(af, xv + kt * 16, SA);
                wmma::mma_sync(acc, af, bf, acc);
            }
            load_bfrag(bf, TB_GF1 + 16 * 4 + nt, lane);
            wmma::load_matrix_sync(af, xv + 128, SA);
            wmma::mma_sync(acc, af, bf, acc);
#pragma unroll
            for (int kt = 0; kt < 8; ++kt) {
                load_bfrag(bf, TB_GF1 + (8 + kt) * 4 + nt, lane);
                wmma::load_matrix_sync(af, yl + kt * 16, SA);
                wmma::mma_sync(acc, af, bf, acc);
            }
            FragH h0;
#pragma unroll
            for (int e = 0; e < acc.num_elements; ++e) {
                float v = acc.x[e];
                h0.x[e] = __float2half((v >= 0.0f) ? v : 0.2f * v);
            }
            wmma::store_matrix_sync(smh + OFF_H + 2 * 16 * SH + nt * 16, h0, SH, wmma::mem_row_major);
        }
    }
    __syncthreads();

    // ===== gf GEMM2: [48 x 80] @ [80 x 128]; tanh -> G0/G1/G2 (half) =====
    {
        const int nt = wid;
        FragC acc[3];
#pragma unroll
        for (int i = 0; i < 3; ++i) wmma::fill_fragment(acc[i], 0.0f);
        FragA af; FragB bf;
#pragma unroll
        for (int kt = 0; kt < 5; ++kt) {
            load_bfrag(bf, TB_GF2 + kt * 8 + nt, lane);
            int aoff = (kt < 4) ? kt * 16 : 64;
#pragma unroll
            for (int i = 0; i < 3; ++i) {
                wmma::load_matrix_sync(af, smh + OFF_H + i * 16 * SH + aoff, SH);
                wmma::mma_sync(acc[i], af, bf, acc[i]);
            }
        }
#pragma unroll
        for (int i = 0; i < 3; ++i) {
            FragH hh;
#pragma unroll
            for (int e = 0; e < acc[i].num_elements; ++e)
                hh.x[e] = __float2half(tanh_fast(acc[i].x[e]));
            wmma::store_matrix_sync(smh + (3 + i) * RSA + nt * 16, hh, SA, wmma::mem_row_major);
        }
    }
    __syncthreads();

    // ============ Phase C: softmax(g) dots, n2, a_v/a_l/v_l, bimodal ============
    {
#pragma unroll
        for (int rr = 0; rr < 2; ++rr) {
            int r = wid * 2 + rr;
            float4 g0 = ld_h4(smh + 3 * RSA + r * SA + lane * 4);
            float4 g1 = ld_h4(smh + 4 * RSA + r * SA + lane * 4);
            float4 g2 = ld_h4(smh + 5 * RSA + r * SA + lane * 4);
            float4 pa = ld_h4(smh + 0 * RSA + r * SA + lane * 4);
            float4 pv = ld_h4(smh + 1 * RSA + r * SA + lane * 4);
            float4 pl = ld_h4(smh + 2 * RSA + r * SA + lane * 4);

            float m0 = warp_max(fmaxf(fmaxf(g0.x, g0.y), fmaxf(g0.z, g0.w)));
            float m1 = warp_max(fmaxf(fmaxf(g1.x, g1.y), fmaxf(g1.z, g1.w)));
            float m2 = warp_max(fmaxf(fmaxf(g2.x, g2.y), fmaxf(g2.z, g2.w)));
            float4 e0 = make_float4(__expf(g0.x - m0), __expf(g0.y - m0), __expf(g0.z - m0), __expf(g0.w - m0));
            float4 e1 = make_float4(__expf(g1.x - m1), __expf(g1.y - m1), __expf(g1.z - m1), __expf(g1.w - m1));
            float4 e2 = make_float4(__expf(g2.x - m2), __expf(g2.y - m2), __expf(g2.z - m2), __expf(g2.w - m2));
            float i0 = 1.0f / warp_sum(e0.x + e0.y + e0.z + e0.w);
            float i1 = 1.0f / warp_sum(e1.x + e1.y + e1.z + e1.w);
            float i2 = 1.0f / warp_sum(e2.x + e2.y + e2.z + e2.w);

            float d01 = warp_sum(e0.x * e1.x + e0.y * e1.y + e0.z * e1.z + e0.w * e1.w);
            float d02 = warp_sum(e0.x * e2.x + e0.y * e2.y + e0.z * e2.z + e0.w * e2.w);
            float d12 = warp_sum(e1.x * e2.x + e1.y * e2.y + e1.z * e2.z + e1.w * e2.w);
            float d0l = warp_sum(e0.x * pl.x + e0.y * pl.y + e0.z * pl.z + e0.w * pl.w);
            float d1v = warp_sum(e1.x * pv.x + e1.y * pv.y + e1.z * pv.z + e1.w * pv.w);
            float d2a = warp_sum(e2.x * pa.x + e2.y * pa.y + e2.z * pa.z + e2.w * pa.w);

            const float* sc = smf + OFF_SC + r * 16;
            float sav = sc[3], sal = sc[4], svl = sc[5];
            float sa = sc[6], sv = sc[7], sl = sc[8];
            float t0 = (sav + svl) / (d02 * i0 * i2 + 0.5f);
            float t1 = (sav + sal) / (d01 * i0 * i1 + 0.5f);
            float t2 = (sal + svl) / (d12 * i1 * i2 + 0.5f);
            float t3 = (sav + sl)  / (d0l * i0 + 0.5f);
            float t4 = (sal + sv)  / (d1v * i1 + 0.5f);
            float t5 = (sa  + svl) / (d2a * i2 + 0.5f);
            float mm = fmaxf(fmaxf(fmaxf(t0, t1), fmaxf(t2, t3)), fmaxf(t4, t5));
            float q0 = __expf(t0 - mm), q1 = __expf(t1 - mm), q2 = __expf(t2 - mm);
            float q3 = __expf(t3 - mm), q4 = __expf(t4 - mm), q5 = __expf(t5 - mm);
            float qi = 1.0f / (q0 + q1 + q2 + q3 + q4 + q5);
            if (lane == 0) {
                float* scw = smf + OFF_SC + r * 16;
                scw[9]  = q0 * qi; scw[10] = q1 * qi; scw[11] = q2 * qi;
                scw[12] = q3 * qi; scw[13] = q4 * qi; scw[14] = q5 * qi;
            }

            float n0 = sc[0], n1 = sc[1], n2v = sc[2];
            float4 av = make_float4(tanh_fast(n0 * g0.x), tanh_fast(n0 * g0.y), tanh_fast(n0 * g0.z), tanh_fast(n0 * g0.w));
            float4 al = make_float4(tanh_fast(n1 * g1.x), tanh_fast(n1 * g1.y), tanh_fast(n1 * g1.z), tanh_fast(n1 * g1.w));
            float4 vl = make_float4(tanh_fast(n2v * g2.x), tanh_fast(n2v * g2.y), tanh_fast(n2v * g2.z), tanh_fast(n2v * g2.w));
            st_h4(smh + 3 * RSA + r * SA + lane * 4, av.x, av.y, av.z, av.w);
            st_h4(smh + 4 * RSA + r * SA + lane * 4, al.x, al.y, al.z, al.w);
            st_h4(smh + 5 * RSA + r * SA + lane * 4, vl.x, vl.y, vl.z, vl.w);
            st_h4(smh + OFF_FUS + r * SF + 128 + lane * 4,
                  av.x + al.x + vl.x, av.y + al.y + vl.y,
                  av.z + al.z + vl.z, av.w + al.w + vl.w);
        }
    }
    __syncthreads();

    // ===== gf2 GEMM1 (6 pairs, x-half dedup): [96 x 272] @ [272 x 64] =====
    // pairs: p0=(G0,G2) p1=(G0,G1) p2=(G2,G1) p3=(G0,L) p4=(G1,V) p5=(G2,A)
    // buffers: A=0 V=1 L=2 G0=3 G1=4 G2=5. H rows: p_i -> i*16.
    {
        const int nt = wid & 3;
        FragA af, af1, af2; FragB bf;
        if (wid < 4) {
            const __half* x0 = smh + 3 * RSA;   // G0
            const __half* y0 = smh + 5 * RSA;   // G2 (p0)
            const __half* y1 = smh + 4 * RSA;   // G1 (p1)
            const __half* y3 = smh + 2 * RSA;   // L  (p3)
            FragC fx; wmma::fill_fragment(fx, 0.0f);
#pragma unroll
            for (int kt = 0; kt < 8; ++kt) {
                load_bfrag(bf, TB_G21 + kt * 4 + nt, lane);
                wmma::load_matrix_sync(af, x0 + kt * 16, SA);
                wmma::mma_sync(fx, af, bf, fx);
            }
            load_bfrag(bf, TB_G21 + 16 * 4 + nt, lane);
            wmma::load_matrix_sync(af, x0 + 128, SA);
            wmma::mma_sync(fx, af, bf, fx);
            FragC acc0, acc1, acc3;
            copy_frag(acc0, fx); copy_frag(acc1, fx); copy_frag(acc3, fx);
#pragma unroll
            for (int kt = 0; kt < 8; ++kt) {
                load_bfrag(bf, TB_G21 + (8 + kt) * 4 + nt, lane);
                wmma::load_matrix_sync(af, y0 + kt * 16, SA);
                wmma::load_matrix_sync(af1, y1 + kt * 16, SA);
                wmma::load_matrix_sync(af2, y3 + kt * 16, SA);
                wmma::mma_sync(acc0, af, bf, acc0);
                wmma::mma_sync(acc1, af1, bf, acc1);
                wmma::mma_sync(acc3, af2, bf, acc3);
            }
            FragH h0, h1, h3;
#pragma unroll
            for (int e = 0; e < acc0.num_elements; ++e) {
                float v0 = acc0.x[e];
                h0.x[e] = __float2half((v0 >= 0.0f) ? v0 : 0.2f * v0);
                float v1 = acc1.x[e];
                h1.x[e] = __float2half((v1 >= 0.0f) ? v1 : 0.2f * v1);
                float v3 = acc3.x[e];
                h3.x[e] = __float2half((v3 >= 0.0f) ? v3 : 0.2f * v3);
            }
            wmma::store_matrix_sync(smh + OFF_H + 0 * 16 * SH + nt * 16, h0, SH, wmma::mem_row_major);
            wmma::store_matrix_sync(smh + OFF_H + 1 * 16 * SH + nt * 16, h1, SH, wmma::mem_row_major);
            wmma::store_matrix_sync(smh + OFF_H + 3 * 16 * SH + nt * 16, h3, SH, wmma::mem_row_major);
        } else {
            const __half* xg2 = smh + 5 * RSA;  // G2
            const __half* xg1 = smh + 4 * RSA;  // G1
            const __half* y2 = smh + 4 * RSA;   // G1 (p2)
            const __half* y4 = smh + 1 * RSA;   // V  (p4)
            const __half* y5 = smh + 0 * RSA;   // A  (p5)
            FragC fx2, fx1;
            wmma::fill_fragment(fx2, 0.0f);
            wmma::fill_fragment(fx1, 0.0f);
#pragma unroll
            for (int kt = 0; kt < 8; ++kt) {
                load_bfrag(bf, TB_G21 + kt * 4 + nt, lane);
                wmma::load_matrix_sync(af, xg2 + kt * 16, SA);
                wmma::load_matrix_sync(af1, xg1 + kt * 16, SA);
                wmma::mma_sync(fx2, af, bf, fx2);
                wmma::mma_sync(fx1, af1, bf, fx1);
            }
            load_bfrag(bf, TB_G21 + 16 * 4 + nt, lane);
            wmma::load_matrix_sync(af, xg2 + 128, SA);
            wmma::load_matrix_sync(af1, xg1 + 128, SA);
            wmma::mma_sync(fx2, af, bf, fx2);
            wmma::mma_sync(fx1, af1, bf, fx1);
            FragC acc2, acc4, acc5;
            copy_frag(acc2, fx2); copy_frag(acc4, fx1); copy_frag(acc5, fx2);
#pragma unroll
            for (int kt = 0; kt < 8; ++kt) {
                load_bfrag(bf, TB_G21 + (8 + kt) * 4 + nt, lane);
                wmma::load_matrix_sync(af, y2 + kt * 16, SA);
                wmma::load_matrix_sync(af1, y4 + kt * 16, SA);
                wmma::load_matrix_sync(af2, y5 + kt * 16, SA);
                wmma::mma_sync(acc2, af, bf, acc2);
                wmma::mma_sync(acc4, af1, bf, acc4);
                wmma::mma_sync(acc5, af2, bf, acc5);
            }
            FragH h2, h4, h5;
#pragma unroll
            for (int e = 0; e < acc2.num_elements; ++e) {
                float v2 = acc2.x[e];
                h2.x[e] = __float2half((v2 >= 0.0f) ? v2 : 0.2f * v2);
                float v4 = acc4.x[e];
                h4.x[e] = __float2half((v4 >= 0.0f) ? v4 : 0.2f * v4);
                float v5 = acc5.x[e];
                h5.x[e] = __float2half((v5 >= 0.0f) ? v5 : 0.2f * v5);
            }
            wmma::store_matrix_sync(smh + OFF_H + 2 * 16 * SH + nt * 16, h2, SH, wmma::mem_row_major);
            wmma::store_matrix_sync(smh + OFF_H + 4 * 16 * SH + nt * 16, h4, SH, wmma::mem_row_major);
            wmma::store_matrix_sync(smh + OFF_H + 5 * 16 * SH + nt * 16, h5, SH, wmma::mem_row_major);
        }
    }
    __syncthreads();

    // ===== gf2 GEMM2: [96 x 80] @ [80 x 128] raw -> scratch (G0,G1,G2,A,V,L) =====
    {
        const int nt = wid;
        FragC acc[6];
#pragma unroll
        for (int i = 0; i < 6; ++i) wmma::fill_fragment(acc[i], 0.0f);
        FragA af; FragB bf;
#pragma unroll
        for (int kt = 0; kt < 5; ++kt) {
            load_bfrag(bf, TB_G22 + kt * 8 + nt, lane);
            int aoff = (kt < 4) ? kt * 16 : 64;
#pragma unroll
            for (int i = 0; i < 6; ++i) {
                wmma::load_matrix_sync(af, smh + OFF_H + i * 16 * SH + aoff, SH);
                wmma::mma_sync(acc[i], af, bf, acc[i]);
            }
        }
#pragma unroll
        for (int i = 0; i < 6; ++i) {
            int bidx = (i < 3) ? (3 + i) : (i - 3);
            FragH hh;
#pragma unroll
            for (int e = 0; e < acc[i].num_elements; ++e)
                hh.x[e] = __float2half(acc[i].x[e]);
            wmma::store_matrix_sync(smh + bidx * RSA + nt * 16, hh, SA, wmma::mem_row_major);
        }
    }
    __syncthreads();

    // ===== trimodal epilogue: fus[r][256+c] = sum_p tanh(n2[p]*tanh(raw_p)) =====
    for (int idx = tid; idx < 16 * 128; idx += NT) {
        int r = idx >> 7, c = idx & 127;
        const float* sc = smf + OFF_SC + r * 16 + 9;
        float s = 0.0f;
#pragma unroll
        for (int p = 0; p < 6; ++p) {
            int bidx = (p < 3) ? (3 + p) : (p - 3);
            s += tanh_fast(sc[p] * tanh_fast(__half2float(smh[bidx * RSA + r * SA + c])));
        }
        smh[OFF_FUS + r * SF + 256 + c] = __float2half(s);
    }
    __syncthreads();

    // ===== ll1: [16 x 400] @ [400 x 64], 2-way k-split, float partials =====
    {
        const int part = wid >> 2, nt = wid & 3;
        FragC acc; wmma::fill_fragment(acc, 0.0f);
        FragA af; FragB bf;
        if (part == 0) {
#pragma unroll
            for (int kt = 0; kt < 13; ++kt) {
                load_bfrag(bf, TB_LL1 + kt * 4 + nt, lane);
                wmma::load_matrix_sync(af, smh + OFF_FUS + kt * 16, SF);
                wmma::mma_sync(acc, af, bf, acc);
            }
        } else {
#pragma unroll
            for (int kt = 13; kt < 25; ++kt) {
                load_bfrag(bf, TB_LL1 + kt * 4 + nt, lane);
                int aoff = (kt < 24) ? kt * 16 : 384;
                wmma::load_matrix_sync(af, smh + OFF_FUS + aoff, SF);
                wmma::mma_sync(acc, af, bf, acc);
            }
        }
        wmma::store_matrix_sync(smf + OFF_LL1F + part * 16 * SHF + nt * 16, acc, SHF, wmma::mem_row_major);
    }
    __syncthreads();
    for (int idx = tid; idx < 16 * 64; idx += NT) {
        int r = idx >> 6, c = idx & 63;
        float v = smf[OFF_LL1F + r * SHF + c] + smf[OFF_LL1F + (16 + r) * SHF + c];
        smh[OFF_H2 + r * SH + c] = __float2half(tanh_fast(v));
    }
    __syncthreads();

    // ===== ll2: [16 x 80] @ [80 x 64]; tanh -> H rows 0..15 (half) =====
    if (wid < 4) {
        const int nt = wid;
        FragC acc; wmma::fill_fragment(acc, 0.0f);
        FragA af; FragB bf;
#pragma unroll
        for (int kt = 0; kt < 5; ++kt) {
            load_bfrag(bf, TB_LL2 + kt * 4 + nt, lane);
            int aoff = (kt < 4) ? kt * 16 : 64;
            wmma::load_matrix_sync(af, smh + OFF_H2 + aoff, SH);
            wmma::mma_sync(acc, af, bf, acc);
        }
        FragH hh;
#pragma unroll
        for (int e = 0; e < acc.num_elements; ++e)
            hh.x[e] = __float2half(tanh_fast(acc.x[e]));
        wmma::store_matrix_sync(smh + OFF_H + nt * 16, hh, SH, wmma::mem_row_major);
    }
    __syncthreads();

    // ===== ll3: [16 x 80] @ [80 x 128]; accurate tanh -> gmem (float) =====
    {
        const int nt = wid;
        FragC acc; wmma::fill_fragment(acc, 0.0f);
        FragA af; FragB bf;
#pragma unroll
        for (int kt = 0; kt < 5; ++kt) {
            load_bfrag(bf, TB_LL3 + kt * 8 + nt, lane);
            int aoff = (kt < 4) ? kt * 16 : 64;
            wmma::load_matrix_sync(af, smh + OFF_H + aoff, SH);
            wmma::mma_sync(acc, af, bf, acc);
        }
#pragma unroll
        for (int e = 0; e < acc.num_elements; ++e)
            acc.x[e] = tanhf(acc.x[e]);
        wmma::store_matrix_sync(out + (size_t)blockIdx.x * R * D + nt * 16, acc, D, wmma::mem_row_major);
    }
}

extern "C" void kernel_launch(void* const* d_in, const int* in_sizes, int n_in,
                              void* d_out, int out_size) {
    const float* Lm     = (const float*)d_in[0];
    const float* Am     = (const float*)d_in[1];
    const float* Vm     = (const float*)d_in[2];
    const float* att_w  = (const float*)d_in[3];
    const float* att_b  = (const float*)d_in[4];
    const float* gf_w1  = (const float*)d_in[5];
    const float* gf_b1  = (const float*)d_in[6];
    const float* gf_w2  = (const float*)d_in[7];
    const float* gf_b2  = (const float*)d_in[8];
    const float* gf2_w1 = (const float*)d_in[9];
    const float* gf2_b1 = (const float*)d_in[10];
    const float* gf2_w2 = (const float*)d_in[11];
    const float* gf2_b2 = (const float*)d_in[12];
    const float* ll_w1  = (const float*)d_in[13];
    const float* ll_b1  = (const float*)d_in[14];
    const float* ll_w2  = (const float*)d_in[15];
    const float* ll_b2  = (const float*)d_in[16];
    const float* ll_w3  = (const float*)d_in[17];
    const float* ll_b3  = (const float*)d_in[18];

    convert_weights<<<(N_TILES + 7) / 8, 256>>>(
        gf_w1, gf_b1, gf_w2, gf_b2, gf2_w1, gf2_b1, gf2_w2, gf2_b2,
        ll_w1, ll_b1, ll_w2, ll_b2, ll_w3, ll_b3);

    int nrows = in_sizes[0] / D;
    int grid = nrows / R;
    cudaFuncSetAttribute(graphfusion_kernel,
                         cudaFuncAttributeMaxDynamicSharedMemorySize, SMEM_BYTES);
    graphfusion_kernel<<<grid, NT, SMEM_BYTES>>>(Lm, Am, Vm, att_w, att_b, (float*)d_out);
}

// round 13
// speedup vs baseline: 7.6668x; 1.0608x over previous
#include <cuda_runtime.h>
#include <mma.h>
#include <cuda_fp16.h>
#include <math.h>

using namespace nvcuda;

namespace {
constexpr int D = 128;
constexpr int R = 16;            // rows per block
constexpr int NT = 256;          // 8 warps
// Strides in HALVES; word-stride %32 == 12
constexpr int SA = 152;          // activation: 128 data + const cols [128..144)
constexpr int SF = 408;          // fusion: 384 data + const [384..400)
constexpr int SH = 88;           // H: 64 data + const [64..80)
constexpr int RSA = R * SA;      // 2432 halves per activation buffer
constexpr int OFF_FUS = 6 * RSA;            // 14592
constexpr int OFF_H   = OFF_FUS + R * SF;   // 21120  [96][SH]
constexpr int OFF_H2  = OFF_H + 96 * SH;    // 29568  [16][SH]
constexpr int HALF_END = OFF_H2 + R * SH;   // 30976 halves
constexpr int OFF_AW   = HALF_END / 2;          // floats
constexpr int OFF_SC   = OFF_AW + 128;
constexpr int SHF  = 76;
constexpr int OFF_LL1F = OFF_SC + R * 16;
constexpr int SMEM_BYTES = (OFF_LL1F + 32 * SHF) * 4;   // 73216 B

// Packed fp16 B-fragment tiles (16x16). Slot = 512 halves (1 KB).
constexpr int TSLOT = 512;
constexpr int TB_GF1 = 0;
constexpr int TB_GF2 = 68;
constexpr int TB_G21 = 108;
constexpr int TB_G22 = 176;
constexpr int TB_LL1 = 216;
constexpr int TB_LL2 = 316;
constexpr int TB_LL3 = 336;
constexpr int N_TILES = 376;
}

__device__ __half g_w[N_TILES * TSLOT];

__device__ __forceinline__ float warp_sum(float x) {
#pragma unroll
    for (int o = 16; o > 0; o >>= 1) x += __shfl_xor_sync(0xffffffffu, x, o);
    return x;
}
__device__ __forceinline__ float warp_max(float x) {
#pragma unroll
    for (int o = 16; o > 0; o >>= 1) x = fmaxf(x, __shfl_xor_sync(0xffffffffu, x, o));
    return x;
}
__device__ __forceinline__ float tanh_fast(float x) {
    float y;
    asm("tanh.approx.f32 %0, %1;" : "=f"(y) : "f"(x));
    return y;
}
__device__ __forceinline__ void st_h4(__half* p, float a, float b, float c, float d) {
    __half2* q = (__half2*)p;
    q[0] = __floats2half2_rn(a, b);
    q[1] = __floats2half2_rn(c, d);
}
__device__ __forceinline__ float4 ld_h4(const __half* p) {
    const __half2* q = (const __half2*)p;
    float2 u = __half22float2(q[0]), v = __half22float2(q[1]);
    return make_float4(u.x, u.y, v.x, v.y);
}

typedef wmma::fragment<wmma::matrix_a, 16, 16, 16, __half, wmma::row_major> FragA;
typedef wmma::fragment<wmma::matrix_b, 16, 16, 16, __half, wmma::row_major> FragB;
typedef wmma::fragment<wmma::accumulator, 16, 16, 16, float> FragC;
typedef wmma::fragment<wmma::accumulator, 16, 16, 16, __half> FragH;

__device__ __forceinline__ void copy_frag(FragC& d, const FragC& s) {
#pragma unroll
    for (int e = 0; e < d.num_elements; ++e) d.x[e] = s.x[e];
}
__device__ __forceinline__ void load_bfrag(FragB& bf, int tile, int lane) {
    const __half* p = g_w + tile * TSLOT + lane * bf.num_elements;
#pragma unroll
    for (int e = 0; e < bf.num_elements; e += 8) {
        uint4 q = __ldg((const uint4*)(p + e));
        const __half* hp = (const __half*)&q;
#pragma unroll
        for (int j = 0; j < 8; ++j) bf.x[e + j] = hp[j];
    }
}

__global__ void convert_weights(
    const float* __restrict__ gf_w1, const float* __restrict__ gf_b1,
    const float* __restrict__ gf_w2, const float* __restrict__ gf_b2,
    const float* __restrict__ gf2_w1, const float* __restrict__ gf2_b1,
    const float* __restrict__ gf2_w2, const float* __restrict__ gf2_b2,
    const float* __restrict__ ll_w1, const float* __restrict__ ll_b1,
    const float* __restrict__ ll_w2, const float* __restrict__ ll_b2,
    const float* __restrict__ ll_w3, const float* __restrict__ ll_b3)
{
    __shared__ __half tile[8][256];
    const int w = threadIdx.x >> 5, lane = threadIdx.x & 31;
    const int t = blockIdx.x * 8 + w;
    if (t >= N_TILES) return;   // warp-uniform

    int t2 = t;
    const float* wsrc; const float* bsrc; int nNT, rmax;
    if      (t2 < TB_GF2) { t2 -= TB_GF1; wsrc = gf_w1;  bsrc = gf_b1;  nNT = 4; rmax = 256; }
    else if (t2 < TB_G21) { t2 -= TB_GF2; wsrc = gf_w2;  bsrc = gf_b2;  nNT = 8; rmax = 64;  }
    else if (t2 < TB_G22) { t2 -= TB_G21; wsrc = gf2_w1; bsrc = gf2_b1; nNT = 4; rmax = 256; }
    else if (t2 < TB_LL1) { t2 -= TB_G22; wsrc = gf2_w2; bsrc = gf2_b2; nNT = 8; rmax = 64;  }
    else if (t2 < TB_LL2) { t2 -= TB_LL1; wsrc = ll_w1;  bsrc = ll_b1;  nNT = 4; rmax = 384; }
    else if (t2 < TB_LL3) { t2 -= TB_LL2; wsrc = ll_w2;  bsrc = ll_b2;  nNT = 4; rmax = 64;  }
    else                  { t2 -= TB_LL3; wsrc = ll_w3;  bsrc = ll_b3;  nNT = 8; rmax = 64;  }
    const int kt = t2 / nNT, nt = t2 % nNT;
    const int ncols = nNT * 16;

#pragma unroll
    for (int j = 0; j < 8; ++j) {
        int idx = lane * 8 + j;
        int rr = idx >> 4, cc = idx & 15;
        int r = kt * 16 + rr, c = nt * 16 + cc;
        float v = 0.0f;
        if (r < rmax)       v = wsrc[r * ncols + c];
        else if (r == rmax) v = bsrc[c];
        tile[w][idx] = __float2half_rn(v);
    }
    __syncwarp();
    FragB bf;
    wmma::load_matrix_sync(bf, &tile[w][0], 16);
    __half* dst = g_w + t * TSLOT + lane * bf.num_elements;
#pragma unroll
    for (int e = 0; e < bf.num_elements; ++e) dst[e] = bf.x[e];
}

__global__ void __launch_bounds__(NT, 2)
graphfusion_kernel(
    const float* __restrict__ Lm, const float* __restrict__ Am, const float* __restrict__ Vm,
    const float* __restrict__ att_w, const float* __restrict__ att_b,
    float* __restrict__ out)
{
    extern __shared__ __align__(16) char smraw[];
    __half* smh = (__half*)smraw;
    float*  smf = (float*)smraw;
    const int tid  = threadIdx.x;
    const int lane = tid & 31;
    const int wid  = tid >> 5;   // 0..7

    // ---- init: att_w + constant bias columns, vectorized (16-half groups) ----
    if (tid < D) smf[OFF_AW + tid] = att_w[tid];
    if (tid < 224) {
        int g = tid, addr;
        if (g < 96)       { int b = g >> 4, r = g & 15; addr = b * RSA + r * SA + 128; }
        else if (g < 112) { int r = g - 96;  addr = OFF_FUS + r * SF + 384; }
        else if (g < 208) { int r = g - 112; addr = OFF_H  + r * SH + 64; }
        else              { int r = g - 208; addr = OFF_H2 + r * SH + 64; }
        uint4 z0 = make_uint4(0x00003c00u, 0u, 0u, 0u);   // halves [1.0, 0 x7]
        uint4 z1 = make_uint4(0u, 0u, 0u, 0u);
        ((uint4*)(smh + addr))[0] = z0;
        ((uint4*)(smh + addr))[1] = z1;
    }
    __syncthreads();
    const float attb = __ldg(att_b);

    // ================= Phase A: scalars + softmaxes + unimodal =================
    {
        float4 aw = ((const float4*)(smf + OFF_AW))[lane];
#pragma unroll
        for (int rr = 0; rr < 2; ++rr) {
            int r = wid * 2 + rr;
            size_t grow = (size_t)blockIdx.x * R + r;
            float4 a4 = ((const float4*)(Am + grow * D))[lane];
            float4 v4 = ((const float4*)(Vm + grow * D))[lane];
            float4 l4 = ((const float4*)(Lm + grow * D))[lane];

            float sa = tanh_fast(warp_sum(a4.x * aw.x + a4.y * aw.y + a4.z * aw.z + a4.w * aw.w) + attb);
            float sv = tanh_fast(warp_sum(v4.x * aw.x + v4.y * aw.y + v4.z * aw.z + v4.w * aw.w) + attb);
            float sl = tanh_fast(warp_sum(l4.x * aw.x + l4.y * aw.y + l4.z * aw.z + l4.w * aw.w) + attb);

            st_h4(smh + OFF_FUS + r * SF + lane * 4,
                  (sa * a4.x + sv * v4.x + sl * l4.x) * (1.0f / 3.0f),
                  (sa * a4.y + sv * v4.y + sl * l4.y) * (1.0f / 3.0f),
                  (sa * a4.z + sv * v4.z + sl * l4.z) * (1.0f / 3.0f),
                  (sa * a4.w + sv * v4.w + sl * l4.w) * (1.0f / 3.0f));

            float ma = warp_max(fmaxf(fmaxf(a4.x, a4.y), fmaxf(a4.z, a4.w)));
            float4 ea = make_float4(__expf(a4.x - ma), __expf(a4.y - ma), __expf(a4.z - ma), __expf(a4.w - ma));
            float ia = 1.0f / warp_sum(ea.x + ea.y + ea.z + ea.w);
            float4 pa = make_float4(ea.x * ia, ea.y * ia, ea.z * ia, ea.w * ia);

            float mv = warp_max(fmaxf(fmaxf(v4.x, v4.y), fmaxf(v4.z, v4.w)));
            float4 ev = make_float4(__expf(v4.x - mv), __expf(v4.y - mv), __expf(v4.z - mv), __expf(v4.w - mv));
            float iv = 1.0f / warp_sum(ev.x + ev.y + ev.z + ev.w);
            float4 pv = make_float4(ev.x * iv, ev.y * iv, ev.z * iv, ev.w * iv);

            float ml = warp_max(fmaxf(fmaxf(l4.x, l4.y), fmaxf(l4.z, l4.w)));
            float4 el = make_float4(__expf(l4.x - ml), __expf(l4.y - ml), __expf(l4.z - ml), __expf(l4.w - ml));
            float il = 1.0f / warp_sum(el.x + el.y + el.z + el.w);
            float4 pl = make_float4(el.x * il, el.y * il, el.z * il, el.w * il);

            st_h4(smh + 0 * RSA + r * SA + lane * 4, pa.x, pa.y, pa.z, pa.w);
            st_h4(smh + 1 * RSA + r * SA + lane * 4, pv.x, pv.y, pv.z, pv.w);
            st_h4(smh + 2 * RSA + r * SA + lane * 4, pl.x, pl.y, pl.z, pl.w);

            float dav = warp_sum(pa.x * pv.x + pa.y * pv.y + pa.z * pv.z + pa.w * pv.w);
            float dal = warp_sum(pa.x * pl.x + pa.y * pl.y + pa.z * pl.z + pa.w * pl.w);
            float dvl = warp_sum(pv.x * pl.x + pv.y * pl.y + pv.z * pl.z + pv.w * pl.w);

            float sav = (sa + sv) / (dav + 0.5f);
            float sal = (sa + sl) / (dal + 0.5f);
            float svl = (sl + sv) / (dvl + 0.5f);
            float mx = fmaxf(sav, fmaxf(sal, svl));
            float e0 = __expf(sav - mx), e1 = __expf(sal - mx), e2 = __expf(svl - mx);
            float is = 1.0f / (e0 + e1 + e2);
            if (lane == 0) {
                float* sc = smf + OFF_SC + r * 16;
                sc[0] = e0 * is; sc[1] = e1 * is; sc[2] = e2 * is;
                sc[3] = sav; sc[4] = sal; sc[5] = svl;
                sc[6] = sa;  sc[7] = sv;  sc[8] = sl;
            }
        }
    }
    __syncthreads();

    // ===== gf GEMM1: [48 x 272] @ [272 x 64], fp16 k16, x-half dedup =====
    {
        const int nt = wid & 3;
        FragA af, af1; FragB bf;
        if (wid < 4) {
            const __half* xa = smh + 0 * RSA;
            const __half* yv = smh + 1 * RSA;
            const __half* yl = smh + 2 * RSA;
            FragC fx; wmma::fill_fragment(fx, 0.0f);
#pragma unroll
            for (int kt = 0; kt < 8; ++kt) {
                load_bfrag(bf, TB_GF1 + kt * 4 + nt, lane);
                wmma::load_matrix_sync(af, xa + kt * 16, SA);
                wmma::mma_sync(fx, af, bf, fx);
            }
            load_bfrag(bf, TB_GF1 + 16 * 4 + nt, lane);
            wmma::load_matrix_sync(af, xa + 128, SA);
            wmma::mma_sync(fx, af, bf, fx);
            FragC acc0, acc1;
            copy_frag(acc0, fx); copy_frag(acc1, fx);
#pragma unroll
            for (int kt = 0; kt < 8; ++kt) {
                load_bfrag(bf, TB_GF1 + (8 + kt) * 4 + nt, lane);
                wmma::load_matrix_sync(af, yv + kt * 16, SA);
                wmma::load_matrix_sync(af1, yl + kt * 16, SA);
                wmma::mma_sync(acc0, af, bf, acc0);
                wmma::mma_sync(acc1, af1, bf, acc1);
            }
            FragH h0, h1;
#pragma unroll
            for (int e = 0; e < acc0.num_elements; ++e) {
                float v0 = acc0.x[e];
                h0.x[e] = __float2half((v0 >= 0.0f) ? v0 : 0.2f * v0);
                float v1 = acc1.x[e];
                h1.x[e] = __float2half((v1 >= 0.0f) ? v1 : 0.2f * v1);
            }
            wmma::store_matrix_sync(smh + OFF_H + 0 * 16 * SH + nt * 16, h0, SH, wmma::mem_row_major);
            wmma::store_matrix_sync(smh + OFF_H + 1 * 16 * SH + nt * 16, h1, SH, wmma::mem_row_major);
        } else {
            const __half* xv = smh + 1 * RSA;
            const __half* yl = smh + 2 * RSA;
            FragC acc; wmma::fill_fragment(acc, 0.0f);
#pragma unroll
            for (int kt = 0; kt < 8; ++kt) {
                load_bfrag(bf, TB_GF1 + kt * 4 + nt, lane);
                wmma::load_matrix_sync(af, xv + kt * 16, SA);
                wmma::mma_sync(acc, af, bf, acc);
            }
            load_bfrag(bf, TB_GF1 + 16 * 4 + nt, lane);
            wmma::load_matrix_sync(af, xv + 128, SA);
            wmma::mma_sync(acc, af, bf, acc);
#pragma unroll
            for (int kt = 0; kt < 8; ++kt) {
                load_bfrag(bf, TB_GF1 + (8 + kt) * 4 + nt, lane);
                wmma::load_matrix_sync(af, yl + kt * 16, SA);
                wmma::mma_sync(acc, af, bf, acc);
            }
            FragH h0;
#pragma unroll
            for (int e = 0; e < acc.num_elements; ++e) {
                float v = acc.x[e];
                h0.x[e] = __float2half((v >= 0.0f) ? v : 0.2f * v);
            }
            wmma::store_matrix_sync(smh + OFF_H + 2 * 16 * SH + nt * 16, h0, SH, wmma::mem_row_major);
        }
    }
    __syncthreads();

    // ===== gf GEMM2: [48 x 80] @ [80 x 128]; tanh -> G0/G1/G2 (half) =====
    {
        const int nt = wid;
        FragC acc[3];
#pragma unroll
        for (int i = 0; i < 3; ++i) wmma::fill_fragment(acc[i], 0.0f);
        FragA af; FragB bf;
#pragma unroll
        for (int kt = 0; kt < 5; ++kt) {
            load_bfrag(bf, TB_GF2 + kt * 8 + nt, lane);
            int aoff = (kt < 4) ? kt * 16 : 64;
#pragma unroll
            for (int i = 0; i < 3; ++i) {
                wmma::load_matrix_sync(af, smh + OFF_H + i * 16 * SH + aoff, SH);
                wmma::mma_sync(acc[i], af, bf, acc[i]);
            }
        }
#pragma unroll
        for (int i = 0; i < 3; ++i) {
            FragH hh;
#pragma unroll
            for (int e = 0; e < acc[i].num_elements; ++e)
                hh.x[e] = __float2half(tanh_fast(acc[i].x[e]));
            wmma::store_matrix_sync(smh + (3 + i) * RSA + nt * 16, hh, SA, wmma::mem_row_major);
        }
    }
    __syncthreads();

    // ============ Phase C: softmax(g) dots, n2, a_v/a_l/v_l, bimodal ============
    {
#pragma unroll
        for (int rr = 0; rr < 2; ++rr) {
            int r = wid * 2 + rr;
            float4 g0 = ld_h4(smh + 3 * RSA + r * SA + lane * 4);
            float4 g1 = ld_h4(smh + 4 * RSA + r * SA + lane * 4);
            float4 g2 = ld_h4(smh + 5 * RSA + r * SA + lane * 4);
            float4 pa = ld_h4(smh + 0 * RSA + r * SA + lane * 4);
            float4 pv = ld_h4(smh + 1 * RSA + r * SA + lane * 4);
            float4 pl = ld_h4(smh + 2 * RSA + r * SA + lane * 4);

            float m0 = warp_max(fmaxf(fmaxf(g0.x, g0.y), fmaxf(g0.z, g0.w)));
            float m1 = warp_max(fmaxf(fmaxf(g1.x, g1.y), fmaxf(g1.z, g1.w)));
            float m2 = warp_max(fmaxf(fmaxf(g2.x, g2.y), fmaxf(g2.z, g2.w)));
            float4 e0 = make_float4(__expf(g0.x - m0), __expf(g0.y - m0), __expf(g0.z - m0), __expf(g0.w - m0));
            float4 e1 = make_float4(__expf(g1.x - m1), __expf(g1.y - m1), __expf(g1.z - m1), __expf(g1.w - m1));
            float4 e2 = make_float4(__expf(g2.x - m2), __expf(g2.y - m2), __expf(g2.z - m2), __expf(g2.w - m2));
            float i0 = 1.0f / warp_sum(e0.x + e0.y + e0.z + e0.w);
            float i1 = 1.0f / warp_sum(e1.x + e1.y + e1.z + e1.w);
            float i2 = 1.0f / warp_sum(e2.x + e2.y + e2.z + e2.w);

            float d01 = warp_sum(e0.x * e1.x + e0.y * e1.y + e0.z * e1.z + e0.w * e1.w);
            float d02 = warp_sum(e0.x * e2.x + e0.y * e2.y + e0.z * e2.z + e0.w * e2.w);
            float d12 = warp_sum(e1.x * e2.x + e1.y * e2.y + e1.z * e2.z + e1.w * e2.w);
            float d0l = warp_sum(e0.x * pl.x + e0.y * pl.y + e0.z * pl.z + e0.w * pl.w);
            float d1v = warp_sum(e1.x * pv.x + e1.y * pv.y + e1.z * pv.z + e1.w * pv.w);
            float d2a = warp_sum(e2.x * pa.x + e2.y * pa.y + e2.z * pa.z + e2.w * pa.w);

            const float* sc = smf + OFF_SC + r * 16;
            float sav = sc[3], sal = sc[4], svl = sc[5];
            float sa = sc[6], sv = sc[7], sl = sc[8];
            float t0 = (sav + svl) / (d02 * i0 * i2 + 0.5f);
            float t1 = (sav + sal) / (d01 * i0 * i1 + 0.5f);
            float t2 = (sal + svl) / (d12 * i1 * i2 + 0.5f);
            float t3 = (sav + sl)  / (d0l * i0 + 0.5f);
            float t4 = (sal + sv)  / (d1v * i1 + 0.5f);
            float t5 = (sa  + svl) / (d2a * i2 + 0.5f);
            float mm = fmaxf(fmaxf(fmaxf(t0, t1), fmaxf(t2, t3)), fmaxf(t4, t5));
            float q0 = __expf(t0 - mm), q1 = __expf(t1 - mm), q2 = __expf(t2 - mm);
            float q3 = __expf(t3 - mm), q4 = __expf(t4 - mm), q5 = __expf(t5 - mm);
            float qi = 1.0f / (q0 + q1 + q2 + q3 + q4 + q5);
            if (lane == 0) {
                float* scw = smf + OFF_SC + r * 16;
                scw[9]  = q0 * qi; scw[10] = q1 * qi; scw[11] = q2 * qi;
                scw[12] = q3 * qi; scw[13] = q4 * qi; scw[14] = q5 * qi;
            }

            float n0 = sc[0], n1 = sc[1], n2v = sc[2];
            float4 av = make_float4(tanh_fast(n0 * g0.x), tanh_fast(n0 * g0.y), tanh_fast(n0 * g0.z), tanh_fast(n0 * g0.w));
            float4 al = make_float4(tanh_fast(n1 * g1.x), tanh_fast(n1 * g1.y), tanh_fast(n1 * g1.z), tanh_fast(n1 * g1.w));
            float4 vl = make_float4(tanh_fast(n2v * g2.x), tanh_fast(n2v * g2.y), tanh_fast(n2v * g2.z), tanh_fast(n2v * g2.w));
            st_h4(smh + 3 * RSA + r * SA + lane * 4, av.x, av.y, av.z, av.w);
            st_h4(smh + 4 * RSA + r * SA + lane * 4, al.x, al.y, al.z, al.w);
            st_h4(smh + 5 * RSA + r * SA + lane * 4, vl.x, vl.y, vl.z, vl.w);
            st_h4(smh + OFF_FUS + r * SF + 128 + lane * 4,
                  av.x + al.x + vl.x, av.y + al.y + vl.y,
                  av.z + al.z + vl.z, av.w + al.w + vl.w);
        }
    }
    __syncthreads();

    // ===== gf2 GEMM1 (6 pairs, x-half dedup): [96 x 272] @ [272 x 64] =====
    {
        const int nt = wid & 3;
        FragA af, af1, af2; FragB bf;
        if (wid < 4) {
            const __half* x0 = smh + 3 * RSA;   // G0
            const __half* y0 = smh + 5 * RSA;   // G2 (p0)
            const __half* y1 = smh + 4 * RSA;   // G1 (p1)
            const __half* y3 = smh + 2 * RSA;   // L  (p3)
            FragC fx; wmma::fill_fragment(fx, 0.0f);
#pragma unroll
            for (int kt = 0; kt < 8; ++kt) {
                load_bfrag(bf, TB_G21 + kt * 4 + nt, lane);
                wmma::load_matrix_sync(af, x0 + kt * 16, SA);
                wmma::mma_sync(fx, af, bf, fx);
            }
            load_bfrag(bf, TB_G21 + 16 * 4 + nt, lane);
            wmma::load_matrix_sync(af, x0 + 128, SA);
            wmma::mma_sync(fx, af, bf, fx);
            FragC acc0, acc1, acc3;
            copy_frag(acc0, fx); copy_frag(acc1, fx); copy_frag(acc3, fx);
#pragma unroll
            for (int kt = 0; kt < 8; ++kt) {
                load_bfrag(bf, TB_G21 + (8 + kt) * 4 + nt, lane);
                wmma::load_matrix_sync(af, y0 + kt * 16, SA);
                wmma::load_matrix_sync(af1, y1 + kt * 16, SA);
                wmma::load_matrix_sync(af2, y3 + kt * 16, SA);
                wmma::mma_sync(acc0, af, bf, acc0);
                wmma::mma_sync(acc1, af1, bf, acc1);
                wmma::mma_sync(acc3, af2, bf, acc3);
            }
            FragH h0, h1, h3;
#pragma unroll
            for (int e = 0; e < acc0.num_elements; ++e) {
                float v0 = acc0.x[e];
                h0.x[e] = __float2half((v0 >= 0.0f) ? v0 : 0.2f * v0);
                float v1 = acc1.x[e];
                h1.x[e] = __float2half((v1 >= 0.0f) ? v1 : 0.2f * v1);
                float v3 = acc3.x[e];
                h3.x[e] = __float2half((v3 >= 0.0f) ? v3 : 0.2f * v3);
            }
            wmma::store_matrix_sync(smh + OFF_H + 0 * 16 * SH + nt * 16, h0, SH, wmma::mem_row_major);
            wmma::store_matrix_sync(smh + OFF_H + 1 * 16 * SH + nt * 16, h1, SH, wmma::mem_row_major);
            wmma::store_matrix_sync(smh + OFF_H + 3 * 16 * SH + nt * 16, h3, SH, wmma::mem_row_major);
        } else {
            const __half* xg2 = smh + 5 * RSA;  // G2
            const __half* xg1 = smh + 4 * RSA;  // G1
            const __half* y2 = smh + 4 * RSA;   // G1 (p2)
            const __half* y4 = smh + 1 * RSA;   // V  (p4)
            const __half* y5 = smh + 0 * RSA;   // A  (p5)
            FragC fx2, fx1;
            wmma::fill_fragment(fx2, 0.0f);
            wmma::fill_fragment(fx1, 0.0f);
#pragma unroll
            for (int kt = 0; kt < 8; ++kt) {
                load_bfrag(bf, TB_G21 + kt * 4 + nt, lane);
                wmma::load_matrix_sync(af, xg2 + kt * 16, SA);
                wmma::load_matrix_sync(af1, xg1 + kt * 16, SA);
                wmma::mma_sync(fx2, af, bf, fx2);
                wmma::mma_sync(fx1, af1, bf, fx1);
            }
            load_bfrag(bf, TB_G21 + 16 * 4 + nt, lane);
            wmma::load_matrix_sync(af, xg2 + 128, SA);
            wmma::load_matrix_sync(af1, xg1 + 128, SA);
            wmma::mma_sync(fx2, af, bf, fx2);
            wmma::mma_sync(fx1, af1, bf, fx1);
            FragC acc2, acc4, acc5;
            copy_frag(acc2, fx2); copy_frag(acc4, fx1); copy_frag(acc5, fx2);
#pragma unroll
            for (int kt = 0; kt < 8; ++kt) {
                load_bfrag(bf, TB_G21 + (8 + kt) * 4 + nt, lane);
                wmma::load_matrix_sync(af, y2 + kt * 16, SA);
                wmma::load_matrix_sync(af1, y4 + kt * 16, SA);
                wmma::load_matrix_sync(af2, y5 + kt * 16, SA);
                wmma::mma_sync(acc2, af, bf, acc2);
                wmma::mma_sync(acc4, af1, bf, acc4);
                wmma::mma_sync(acc5, af2, bf, acc5);
            }
            FragH h2, h4, h5;
#pragma unroll
            for (int e = 0; e < acc2.num_elements; ++e) {
                float v2 = acc2.x[e];
                h2.x[e] = __float2half((v2 >= 0.0f) ? v2 : 0.2f * v2);
                float v4 = acc4.x[e];
                h4.x[e] = __float2half((v4 >= 0.0f) ? v4 : 0.2f * v4);
                float v5 = acc5.x[e];
                h5.x[e] = __float2half((v5 >= 0.0f) ? v5 : 0.2f * v5);
            }
            wmma::store_matrix_sync(smh + OFF_H + 2 * 16 * SH + nt * 16, h2, SH, wmma::mem_row_major);
            wmma::store_matrix_sync(smh + OFF_H + 4 * 16 * SH + nt * 16, h4, SH, wmma::mem_row_major);
            wmma::store_matrix_sync(smh + OFF_H + 5 * 16 * SH + nt * 16, h5, SH, wmma::mem_row_major);
        }
    }
    __syncthreads();

    // ===== gf2 GEMM2: [96 x 80] @ [80 x 128] raw -> scratch (G0,G1,G2,A,V,L) =====
    {
        const int nt = wid;
        FragC acc[6];
#pragma unroll
        for (int i = 0; i < 6; ++i) wmma::fill_fragment(acc[i], 0.0f);
        FragA af; FragB bf;
#pragma unroll
        for (int kt = 0; kt < 5; ++kt) {
            load_bfrag(bf, TB_G22 + kt * 8 + nt, lane);
            int aoff = (kt < 4) ? kt * 16 : 64;
#pragma unroll
            for (int i = 0; i < 6; ++i) {
                wmma::load_matrix_sync(af, smh + OFF_H + i * 16 * SH + aoff, SH);
                wmma::mma_sync(acc[i], af, bf, acc[i]);
            }
        }
#pragma unroll
        for (int i = 0; i < 6; ++i) {
            int bidx = (i < 3) ? (3 + i) : (i - 3);
            FragH hh;
#pragma unroll
            for (int e = 0; e < acc[i].num_elements; ++e)
                hh.x[e] = __float2half(acc[i].x[e]);
            wmma::store_matrix_sync(smh + bidx * RSA + nt * 16, hh, SA, wmma::mem_row_major);
        }
    }
    __syncthreads();

    // ===== trimodal epilogue (vectorized): fus[r][256+c] = sum_p tanh(n2[p]*tanh(raw_p)) =====
    {
        // 256 threads cover 16 rows x 16 col-groups of 8 halves
        int r = tid >> 4, c8 = (tid & 15) * 8;
        const float* sc = smf + OFF_SC + r * 16 + 9;
        float s[8];
#pragma unroll
        for (int j = 0; j < 8; ++j) s[j] = 0.0f;
#pragma unroll
        for (int p = 0; p < 6; ++p) {
            int bidx = (p < 3) ? (3 + p) : (p - 3);
            float nv = sc[p];
            uint4 q = ((const uint4*)(smh + bidx * RSA + r * SA + c8))[0];
            const __half* hp = (const __half*)&q;
#pragma unroll
            for (int j = 0; j < 8; ++j)
                s[j] += tanh_fast(nv * tanh_fast(__half2float(hp[j])));
        }
        __half* dst = smh + OFF_FUS + r * SF + 256 + c8;
        st_h4(dst,     s[0], s[1], s[2], s[3]);
        st_h4(dst + 4, s[4], s[5], s[6], s[7]);
    }
    __syncthreads();

    // ===== ll1: [16 x 400] @ [400 x 64], 2-way k-split, float partials =====
    {
        const int part = wid >> 2, nt = wid & 3;
        FragC acc; wmma::fill_fragment(acc, 0.0f);
        FragA af; FragB bf;
        if (part == 0) {
#pragma unroll
            for (int kt = 0; kt < 13; ++kt) {
                load_bfrag(bf, TB_LL1 + kt * 4 + nt, lane);
                wmma::load_matrix_sync(af, smh + OFF_FUS + kt * 16, SF);
                wmma::mma_sync(acc, af, bf, acc);
            }
        } else {
#pragma unroll
            for (int kt = 13; kt < 25; ++kt) {
                load_bfrag(bf, TB_LL1 + kt * 4 + nt, lane);
                int aoff = (kt < 24) ? kt * 16 : 384;
                wmma::load_matrix_sync(af, smh + OFF_FUS + aoff, SF);
                wmma::mma_sync(acc, af, bf, acc);
            }
        }
        wmma::store_matrix_sync(smf + OFF_LL1F + part * 16 * SHF + nt * 16, acc, SHF, wmma::mem_row_major);
    }
    __syncthreads();
    {
        // vectorized reduce + tanh: 256 threads cover 16 rows x 16 col-groups of 4 floats
        int r = tid >> 4, c4 = (tid & 15) * 4;
        float4 va = ((const float4*)(smf + OFF_LL1F + r * SHF + c4))[0];
        float4 vb = ((const float4*)(smf + OFF_LL1F + (16 + r) * SHF + c4))[0];
        st_h4(smh + OFF_H2 + r * SH + c4,
              tanh_fast(va.x + vb.x), tanh_fast(va.y + vb.y),
              tanh_fast(va.z + vb.z), tanh_fast(va.w + vb.w));
    }
    __syncthreads();

    // ===== ll2: [16 x 80] @ [80 x 64]; tanh -> H rows 0..15 (half) =====
    if (wid < 4) {
        const int nt = wid;
        FragC acc; wmma::fill_fragment(acc, 0.0f);
        FragA af; FragB bf;
#pragma unroll
        for (int kt = 0; kt < 5; ++kt) {
            load_bfrag(bf, TB_LL2 + kt * 4 + nt, lane);
            int aoff = (kt < 4) ? kt * 16 : 64;
            wmma::load_matrix_sync(af, smh + OFF_H2 + aoff, SH);
            wmma::mma_sync(acc, af, bf, acc);
        }
        FragH hh;
#pragma unroll
        for (int e = 0; e < acc.num_elements; ++e)
            hh.x[e] = __float2half(tanh_fast(acc.x[e]));
        wmma::store_matrix_sync(smh + OFF_H + nt * 16, hh, SH, wmma::mem_row_major);
    }
    __syncthreads();

    // ===== ll3: [16 x 80] @ [80 x 128]; accurate tanh -> gmem (float) =====
    {
        const int nt = wid;
        FragC acc; wmma::fill_fragment(acc, 0.0f);
        FragA af; FragB bf;
#pragma unroll
        for (int kt = 0; kt < 5; ++kt) {
            load_bfrag(bf, TB_LL3 + kt * 8 + nt, lane);
            int aoff = (kt < 4) ? kt * 16 : 64;
            wmma::load_matrix_sync(af, smh + OFF_H + aoff, SH);
            wmma::mma_sync(acc, af, bf, acc);
        }
#pragma unroll
        for (int e = 0; e < acc.num_elements; ++e)
            acc.x[e] = tanhf(acc.x[e]);
        wmma::store_matrix_sync(out + (size_t)blockIdx.x * R * D + nt * 16, acc, D, wmma::mem_row_major);
    }
}

extern "C" void kernel_launch(void* const* d_in, const int* in_sizes, int n_in,
                              void* d_out, int out_size) {
    const float* Lm     = (const float*)d_in[0];
    const float* Am     = (const float*)d_in[1];
    const float* Vm     = (const float*)d_in[2];
    const float* att_w  = (const float*)d_in[3];
    const float* att_b  = (const float*)d_in[4];
    const float* gf_w1  = (const float*)d_in[5];
    const float* gf_b1  = (const float*)d_in[6];
    const float* gf_w2  = (const float*)d_in[7];
    const float* gf_b2  = (const float*)d_in[8];
    const float* gf2_w1 = (const float*)d_in[9];
    const float* gf2_b1 = (const float*)d_in[10];
    const float* gf2_w2 = (const float*)d_in[11];
    const float* gf2_b2 = (const float*)d_in[12];
    const float* ll_w1  = (const float*)d_in[13];
    const float* ll_b1  = (const float*)d_in[14];
    const float* ll_w2  = (const float*)d_in[15];
    const float* ll_b2  = (const float*)d_in[16];
    const float* ll_w3  = (const float*)d_in[17];
    const float* ll_b3  = (const float*)d_in[18];

    convert_weights<<<(N_TILES + 7) / 8, 256>>>(
        gf_w1, gf_b1, gf_w2, gf_b2, gf2_w1, gf2_b1, gf2_w2, gf2_b2,
        ll_w1, ll_b1, ll_w2, ll_b2, ll_w3, ll_b3);

    int nrows = in_sizes[0] / D;
    int grid = nrows / R;
    cudaFuncSetAttribute(graphfusion_kernel,
                         cudaFuncAttributeMaxDynamicSharedMemorySize, SMEM_BYTES);
    graphfusion_kernel<<<grid, NT, SMEM_BYTES>>>(Lm, Am, Vm, att_w, att_b, (float*)d_out);
}

// round 14
// speedup vs baseline: 8.0552x; 1.0507x over previous
#include <cuda_runtime.h>
#include <mma.h>
#include <cuda_fp16.h>
#include <math.h>

using namespace nvcuda;

namespace {
constexpr int D = 128;
constexpr int R = 16;            // rows per block
constexpr int NT = 256;          // 8 warps
// Strides in HALVES; word-stride %32 == 12
constexpr int SA = 152;          // activation: 128 data + const cols [128..144)
constexpr int SF = 408;          // fusion: 384 data + const [384..400)
constexpr int SH = 88;           // H: 64 data + const [64..80)
constexpr int RSA = R * SA;      // 2432 halves per activation buffer
constexpr int OFF_FUS = 6 * RSA;            // 14592
constexpr int OFF_H   = OFF_FUS + R * SF;   // 21120  [96][SH]
constexpr int OFF_H2  = OFF_H + 96 * SH;    // 29568  [16][SH]
constexpr int HALF_END = OFF_H2 + R * SH;   // 30976 halves
constexpr int OFF_AW   = HALF_END / 2;          // floats
constexpr int OFF_SC   = OFF_AW + 128;
constexpr int SHF  = 76;
constexpr int OFF_LL1F = OFF_SC + R * 16;
constexpr int SMEM_BYTES = (OFF_LL1F + 32 * SHF) * 4;   // 73216 B (x3 CTAs = 219648)

// Packed fp16 B-fragment tiles (16x16). Slot = 512 halves (1 KB).
constexpr int TSLOT = 512;
constexpr int TB_GF1 = 0;
constexpr int TB_GF2 = 68;
constexpr int TB_G21 = 108;
constexpr int TB_G22 = 176;
constexpr int TB_LL1 = 216;
constexpr int TB_LL2 = 316;
constexpr int TB_LL3 = 336;
constexpr int N_TILES = 376;
}

__device__ __half g_w[N_TILES * TSLOT];

__device__ __forceinline__ float warp_sum(float x) {
#pragma unroll
    for (int o = 16; o > 0; o >>= 1) x += __shfl_xor_sync(0xffffffffu, x, o);
    return x;
}
__device__ __forceinline__ float warp_max(float x) {
#pragma unroll
    for (int o = 16; o > 0; o >>= 1) x = fmaxf(x, __shfl_xor_sync(0xffffffffu, x, o));
    return x;
}
__device__ __forceinline__ float tanh_fast(float x) {
    float y;
    asm("tanh.approx.f32 %0, %1;" : "=f"(y) : "f"(x));
    return y;
}
__device__ __forceinline__ void st_h4(__half* p, float a, float b, float c, float d) {
    __half2* q = (__half2*)p;
    q[0] = __floats2half2_rn(a, b);
    q[1] = __floats2half2_rn(c, d);
}
__device__ __forceinline__ float4 ld_h4(const __half* p) {
    const __half2* q = (const __half2*)p;
    float2 u = __half22float2(q[0]), v = __half22float2(q[1]);
    return make_float4(u.x, u.y, v.x, v.y);
}

typedef wmma::fragment<wmma::matrix_a, 16, 16, 16, __half, wmma::row_major> FragA;
typedef wmma::fragment<wmma::matrix_b, 16, 16, 16, __half, wmma::row_major> FragB;
typedef wmma::fragment<wmma::accumulator, 16, 16, 16, float> FragC;
typedef wmma::fragment<wmma::accumulator, 16, 16, 16, __half> FragH;

__device__ __forceinline__ void copy_frag(FragC& d, const FragC& s) {
#pragma unroll
    for (int e = 0; e < d.num_elements; ++e) d.x[e] = s.x[e];
}
__device__ __forceinline__ void load_bfrag(FragB& bf, int tile, int lane) {
    const __half* p = g_w + tile * TSLOT + lane * bf.num_elements;
#pragma unroll
    for (int e = 0; e < bf.num_elements; e += 8) {
        uint4 q = __ldg((const uint4*)(p + e));
        const __half* hp = (const __half*)&q;
#pragma unroll
        for (int j = 0; j < 8; ++j) bf.x[e + j] = hp[j];
    }
}

__global__ void convert_weights(
    const float* __restrict__ gf_w1, const float* __restrict__ gf_b1,
    const float* __restrict__ gf_w2, const float* __restrict__ gf_b2,
    const float* __restrict__ gf2_w1, const float* __restrict__ gf2_b1,
    const float* __restrict__ gf2_w2, const float* __restrict__ gf2_b2,
    const float* __restrict__ ll_w1, const float* __restrict__ ll_b1,
    const float* __restrict__ ll_w2, const float* __restrict__ ll_b2,
    const float* __restrict__ ll_w3, const float* __restrict__ ll_b3)
{
    __shared__ __half tile[8][256];
    const int w = threadIdx.x >> 5, lane = threadIdx.x & 31;
    const int t = blockIdx.x * 8 + w;
    if (t >= N_TILES) return;   // warp-uniform

    int t2 = t;
    const float* wsrc; const float* bsrc; int nNT, rmax;
    if      (t2 < TB_GF2) { t2 -= TB_GF1; wsrc = gf_w1;  bsrc = gf_b1;  nNT = 4; rmax = 256; }
    else if (t2 < TB_G21) { t2 -= TB_GF2; wsrc = gf_w2;  bsrc = gf_b2;  nNT = 8; rmax = 64;  }
    else if (t2 < TB_G22) { t2 -= TB_G21; wsrc = gf2_w1; bsrc = gf2_b1; nNT = 4; rmax = 256; }
    else if (t2 < TB_LL1) { t2 -= TB_G22; wsrc = gf2_w2; bsrc = gf2_b2; nNT = 8; rmax = 64;  }
    else if (t2 < TB_LL2) { t2 -= TB_LL1; wsrc = ll_w1;  bsrc = ll_b1;  nNT = 4; rmax = 384; }
    else if (t2 < TB_LL3) { t2 -= TB_LL2; wsrc = ll_w2;  bsrc = ll_b2;  nNT = 4; rmax = 64;  }
    else                  { t2 -= TB_LL3; wsrc = ll_w3;  bsrc = ll_b3;  nNT = 8; rmax = 64;  }
    const int kt = t2 / nNT, nt = t2 % nNT;
    const int ncols = nNT * 16;

#pragma unroll
    for (int j = 0; j < 8; ++j) {
        int idx = lane * 8 + j;
        int rr = idx >> 4, cc = idx & 15;
        int r = kt * 16 + rr, c = nt * 16 + cc;
        float v = 0.0f;
        if (r < rmax)       v = wsrc[r * ncols + c];
        else if (r == rmax) v = bsrc[c];
        tile[w][idx] = __float2half_rn(v);
    }
    __syncwarp();
    FragB bf;
    wmma::load_matrix_sync(bf, &tile[w][0], 16);
    __half* dst = g_w + t * TSLOT + lane * bf.num_elements;
#pragma unroll
    for (int e = 0; e < bf.num_elements; ++e) dst[e] = bf.x[e];
}

__global__ void __launch_bounds__(NT, 3)
graphfusion_kernel(
    const float* __restrict__ Lm, const float* __restrict__ Am, const float* __restrict__ Vm,
    const float* __restrict__ att_w, const float* __restrict__ att_b,
    float* __restrict__ out)
{
    extern __shared__ __align__(16) char smraw[];
    __half* smh = (__half*)smraw;
    float*  smf = (float*)smraw;
    const int tid  = threadIdx.x;
    const int lane = tid & 31;
    const int wid  = tid >> 5;   // 0..7

    // ---- init: att_w + constant bias columns, vectorized (16-half groups) ----
    if (tid < D) smf[OFF_AW + tid] = att_w[tid];
    if (tid < 224) {
        int g = tid, addr;
        if (g < 96)       { int b = g >> 4, r = g & 15; addr = b * RSA + r * SA + 128; }
        else if (g < 112) { int r = g - 96;  addr = OFF_FUS + r * SF + 384; }
        else if (g < 208) { int r = g - 112; addr = OFF_H  + r * SH + 64; }
        else              { int r = g - 208; addr = OFF_H2 + r * SH + 64; }
        uint4 z0 = make_uint4(0x00003c00u, 0u, 0u, 0u);   // halves [1.0, 0 x7]
        uint4 z1 = make_uint4(0u, 0u, 0u, 0u);
        ((uint4*)(smh + addr))[0] = z0;
        ((uint4*)(smh + addr))[1] = z1;
    }
    __syncthreads();
    const float attb = __ldg(att_b);

    // ================= Phase A: scalars + softmaxes + unimodal =================
    {
        float4 aw = ((const float4*)(smf + OFF_AW))[lane];
#pragma unroll
        for (int rr = 0; rr < 2; ++rr) {
            int r = wid * 2 + rr;
            size_t grow = (size_t)blockIdx.x * R + r;
            float4 a4 = ((const float4*)(Am + grow * D))[lane];
            float4 v4 = ((const float4*)(Vm + grow * D))[lane];
            float4 l4 = ((const float4*)(Lm + grow * D))[lane];

            float sa = tanh_fast(warp_sum(a4.x * aw.x + a4.y * aw.y + a4.z * aw.z + a4.w * aw.w) + attb);
            float sv = tanh_fast(warp_sum(v4.x * aw.x + v4.y * aw.y + v4.z * aw.z + v4.w * aw.w) + attb);
            float sl = tanh_fast(warp_sum(l4.x * aw.x + l4.y * aw.y + l4.z * aw.z + l4.w * aw.w) + attb);

            st_h4(smh + OFF_FUS + r * SF + lane * 4,
                  (sa * a4.x + sv * v4.x + sl * l4.x) * (1.0f / 3.0f),
                  (sa * a4.y + sv * v4.y + sl * l4.y) * (1.0f / 3.0f),
                  (sa * a4.z + sv * v4.z + sl * l4.z) * (1.0f / 3.0f),
                  (sa * a4.w + sv * v4.w + sl * l4.w) * (1.0f / 3.0f));

            float ma = warp_max(fmaxf(fmaxf(a4.x, a4.y), fmaxf(a4.z, a4.w)));
            float4 ea = make_float4(__expf(a4.x - ma), __expf(a4.y - ma), __expf(a4.z - ma), __expf(a4.w - ma));
            float ia = 1.0f / warp_sum(ea.x + ea.y + ea.z + ea.w);
            float4 pa = make_float4(ea.x * ia, ea.y * ia, ea.z * ia, ea.w * ia);

            float mv = warp_max(fmaxf(fmaxf(v4.x, v4.y), fmaxf(v4.z, v4.w)));
            float4 ev = make_float4(__expf(v4.x - mv), __expf(v4.y - mv), __expf(v4.z - mv), __expf(v4.w - mv));
            float iv = 1.0f / warp_sum(ev.x + ev.y + ev.z + ev.w);
            float4 pv = make_float4(ev.x * iv, ev.y * iv, ev.z * iv, ev.w * iv);

            float ml = warp_max(fmaxf(fmaxf(l4.x, l4.y), fmaxf(l4.z, l4.w)));
            float4 el = make_float4(__expf(l4.x - ml), __expf(l4.y - ml), __expf(l4.z - ml), __expf(l4.w - ml));
            float il = 1.0f / warp_sum(el.x + el.y + el.z + el.w);
            float4 pl = make_float4(el.x * il, el.y * il, el.z * il, el.w * il);

            st_h4(smh + 0 * RSA + r * SA + lane * 4, pa.x, pa.y, pa.z, pa.w);
            st_h4(smh + 1 * RSA + r * SA + lane * 4, pv.x, pv.y, pv.z, pv.w);
            st_h4(smh + 2 * RSA + r * SA + lane * 4, pl.x, pl.y, pl.z, pl.w);

            float dav = warp_sum(pa.x * pv.x + pa.y * pv.y + pa.z * pv.z + pa.w * pv.w);
            float dal = warp_sum(pa.x * pl.x + pa.y * pl.y + pa.z * pl.z + pa.w * pl.w);
            float dvl = warp_sum(pv.x * pl.x + pv.y * pl.y + pv.z * pl.z + pv.w * pl.w);

            float sav = (sa + sv) / (dav + 0.5f);
            float sal = (sa + sl) / (dal + 0.5f);
            float svl = (sl + sv) / (dvl + 0.5f);
            float mx = fmaxf(sav, fmaxf(sal, svl));
            float e0 = __expf(sav - mx), e1 = __expf(sal - mx), e2 = __expf(svl - mx);
            float is = 1.0f / (e0 + e1 + e2);
            if (lane == 0) {
                float* sc = smf + OFF_SC + r * 16;
                sc[0] = e0 * is; sc[1] = e1 * is; sc[2] = e2 * is;
                sc[3] = sav; sc[4] = sal; sc[5] = svl;
                sc[6] = sa;  sc[7] = sv;  sc[8] = sl;
            }
        }
    }
    __syncthreads();

    // ===== gf GEMM1: [48 x 272] @ [272 x 64], fp16 k16, x-half dedup =====
    {
        const int nt = wid & 3;
        FragA af, af1; FragB bf;
        if (wid < 4) {
            const __half* xa = smh + 0 * RSA;
            const __half* yv = smh + 1 * RSA;
            const __half* yl = smh + 2 * RSA;
            FragC fx; wmma::fill_fragment(fx, 0.0f);
#pragma unroll
            for (int kt = 0; kt < 8; ++kt) {
                load_bfrag(bf, TB_GF1 + kt * 4 + nt, lane);
                wmma::load_matrix_sync(af, xa + kt * 16, SA);
                wmma::mma_sync(fx, af, bf, fx);
            }
            load_bfrag(bf, TB_GF1 + 16 * 4 + nt, lane);
            wmma::load_matrix_sync(af, xa + 128, SA);
            wmma::mma_sync(fx, af, bf, fx);
            FragC acc0, acc1;
            copy_frag(acc0, fx); copy_frag(acc1, fx);
#pragma unroll
            for (int kt = 0; kt < 8; ++kt) {
                load_bfrag(bf, TB_GF1 + (8 + kt) * 4 + nt, lane);
                wmma::load_matrix_sync(af, yv + kt * 16, SA);
                wmma::load_matrix_sync(af1, yl + kt * 16, SA);
                wmma::mma_sync(acc0, af, bf, acc0);
                wmma::mma_sync(acc1, af1, bf, acc1);
            }
            FragH h0, h1;
#pragma unroll
            for (int e = 0; e < acc0.num_elements; ++e) {
                float v0 = acc0.x[e];
                h0.x[e] = __float2half((v0 >= 0.0f) ? v0 : 0.2f * v0);
                float v1 = acc1.x[e];
                h1.x[e] = __float2half((v1 >= 0.0f) ? v1 : 0.2f * v1);
            }
            wmma::store_matrix_sync(smh + OFF_H + 0 * 16 * SH + nt * 16, h0, SH, wmma::mem_row_major);
            wmma::store_matrix_sync(smh + OFF_H + 1 * 16 * SH + nt * 16, h1, SH, wmma::mem_row_major);
        } else {
            const __half* xv = smh + 1 * RSA;
            const __half* yl = smh + 2 * RSA;
            FragC acc; wmma::fill_fragment(acc, 0.0f);
#pragma unroll
            for (int kt = 0; kt < 8; ++kt) {
                load_bfrag(bf, TB_GF1 + kt * 4 + nt, lane);
                wmma::load_matrix_sync(af, xv + kt * 16, SA);
                wmma::mma_sync(acc, af, bf, acc);
            }
            load_bfrag(bf, TB_GF1 + 16 * 4 + nt, lane);
            wmma::load_matrix_sync(af, xv + 128, SA);
            wmma::mma_sync(acc, af, bf, acc);
#pragma unroll
            for (int kt = 0; kt < 8; ++kt) {
                load_bfrag(bf, TB_GF1 + (8 + kt) * 4 + nt, lane);
                wmma::load_matrix_sync(af, yl + kt * 16, SA);
                wmma::mma_sync(acc, af, bf, acc);
            }
            FragH h0;
#pragma unroll
            for (int e = 0; e < acc.num_elements; ++e) {
                float v = acc.x[e];
                h0.x[e] = __float2half((v >= 0.0f) ? v : 0.2f * v);
            }
            wmma::store_matrix_sync(smh + OFF_H + 2 * 16 * SH + nt * 16, h0, SH, wmma::mem_row_major);
        }
    }
    __syncthreads();

    // ===== gf GEMM2: [48 x 80] @ [80 x 128], n-pair retile =====
    // w0-3: nt2=wid, m{0,1} x n32 (4 acc). w4-7: nt2=wid-4, m{2} x n32 (2 acc).
    {
        FragA af; FragB bf0, bf1;
        if (wid < 4) {
            const int nt2 = wid;
            FragC acc[2][2];
#pragma unroll
            for (int i = 0; i < 2; ++i) { wmma::fill_fragment(acc[i][0], 0.0f); wmma::fill_fragment(acc[i][1], 0.0f); }
#pragma unroll
            for (int kt = 0; kt < 5; ++kt) {
                load_bfrag(bf0, TB_GF2 + kt * 8 + nt2 * 2, lane);
                load_bfrag(bf1, TB_GF2 + kt * 8 + nt2 * 2 + 1, lane);
                int aoff = (kt < 4) ? kt * 16 : 64;
#pragma unroll
                for (int i = 0; i < 2; ++i) {
                    wmma::load_matrix_sync(af, smh + OFF_H + i * 16 * SH + aoff, SH);
                    wmma::mma_sync(acc[i][0], af, bf0, acc[i][0]);
                    wmma::mma_sync(acc[i][1], af, bf1, acc[i][1]);
                }
            }
#pragma unroll
            for (int i = 0; i < 2; ++i)
#pragma unroll
                for (int j = 0; j < 2; ++j) {
                    FragH hh;
#pragma unroll
                    for (int e = 0; e < acc[i][j].num_elements; ++e)
                        hh.x[e] = __float2half(tanh_fast(acc[i][j].x[e]));
                    wmma::store_matrix_sync(smh + (3 + i) * RSA + (nt2 * 2 + j) * 16, hh, SA, wmma::mem_row_major);
                }
        } else {
            const int nt2 = wid - 4;
            FragC acc[2];
            wmma::fill_fragment(acc[0], 0.0f); wmma::fill_fragment(acc[1], 0.0f);
#pragma unroll
            for (int kt = 0; kt < 5; ++kt) {
                load_bfrag(bf0, TB_GF2 + kt * 8 + nt2 * 2, lane);
                load_bfrag(bf1, TB_GF2 + kt * 8 + nt2 * 2 + 1, lane);
                int aoff = (kt < 4) ? kt * 16 : 64;
                wmma::load_matrix_sync(af, smh + OFF_H + 2 * 16 * SH + aoff, SH);
                wmma::mma_sync(acc[0], af, bf0, acc[0]);
                wmma::mma_sync(acc[1], af, bf1, acc[1]);
            }
#pragma unroll
            for (int j = 0; j < 2; ++j) {
                FragH hh;
#pragma unroll
                for (int e = 0; e < acc[j].num_elements; ++e)
                    hh.x[e] = __float2half(tanh_fast(acc[j].x[e]));
                wmma::store_matrix_sync(smh + 5 * RSA + (nt2 * 2 + j) * 16, hh, SA, wmma::mem_row_major);
            }
        }
    }
    __syncthreads();

    // ============ Phase C: softmax(g) dots, n2, a_v/a_l/v_l, bimodal ============
    {
#pragma unroll
        for (int rr = 0; rr < 2; ++rr) {
            int r = wid * 2 + rr;
            float4 g0 = ld_h4(smh + 3 * RSA + r * SA + lane * 4);
            float4 g1 = ld_h4(smh + 4 * RSA + r * SA + lane * 4);
            float4 g2 = ld_h4(smh + 5 * RSA + r * SA + lane * 4);
            float4 pa = ld_h4(smh + 0 * RSA + r * SA + lane * 4);
            float4 pv = ld_h4(smh + 1 * RSA + r * SA + lane * 4);
            float4 pl = ld_h4(smh + 2 * RSA + r * SA + lane * 4);

            float m0 = warp_max(fmaxf(fmaxf(g0.x, g0.y), fmaxf(g0.z, g0.w)));
            float m1 = warp_max(fmaxf(fmaxf(g1.x, g1.y), fmaxf(g1.z, g1.w)));
            float m2 = warp_max(fmaxf(fmaxf(g2.x, g2.y), fmaxf(g2.z, g2.w)));
            float4 e0 = make_float4(__expf(g0.x - m0), __expf(g0.y - m0), __expf(g0.z - m0), __expf(g0.w - m0));
            float4 e1 = make_float4(__expf(g1.x - m1), __expf(g1.y - m1), __expf(g1.z - m1), __expf(g1.w - m1));
            float4 e2 = make_float4(__expf(g2.x - m2), __expf(g2.y - m2), __expf(g2.z - m2), __expf(g2.w - m2));
            float i0 = 1.0f / warp_sum(e0.x + e0.y + e0.z + e0.w);
            float i1 = 1.0f / warp_sum(e1.x + e1.y + e1.z + e1.w);
            float i2 = 1.0f / warp_sum(e2.x + e2.y + e2.z + e2.w);

            float d01 = warp_sum(e0.x * e1.x + e0.y * e1.y + e0.z * e1.z + e0.w * e1.w);
            float d02 = warp_sum(e0.x * e2.x + e0.y * e2.y + e0.z * e2.z + e0.w * e2.w);
            float d12 = warp_sum(e1.x * e2.x + e1.y * e2.y + e1.z * e2.z + e1.w * e2.w);
            float d0l = warp_sum(e0.x * pl.x + e0.y * pl.y + e0.z * pl.z + e0.w * pl.w);
            float d1v = warp_sum(e1.x * pv.x + e1.y * pv.y + e1.z * pv.z + e1.w * pv.w);
            float d2a = warp_sum(e2.x * pa.x + e2.y * pa.y + e2.z * pa.z + e2.w * pa.w);

            const float* sc = smf + OFF_SC + r * 16;
            float sav = sc[3], sal = sc[4], svl = sc[5];
            float sa = sc[6], sv = sc[7], sl = sc[8];
            float t0 = (sav + svl) / (d02 * i0 * i2 + 0.5f);
            float t1 = (sav + sal) / (d01 * i0 * i1 + 0.5f);
            float t2 = (sal + svl) / (d12 * i1 * i2 + 0.5f);
            float t3 = (sav + sl)  / (d0l * i0 + 0.5f);
            float t4 = (sal + sv)  / (d1v * i1 + 0.5f);
            float t5 = (sa  + svl) / (d2a * i2 + 0.5f);
            float mm = fmaxf(fmaxf(fmaxf(t0, t1), fmaxf(t2, t3)), fmaxf(t4, t5));
            float q0 = __expf(t0 - mm), q1 = __expf(t1 - mm), q2 = __expf(t2 - mm);
            float q3 = __expf(t3 - mm), q4 = __expf(t4 - mm), q5 = __expf(t5 - mm);
            float qi = 1.0f / (q0 + q1 + q2 + q3 + q4 + q5);
            if (lane == 0) {
                float* scw = smf + OFF_SC + r * 16;
                scw[9]  = q0 * qi; scw[10] = q1 * qi; scw[11] = q2 * qi;
                scw[12] = q3 * qi; scw[13] = q4 * qi; scw[14] = q5 * qi;
            }

            float n0 = sc[0], n1 = sc[1], n2v = sc[2];
            float4 av = make_float4(tanh_fast(n0 * g0.x), tanh_fast(n0 * g0.y), tanh_fast(n0 * g0.z), tanh_fast(n0 * g0.w));
            float4 al = make_float4(tanh_fast(n1 * g1.x), tanh_fast(n1 * g1.y), tanh_fast(n1 * g1.z), tanh_fast(n1 * g1.w));
            float4 vl = make_float4(tanh_fast(n2v * g2.x), tanh_fast(n2v * g2.y), tanh_fast(n2v * g2.z), tanh_fast(n2v * g2.w));
            st_h4(smh + 3 * RSA + r * SA + lane * 4, av.x, av.y, av.z, av.w);
            st_h4(smh + 4 * RSA + r * SA + lane * 4, al.x, al.y, al.z, al.w);
            st_h4(smh + 5 * RSA + r * SA + lane * 4, vl.x, vl.y, vl.z, vl.w);
            st_h4(smh + OFF_FUS + r * SF + 128 + lane * 4,
                  av.x + al.x + vl.x, av.y + al.y + vl.y,
                  av.z + al.z + vl.z, av.w + al.w + vl.w);
        }
    }
    __syncthreads();

    // ===== gf2 GEMM1 (6 pairs, x-half dedup): [96 x 272] @ [272 x 64] =====
    {
        const int nt = wid & 3;
        FragA af, af1, af2; FragB bf;
        if (wid < 4) {
            const __half* x0 = smh + 3 * RSA;   // G0
            const __half* y0 = smh + 5 * RSA;   // G2 (p0)
            const __half* y1 = smh + 4 * RSA;   // G1 (p1)
            const __half* y3 = smh + 2 * RSA;   // L  (p3)
            FragC fx; wmma::fill_fragment(fx, 0.0f);
#pragma unroll
            for (int kt = 0; kt < 8; ++kt) {
                load_bfrag(bf, TB_G21 + kt * 4 + nt, lane);
                wmma::load_matrix_sync(af, x0 + kt * 16, SA);
                wmma::mma_sync(fx, af, bf, fx);
            }
            load_bfrag(bf, TB_G21 + 16 * 4 + nt, lane);
            wmma::load_matrix_sync(af, x0 + 128, SA);
            wmma::mma_sync(fx, af, bf, fx);
            FragC acc0, acc1, acc3;
            copy_frag(acc0, fx); copy_frag(acc1, fx); copy_frag(acc3, fx);
#pragma unroll
            for (int kt = 0; kt < 8; ++kt) {
                load_bfrag(bf, TB_G21 + (8 + kt) * 4 + nt, lane);
                wmma::load_matrix_sync(af, y0 + kt * 16, SA);
                wmma::load_matrix_sync(af1, y1 + kt * 16, SA);
                wmma::load_matrix_sync(af2, y3 + kt * 16, SA);
                wmma::mma_sync(acc0, af, bf, acc0);
                wmma::mma_sync(acc1, af1, bf, acc1);
                wmma::mma_sync(acc3, af2, bf, acc3);
            }
            FragH h0, h1, h3;
#pragma unroll
            for (int e = 0; e < acc0.num_elements; ++e) {
                float v0 = acc0.x[e];
                h0.x[e] = __float2half((v0 >= 0.0f) ? v0 : 0.2f * v0);
                float v1 = acc1.x[e];
                h1.x[e] = __float2half((v1 >= 0.0f) ? v1 : 0.2f * v1);
                float v3 = acc3.x[e];
                h3.x[e] = __float2half((v3 >= 0.0f) ? v3 : 0.2f * v3);
            }
            wmma::store_matrix_sync(smh + OFF_H + 0 * 16 * SH + nt * 16, h0, SH, wmma::mem_row_major);
            wmma::store_matrix_sync(smh + OFF_H + 1 * 16 * SH + nt * 16, h1, SH, wmma::mem_row_major);
            wmma::store_matrix_sync(smh + OFF_H + 3 * 16 * SH + nt * 16, h3, SH, wmma::mem_row_major);
        } else {
            const __half* xg2 = smh + 5 * RSA;  // G2
            const __half* xg1 = smh + 4 * RSA;  // G1
            const __half* y2 = smh + 4 * RSA;   // G1 (p2)
            const __half* y4 = smh + 1 * RSA;   // V  (p4)
            const __half* y5 = smh + 0 * RSA;   // A  (p5)
            FragC fx2, fx1;
            wmma::fill_fragment(fx2, 0.0f);
            wmma::fill_fragment(fx1, 0.0f);
#pragma unroll
            for (int kt = 0; kt < 8; ++kt) {
                load_bfrag(bf, TB_G21 + kt * 4 + nt, lane);
                wmma::load_matrix_sync(af, xg2 + kt * 16, SA);
                wmma::load_matrix_sync(af1, xg1 + kt * 16, SA);
                wmma::mma_sync(fx2, af, bf, fx2);
                wmma::mma_sync(fx1, af1, bf, fx1);
            }
            load_bfrag(bf, TB_G21 + 16 * 4 + nt, lane);
            wmma::load_matrix_sync(af, xg2 + 128, SA);
            wmma::load_matrix_sync(af1, xg1 + 128, SA);
            wmma::mma_sync(fx2, af, bf, fx2);
            wmma::mma_sync(fx1, af1, bf, fx1);
            FragC acc2, acc4, acc5;
            copy_frag(acc2, fx2); copy_frag(acc4, fx1); copy_frag(acc5, fx2);
#pragma unroll
            for (int kt = 0; kt < 8; ++kt) {
                load_bfrag(bf, TB_G21 + (8 + kt) * 4 + nt, lane);
                wmma::load_matrix_sync(af, y2 + kt * 16, SA);
                wmma::load_matrix_sync(af1, y4 + kt * 16, SA);
                wmma::load_matrix_sync(af2, y5 + kt * 16, SA);
                wmma::mma_sync(acc2, af, bf, acc2);
                wmma::mma_sync(acc4, af1, bf, acc4);
                wmma::mma_sync(acc5, af2, bf, acc5);
            }
            FragH h2, h4, h5;
#pragma unroll
            for (int e = 0; e < acc2.num_elements; ++e) {
                float v2 = acc2.x[e];
                h2.x[e] = __float2half((v2 >= 0.0f) ? v2 : 0.2f * v2);
                float v4 = acc4.x[e];
                h4.x[e] = __float2half((v4 >= 0.0f) ? v4 : 0.2f * v4);
                float v5 = acc5.x[e];
                h5.x[e] = __float2half((v5 >= 0.0f) ? v5 : 0.2f * v5);
            }
            wmma::store_matrix_sync(smh + OFF_H + 2 * 16 * SH + nt * 16, h2, SH, wmma::mem_row_major);
            wmma::store_matrix_sync(smh + OFF_H + 4 * 16 * SH + nt * 16, h4, SH, wmma::mem_row_major);
            wmma::store_matrix_sync(smh + OFF_H + 5 * 16 * SH + nt * 16, h5, SH, wmma::mem_row_major);
        }
    }
    __syncthreads();

    // ===== gf2 GEMM2: [96 x 80] @ [80 x 128], m-split x n-pair retile =====
    // warp = mg (wid>>2) x nt2 (wid&3): m {mg*3..mg*3+2} x n32
    {
        const int mg = wid >> 2, nt2 = wid & 3;
        FragC acc[3][2];
#pragma unroll
        for (int i = 0; i < 3; ++i) { wmma::fill_fragment(acc[i][0], 0.0f); wmma::fill_fragment(acc[i][1], 0.0f); }
        FragA af; FragB bf0, bf1;
#pragma unroll
        for (int kt = 0; kt < 5; ++kt) {
            load_bfrag(bf0, TB_G22 + kt * 8 + nt2 * 2, lane);
            load_bfrag(bf1, TB_G22 + kt * 8 + nt2 * 2 + 1, lane);
            int aoff = (kt < 4) ? kt * 16 : 64;
#pragma unroll
            for (int i = 0; i < 3; ++i) {
                wmma::load_matrix_sync(af, smh + OFF_H + (mg * 3 + i) * 16 * SH + aoff, SH);
                wmma::mma_sync(acc[i][0], af, bf0, acc[i][0]);
                wmma::mma_sync(acc[i][1], af, bf1, acc[i][1]);
            }
        }
#pragma unroll
        for (int i = 0; i < 3; ++i) {
            int ig = mg * 3 + i;
            int bidx = (ig < 3) ? (3 + ig) : (ig - 3);
#pragma unroll
            for (int j = 0; j < 2; ++j) {
                FragH hh;
#pragma unroll
                for (int e = 0; e < acc[i][j].num_elements; ++e)
                    hh.x[e] = __float2half(acc[i][j].x[e]);
                wmma::store_matrix_sync(smh + bidx * RSA + (nt2 * 2 + j) * 16, hh, SA, wmma::mem_row_major);
            }
        }
    }
    __syncthreads();

    // ===== trimodal epilogue (vectorized) =====
    {
        int r = tid >> 4, c8 = (tid & 15) * 8;
        const float* sc = smf + OFF_SC + r * 16 + 9;
        float s[8];
#pragma unroll
        for (int j = 0; j < 8; ++j) s[j] = 0.0f;
#pragma unroll
        for (int p = 0; p < 6; ++p) {
            int bidx = (p < 3) ? (3 + p) : (p - 3);
            float nv = sc[p];
            uint4 q = ((const uint4*)(smh + bidx * RSA + r * SA + c8))[0];
            const __half* hp = (const __half*)&q;
#pragma unroll
            for (int j = 0; j < 8; ++j)
                s[j] += tanh_fast(nv * tanh_fast(__half2float(hp[j])));
        }
        __half* dst = smh + OFF_FUS + r * SF + 256 + c8;
        st_h4(dst,     s[0], s[1], s[2], s[3]);
        st_h4(dst + 4, s[4], s[5], s[6], s[7]);
    }
    __syncthreads();

    // ===== ll1: [16 x 400] @ [400 x 64], 2-way k-split, float partials =====
    {
        const int part = wid >> 2, nt = wid & 3;
        FragC acc; wmma::fill_fragment(acc, 0.0f);
        FragA af; FragB bf;
        if (part == 0) {
#pragma unroll
            for (int kt = 0; kt < 13; ++kt) {
                load_bfrag(bf, TB_LL1 + kt * 4 + nt, lane);
                wmma::load_matrix_sync(af, smh + OFF_FUS + kt * 16, SF);
                wmma::mma_sync(acc, af, bf, acc);
            }
        } else {
#pragma unroll
            for (int kt = 13; kt < 25; ++kt) {
                load_bfrag(bf, TB_LL1 + kt * 4 + nt, lane);
                int aoff = (kt < 24) ? kt * 16 : 384;
                wmma::load_matrix_sync(af, smh + OFF_FUS + aoff, SF);
                wmma::mma_sync(acc, af, bf, acc);
            }
        }
        wmma::store_matrix_sync(smf + OFF_LL1F + part * 16 * SHF + nt * 16, acc, SHF, wmma::mem_row_major);
    }
    __syncthreads();
    {
        int r = tid >> 4, c4 = (tid & 15) * 4;
        float4 va = ((const float4*)(smf + OFF_LL1F + r * SHF + c4))[0];
        float4 vb = ((const float4*)(smf + OFF_LL1F + (16 + r) * SHF + c4))[0];
        st_h4(smh + OFF_H2 + r * SH + c4,
              tanh_fast(va.x + vb.x), tanh_fast(va.y + vb.y),
              tanh_fast(va.z + vb.z), tanh_fast(va.w + vb.w));
    }
    __syncthreads();

    // ===== ll2: [16 x 80] @ [80 x 64]; tanh -> H rows 0..15 (half) =====
    if (wid < 4) {
        const int nt = wid;
        FragC acc; wmma::fill_fragment(acc, 0.0f);
        FragA af; FragB bf;
#pragma unroll
        for (int kt = 0; kt < 5; ++kt) {
            load_bfrag(bf, TB_LL2 + kt * 4 + nt, lane);
            int aoff = (kt < 4) ? kt * 16 : 64;
            wmma::load_matrix_sync(af, smh + OFF_H2 + aoff, SH);
            wmma::mma_sync(acc, af, bf, acc);
        }
        FragH hh;
#pragma unroll
        for (int e = 0; e < acc.num_elements; ++e)
            hh.x[e] = __float2half(tanh_fast(acc.x[e]));
        wmma::store_matrix_sync(smh + OFF_H + nt * 16, hh, SH, wmma::mem_row_major);
    }
    __syncthreads();

    // ===== ll3: [16 x 80] @ [80 x 128]; accurate tanh -> gmem (float) =====
    {
        const int nt = wid;
        FragC acc; wmma::fill_fragment(acc, 0.0f);
        FragA af; FragB bf;
#pragma unroll
        for (int kt = 0; kt < 5; ++kt) {
            load_bfrag(bf, TB_LL3 + kt * 8 + nt, lane);
            int aoff = (kt < 4) ? kt * 16 : 64;
            wmma::load_matrix_sync(af, smh + OFF_H + aoff, SH);
            wmma::mma_sync(acc, af, bf, acc);
        }
#pragma unroll
        for (int e = 0; e < acc.num_elements; ++e)
            acc.x[e] = tanhf(acc.x[e]);
        wmma::store_matrix_sync(out + (size_t)blockIdx.x * R * D + nt * 16, acc, D, wmma::mem_row_major);
    }
}

extern "C" void kernel_launch(void* const* d_in, const int* in_sizes, int n_in,
                              void* d_out, int out_size) {
    const float* Lm     = (const float*)d_in[0];
    const float* Am     = (const float*)d_in[1];
    const float* Vm     = (const float*)d_in[2];
    const float* att_w  = (const float*)d_in[3];
    const float* att_b  = (const float*)d_in[4];
    const float* gf_w1  = (const float*)d_in[5];
    const float* gf_b1  = (const float*)d_in[6];
    const float* gf_w2  = (const float*)d_in[7];
    const float* gf_b2  = (const float*)d_in[8];
    const float* gf2_w1 = (const float*)d_in[9];
    const float* gf2_b1 = (const float*)d_in[10];
    const float* gf2_w2 = (const float*)d_in[11];
    const float* gf2_b2 = (const float*)d_in[12];
    const float* ll_w1  = (const float*)d_in[13];
    const float* ll_b1  = (const float*)d_in[14];
    const float* ll_w2  = (const float*)d_in[15];
    const float* ll_b2  = (const float*)d_in[16];
    const float* ll_w3  = (const float*)d_in[17];
    const float* ll_b3  = (const float*)d_in[18];

    convert_weights<<<(N_TILES + 7) / 8, 256>>>(
        gf_w1, gf_b1, gf_w2, gf_b2, gf2_w1, gf2_b1, gf2_w2, gf2_b2,
        ll_w1, ll_b1, ll_w2, ll_b2, ll_w3, ll_b3);

    int nrows = in_sizes[0] / D;
    int grid = nrows / R;
    cudaFuncSetAttribute(graphfusion_kernel,
                         cudaFuncAttributeMaxDynamicSharedMemorySize, SMEM_BYTES);
    graphfusion_kernel<<<grid, NT, SMEM_BYTES>>>(Lm, Am, Vm, att_w, att_b, (float*)d_out);
}